// round 1
// baseline (speedup 1.0000x reference)
#include <cuda_runtime.h>
#include <math.h>

#define BB 48
#define SS 512
#define HH 768
#define EE 128
#define LL 16
#define PP 256
#define NERC 11
#define NER_TOTAL (BB*SS*NERC)   // 270336

// ---------------- scratch (device globals; no allocation allowed) -------------
__device__ float g_x  [BB*EE*HH];    // pooled + type_emb
__device__ float g_xn [BB*EE*HH];    // normalized
__device__ float g_sim[BB*EE*EE];
__device__ unsigned char g_Adj[BB*EE*EE];   // A[b][s][t]
__device__ float g_h1 [BB*EE*512];
__device__ float g_s1 [BB*EE*4];
__device__ float g_d1 [BB*EE*4];
__device__ float g_g1v[BB*EE*512];
__device__ float g_h2 [BB*EE*64];
__device__ float g_s2 [BB*EE];
__device__ float g_d2 [BB*EE];
__device__ float g_ent[BB*EE*64];
__device__ float g_clsp[BB*256];

// ============================================================================
// K1: NER head, fused  relu(seq@W1+b1)@W2+b2  -> out[0 : 270336]
// M=24576, N=256, K=768. 64x256 tile, 256 threads, 8x8 per-thread tile.
// ============================================================================
__global__ __launch_bounds__(256) void ner_kernel(
    const float* __restrict__ seq, const float* __restrict__ W1,
    const float* __restrict__ b1,  const float* __restrict__ W2,
    const float* __restrict__ b2,  float* __restrict__ out)
{
    __shared__ float As[64][16];
    __shared__ float Bs[16][256];
    __shared__ float W2s[256][NERC];
    __shared__ float b1s[256];
    __shared__ float b2s[NERC];

    int tid = threadIdx.x;
    int w = tid >> 5, tn = tid & 31;
    int m0 = blockIdx.x * 64;

    for (int i = tid; i < 256*NERC; i += 256) W2s[i/NERC][i%NERC] = W2[i];
    b1s[tid] = b1[tid];
    if (tid < NERC) b2s[tid] = b2[tid];

    float acc[8][8];
    #pragma unroll
    for (int i=0;i<8;i++)
        #pragma unroll
        for (int j=0;j<8;j++) acc[i][j]=0.f;

    int am = tid >> 2, aq = tid & 3;
    for (int k0 = 0; k0 < HH; k0 += 16) {
        __syncthreads();
        *(float4*)&As[am][aq*4] = *(const float4*)&seq[(m0+am)*HH + k0 + aq*4];
        #pragma unroll
        for (int r=0;r<4;r++){
            int lin = tid + 256*r;
            int k = lin >> 6, n4 = lin & 63;
            *(float4*)&Bs[k][n4*4] = *(const float4*)&W1[(k0+k)*256 + n4*4];
        }
        __syncthreads();
        #pragma unroll
        for (int kk=0;kk<16;kk++){
            float a[8];
            #pragma unroll
            for (int i=0;i<8;i++) a[i] = As[w*8+i][kk];
            float4 bl = *(float4*)&Bs[kk][tn*4];
            float4 bh = *(float4*)&Bs[kk][128+tn*4];
            float bv[8] = {bl.x,bl.y,bl.z,bl.w,bh.x,bh.y,bh.z,bh.w};
            #pragma unroll
            for (int i=0;i<8;i++)
                #pragma unroll
                for (int j=0;j<8;j++)
                    acc[i][j] = fmaf(a[i], bv[j], acc[i][j]);
        }
    }

    int cols[8];
    #pragma unroll
    for (int j=0;j<4;j++){ cols[j]=tn*4+j; cols[4+j]=128+tn*4+j; }

    #pragma unroll
    for (int i=0;i<8;i++){
        float rv[8];
        #pragma unroll
        for (int j=0;j<8;j++){
            float v = acc[i][j] + b1s[cols[j]];
            rv[j] = v > 0.f ? v : 0.f;
        }
        int row = m0 + w*8 + i;
        for (int jo=0; jo<NERC; jo++){
            float p = 0.f;
            #pragma unroll
            for (int j=0;j<8;j++) p = fmaf(rv[j], W2s[cols[j]][jo], p);
            #pragma unroll
            for (int off=16;off>0;off>>=1) p += __shfl_xor_sync(0xffffffffu,p,off);
            if (tn==0) out[row*NERC + jo] = p + b2s[jo];
        }
    }
}

// ============================================================================
// K2: span gather + mean + attention softmax + pooled + type_emb; also xn.
// One block per (b,e). Dynamic smem: 16*768 floats (tok tile).
// ============================================================================
__global__ __launch_bounds__(256) void pool_kernel(
    const float* __restrict__ seq, const int* __restrict__ span_start,
    const int* __restrict__ span_len, const int* __restrict__ ent_type,
    const float* __restrict__ type_emb)
{
    extern __shared__ float tok[];          // 16 x 768
    __shared__ float meanv[HH];
    __shared__ float sc[LL];
    __shared__ float wv[LL];
    __shared__ float red[8];

    int be = blockIdx.x;
    int b = be / EE;
    int tid = threadIdx.x;
    int start = span_start[be];
    int len = span_len[be];                 // mask: pos <= len  (len in [0,15])
    float cnt = (float)(len + 1);

    const float4* src = (const float4*)&seq[(size_t)(b*SS + start)*HH];
    float4* dst4 = (float4*)tok;
    for (int q = tid; q < LL*HH/4; q += 256) dst4[q] = src[q];
    __syncthreads();

    for (int d = tid; d < HH; d += 256){
        float s = 0.f;
        for (int l = 0; l <= len; l++) s += tok[l*HH + d];
        meanv[d] = s / cnt;
    }
    __syncthreads();

    int w = tid >> 5, lane = tid & 31;
    for (int l = w; l < LL; l += 8){
        float p = 0.f;
        for (int d = lane; d < HH; d += 32) p = fmaf(tok[l*HH+d], meanv[d], p);
        #pragma unroll
        for (int off=16;off>0;off>>=1) p += __shfl_xor_sync(0xffffffffu,p,off);
        if (lane==0) sc[l] = p;
    }
    __syncthreads();

    if (tid == 0){
        float mx = -1e30f;
        for (int l=0;l<=len;l++) mx = fmaxf(mx, sc[l]);
        float s = 0.f;
        for (int l=0;l<=len;l++){ float e = expf(sc[l]-mx); wv[l]=e; s+=e; }
        float inv = 1.f/s;
        for (int l=0;l<=len;l++) wv[l] *= inv;
        for (int l=len+1;l<LL;l++) wv[l] = 0.f;
    }
    __syncthreads();

    const float* te = &type_emb[ent_type[be]*HH];
    float xv[3]; float nsq = 0.f;
    #pragma unroll
    for (int q = 0; q < 3; q++){
        int d = tid + q*256;
        float p = 0.f;
        for (int l = 0; l <= len; l++) p = fmaf(wv[l], tok[l*HH+d], p);
        float v = p + te[d];
        xv[q] = v;
        g_x[(size_t)be*HH + d] = v;
        nsq = fmaf(v, v, nsq);
    }
    #pragma unroll
    for (int off=16;off>0;off>>=1) nsq += __shfl_xor_sync(0xffffffffu,nsq,off);
    if (lane==0) red[w] = nsq;
    __syncthreads();
    float tot = 0.f;
    #pragma unroll
    for (int i=0;i<8;i++) tot += red[i];
    float inv = 1.f / fmaxf(sqrtf(tot), 1e-12f);
    #pragma unroll
    for (int q=0;q<3;q++){
        int d = tid + q*256;
        g_xn[(size_t)be*HH + d] = xv[q]*inv;
    }
}

// ============================================================================
// K3: sim = xn @ xn^T per batch. 32x32 tiles, grid (48*16).
// ============================================================================
__global__ __launch_bounds__(256) void sim_kernel()
{
    __shared__ float Xa[32][33];
    __shared__ float Xb[32][33];
    int b = blockIdx.x >> 4;
    int tile = blockIdx.x & 15;
    int i0 = (tile >> 2)*32, j0 = (tile & 3)*32;
    int tid = threadIdx.x;
    int ty = tid >> 4, tx = tid & 15;
    const float* X = &g_xn[(size_t)b*EE*HH];
    float a00=0.f,a01=0.f,a10=0.f,a11=0.f;
    int r = tid >> 3, kq = tid & 7;
    for (int k0 = 0; k0 < HH; k0 += 32){
        __syncthreads();
        float4 va = *(const float4*)&X[(i0+r)*HH + k0 + kq*4];
        Xa[r][kq*4+0]=va.x; Xa[r][kq*4+1]=va.y; Xa[r][kq*4+2]=va.z; Xa[r][kq*4+3]=va.w;
        float4 vb = *(const float4*)&X[(j0+r)*HH + k0 + kq*4];
        Xb[r][kq*4+0]=vb.x; Xb[r][kq*4+1]=vb.y; Xb[r][kq*4+2]=vb.z; Xb[r][kq*4+3]=vb.w;
        __syncthreads();
        #pragma unroll
        for (int kk=0;kk<32;kk++){
            float x0 = Xa[ty*2][kk],  x1 = Xa[ty*2+1][kk];
            float y0 = Xb[tx*2][kk],  y1 = Xb[tx*2+1][kk];
            a00 = fmaf(x0,y0,a00); a01 = fmaf(x0,y1,a01);
            a10 = fmaf(x1,y0,a10); a11 = fmaf(x1,y1,a11);
        }
    }
    float* simb = &g_sim[(size_t)b*EE*EE];
    simb[(i0+ty*2  )*EE + j0+tx*2  ] = a00;
    simb[(i0+ty*2  )*EE + j0+tx*2+1] = a01;
    simb[(i0+ty*2+1)*EE + j0+tx*2  ] = a10;
    simb[(i0+ty*2+1)*EE + j0+tx*2+1] = a11;
}

// ============================================================================
// K4: top-6 per row, build adjacency A[b][s][t] (valid>0.1, no self, + eye)
// ============================================================================
__global__ __launch_bounds__(128) void topk_kernel()
{
    int b = blockIdx.x, i = threadIdx.x;
    const float* row = &g_sim[(size_t)(b*EE + i)*EE];
    unsigned char* Ar = &g_Adj[(size_t)(b*EE + i)*EE];
    unsigned long long u0 = 0ull, u1 = 0ull;
    int pick[6]; float pval[6];
    for (int k=0;k<6;k++){
        float best = -1e30f; int bi = 0;
        for (int j=0;j<EE;j++){
            bool used = (j<64) ? ((u0>>j)&1ull) : ((u1>>(j-64))&1ull);
            if (used) continue;
            float v = row[j];
            if (v > best){ best = v; bi = j; }   // strict > : lowest index on ties (lax.top_k)
        }
        pick[k]=bi; pval[k]=best;
        if (bi<64) u0 |= (1ull<<bi); else u1 |= (1ull<<(bi-64));
    }
    for (int j=0;j<EE;j++) Ar[j] = 0;
    #pragma unroll
    for (int k=0;k<6;k++)
        if (pval[k] > 0.1f && pick[k] != i) Ar[pick[k]] = 1;
    Ar[i] = 1;
}

// ============================================================================
// K5: h1 = x @ W_g1  (6144x768 @ 768x512). Same tiling as ner_kernel.
// ============================================================================
__global__ __launch_bounds__(256) void gat1_gemm_kernel(const float* __restrict__ Wg1)
{
    __shared__ float As[64][16];
    __shared__ float Bs[16][256];
    int tid = threadIdx.x, w = tid>>5, tn = tid&31;
    int m0 = blockIdx.x*64, n0 = blockIdx.y*256;
    float acc[8][8];
    #pragma unroll
    for (int i=0;i<8;i++)
        #pragma unroll
        for (int j=0;j<8;j++) acc[i][j]=0.f;
    int am = tid>>2, aq = tid&3;
    for (int k0=0;k0<HH;k0+=16){
        __syncthreads();
        *(float4*)&As[am][aq*4] = *(const float4*)&g_x[(size_t)(m0+am)*HH + k0 + aq*4];
        #pragma unroll
        for (int r=0;r<4;r++){
            int lin = tid + 256*r;
            int k = lin>>6, n4 = lin&63;
            *(float4*)&Bs[k][n4*4] = *(const float4*)&Wg1[(k0+k)*512 + n0 + n4*4];
        }
        __syncthreads();
        #pragma unroll
        for (int kk=0;kk<16;kk++){
            float a[8];
            #pragma unroll
            for (int i=0;i<8;i++) a[i] = As[w*8+i][kk];
            float4 bl = *(float4*)&Bs[kk][tn*4];
            float4 bh = *(float4*)&Bs[kk][128+tn*4];
            float bv[8] = {bl.x,bl.y,bl.z,bl.w,bh.x,bh.y,bh.z,bh.w};
            #pragma unroll
            for (int i=0;i<8;i++)
                #pragma unroll
                for (int j=0;j<8;j++)
                    acc[i][j] = fmaf(a[i], bv[j], acc[i][j]);
        }
    }
    #pragma unroll
    for (int i=0;i<8;i++){
        int row = m0 + w*8 + i;
        *(float4*)&g_h1[(size_t)row*512 + n0 + tn*4] =
            make_float4(acc[i][0],acc[i][1],acc[i][2],acc[i][3]);
        *(float4*)&g_h1[(size_t)row*512 + n0 + 128 + tn*4] =
            make_float4(acc[i][4],acc[i][5],acc[i][6],acc[i][7]);
    }
}

// ============================================================================
// K6: per-row src/dst attention dots for GAT1 (4 heads x 128)
// ============================================================================
__global__ __launch_bounds__(128) void sd1_kernel(const float* __restrict__ a_src,
                                                  const float* __restrict__ a_dst)
{
    int row = blockIdx.x;
    int hd = threadIdx.x >> 5, lane = threadIdx.x & 31;
    const float* hrow = &g_h1[(size_t)row*512 + hd*128];
    float ps = 0.f, pd = 0.f;
    #pragma unroll
    for (int q=0;q<4;q++){
        float hv = hrow[lane + 32*q];
        ps = fmaf(hv, a_src[hd*128 + lane + 32*q], ps);
        pd = fmaf(hv, a_dst[hd*128 + lane + 32*q], pd);
    }
    #pragma unroll
    for (int off=16;off>0;off>>=1){
        ps += __shfl_xor_sync(0xffffffffu,ps,off);
        pd += __shfl_xor_sync(0xffffffffu,pd,off);
    }
    if (lane==0){ g_s1[row*4+hd]=ps; g_d1[row*4+hd]=pd; }
}

// ============================================================================
// K7: GAT1 attention + bias + LN + elu -> g1.  Block per (b, t).
// ============================================================================
__global__ __launch_bounds__(128) void att1_kernel(
    const float* __restrict__ b_g1, const float* __restrict__ gamma,
    const float* __restrict__ beta)
{
    __shared__ int act[EE];
    __shared__ int wcnt[4], woff[4];
    __shared__ int nact_s;
    __shared__ float wts[4][EE];
    __shared__ float red[4], red2[4];

    int be = blockIdx.x;
    int b = be / EE, t = be % EE;
    int tid = threadIdx.x, w = tid>>5, lane = tid&31;

    bool flag = g_Adj[(size_t)(b*EE + tid)*EE + t] != 0;
    unsigned mball = __ballot_sync(0xffffffffu, flag);
    if (lane==0) wcnt[w] = __popc(mball);
    __syncthreads();
    if (tid==0){ int o=0; for (int i2=0;i2<4;i2++){ woff[i2]=o; o+=wcnt[i2]; } nact_s=o; }
    __syncthreads();
    if (flag) act[woff[w] + __popc(mball & ((1u<<lane)-1u))] = tid;
    __syncthreads();
    int nact = nact_s;

    {   // warp w == head hd
        int hd = w;
        float dv = g_d1[be*4 + hd];
        float mx = -1e30f;
        for (int k=lane;k<nact;k+=32){
            float e = g_s1[(b*EE+act[k])*4 + hd] + dv;
            e = e > 0.f ? e : 0.2f*e;                    // leaky_relu(0.2)
            wts[hd][k] = e;
            mx = fmaxf(mx, e);
        }
        #pragma unroll
        for (int off=16;off>0;off>>=1) mx = fmaxf(mx, __shfl_xor_sync(0xffffffffu,mx,off));
        float sum = 0.f;
        for (int k=lane;k<nact;k+=32){
            float e = expf(wts[hd][k]-mx);
            wts[hd][k] = e; sum += e;
        }
        #pragma unroll
        for (int off=16;off>0;off>>=1) sum += __shfl_xor_sync(0xffffffffu,sum,off);
        float inv = 1.f/sum;
        for (int k=lane;k<nact;k+=32) wts[hd][k] *= inv;
    }
    __syncthreads();

    float ov[4];
    #pragma unroll
    for (int q=0;q<4;q++){
        int f = tid + q*128;                  // head = q
        float o = 0.f;
        for (int k=0;k<nact;k++)
            o = fmaf(wts[q][k], g_h1[(size_t)(b*EE+act[k])*512 + f], o);
        ov[q] = o + b_g1[f];
    }
    float ls = ov[0]+ov[1]+ov[2]+ov[3];
    #pragma unroll
    for (int off=16;off>0;off>>=1) ls += __shfl_xor_sync(0xffffffffu,ls,off);
    if (lane==0) red[w] = ls;
    __syncthreads();
    float mean = (red[0]+red[1]+red[2]+red[3]) * (1.f/512.f);
    float lv = 0.f;
    #pragma unroll
    for (int q=0;q<4;q++){ float d = ov[q]-mean; lv = fmaf(d,d,lv); }
    #pragma unroll
    for (int off=16;off>0;off>>=1) lv += __shfl_xor_sync(0xffffffffu,lv,off);
    if (lane==0) red2[w] = lv;
    __syncthreads();
    float var = (red2[0]+red2[1]+red2[2]+red2[3]) * (1.f/512.f);
    float rstd = rsqrtf(var + 1e-5f);
    #pragma unroll
    for (int q=0;q<4;q++){
        int f = tid + q*128;
        float y = (ov[q]-mean)*rstd*gamma[f] + beta[f];
        y = y > 0.f ? y : expm1f(y);                     // elu
        g_g1v[(size_t)be*512 + f] = y;
    }
}

// ============================================================================
// K8: h2 = g1 @ W_g2 (512->64), plus s2/d2 dots. Block per row, 64 threads.
// ============================================================================
__global__ __launch_bounds__(64) void gat2h_kernel(
    const float* __restrict__ Wg2, const float* __restrict__ a_src2,
    const float* __restrict__ a_dst2)
{
    __shared__ float grow[512];
    __shared__ float rs[2], rd[2];
    int row = blockIdx.x, tid = threadIdx.x;
    for (int i=tid;i<512;i+=64) grow[i] = g_g1v[(size_t)row*512 + i];
    __syncthreads();
    float acc = 0.f;
    for (int k=0;k<512;k++) acc = fmaf(grow[k], Wg2[k*64 + tid], acc);
    g_h2[(size_t)row*64 + tid] = acc;
    float ps = acc * a_src2[tid];
    float pd = acc * a_dst2[tid];
    #pragma unroll
    for (int off=16;off>0;off>>=1){
        ps += __shfl_xor_sync(0xffffffffu,ps,off);
        pd += __shfl_xor_sync(0xffffffffu,pd,off);
    }
    int w = tid>>5, lane = tid&31;
    if (lane==0){ rs[w]=ps; rd[w]=pd; }
    __syncthreads();
    if (tid==0){ g_s2[row]=rs[0]+rs[1]; g_d2[row]=rd[0]+rd[1]; }
}

// ============================================================================
// K9: GAT2 attention + bias + LN + elu -> ent.  Block per (b, t).
// ============================================================================
__global__ __launch_bounds__(128) void att2_kernel(
    const float* __restrict__ b_g2, const float* __restrict__ gamma,
    const float* __restrict__ beta)
{
    __shared__ int act[EE];
    __shared__ int wcnt[4], woff[4];
    __shared__ int nact_s;
    __shared__ float wts[EE];
    __shared__ float red[2], red2[2];

    int be = blockIdx.x;
    int b = be / EE, t = be % EE;
    int tid = threadIdx.x, w = tid>>5, lane = tid&31;

    bool flag = g_Adj[(size_t)(b*EE + tid)*EE + t] != 0;
    unsigned mball = __ballot_sync(0xffffffffu, flag);
    if (lane==0) wcnt[w] = __popc(mball);
    __syncthreads();
    if (tid==0){ int o=0; for (int i2=0;i2<4;i2++){ woff[i2]=o; o+=wcnt[i2]; } nact_s=o; }
    __syncthreads();
    if (flag) act[woff[w] + __popc(mball & ((1u<<lane)-1u))] = tid;
    __syncthreads();
    int nact = nact_s;

    if (w == 0){
        float dv = g_d2[be];
        float mx = -1e30f;
        for (int k=lane;k<nact;k+=32){
            float e = g_s2[b*EE + act[k]] + dv;
            e = e > 0.f ? e : 0.2f*e;
            wts[k] = e;
            mx = fmaxf(mx, e);
        }
        #pragma unroll
        for (int off=16;off>0;off>>=1) mx = fmaxf(mx, __shfl_xor_sync(0xffffffffu,mx,off));
        float sum = 0.f;
        for (int k=lane;k<nact;k+=32){
            float e = expf(wts[k]-mx);
            wts[k] = e; sum += e;
        }
        #pragma unroll
        for (int off=16;off>0;off>>=1) sum += __shfl_xor_sync(0xffffffffu,sum,off);
        float inv = 1.f/sum;
        for (int k=lane;k<nact;k+=32) wts[k] *= inv;
    }
    __syncthreads();

    float o = 0.f;
    if (tid < 64){
        for (int k=0;k<nact;k++)
            o = fmaf(wts[k], g_h2[(size_t)(b*EE+act[k])*64 + tid], o);
        o += b_g2[tid];
    }
    float ls = (tid<64) ? o : 0.f;
    #pragma unroll
    for (int off=16;off>0;off>>=1) ls += __shfl_xor_sync(0xffffffffu,ls,off);
    if (w < 2 && lane==0) red[w] = ls;
    __syncthreads();
    float mean = (red[0]+red[1]) * (1.f/64.f);
    float dv2 = (tid<64) ? (o-mean) : 0.f;
    float lv = dv2*dv2;
    #pragma unroll
    for (int off=16;off>0;off>>=1) lv += __shfl_xor_sync(0xffffffffu,lv,off);
    if (w < 2 && lane==0) red2[w] = lv;
    __syncthreads();
    float var = (red2[0]+red2[1]) * (1.f/64.f);
    if (tid < 64){
        float y = (o-mean)*rsqrtf(var+1e-5f)*gamma[tid] + beta[tid];
        y = y > 0.f ? y : expm1f(y);
        g_ent[(size_t)be*64 + tid] = y;
    }
}

// ============================================================================
// K10: per-batch cls contribution through W_r1 rows [160:928]
// ============================================================================
__global__ __launch_bounds__(256) void cls_kernel(const float* __restrict__ seq,
                                                  const float* __restrict__ W_r1)
{
    __shared__ float c[HH];
    int b = blockIdx.x, tid = threadIdx.x;
    for (int d=tid; d<HH; d+=256) c[d] = seq[(size_t)b*SS*HH + d];
    __syncthreads();
    float acc = 0.f;
    for (int d=0; d<HH; d++) acc = fmaf(c[d], W_r1[(160+d)*256 + tid], acc);
    g_clsp[b*256 + tid] = acc;
}

// ============================================================================
// K11: relation head per pair: relu(feat@W_r1+b_r1)@W_r2+b_r2
// ============================================================================
__global__ __launch_bounds__(256) void pair_kernel(
    const int* __restrict__ pair_head, const int* __restrict__ pair_tail,
    const int* __restrict__ pair_rel,  const float* __restrict__ rel_emb,
    const float* __restrict__ W_r1,    const float* __restrict__ b_r1,
    const float* __restrict__ W_r2,    const float* __restrict__ b_r2,
    float* __restrict__ out)
{
    __shared__ float hv[64], tv[64], rv[32];
    __shared__ float red[8];
    int bp = blockIdx.x;
    int b = bp / PP;
    int tid = threadIdx.x;
    int hidx = pair_head[bp], tidx = pair_tail[bp], ridx = pair_rel[bp];
    if (tid < 64)        hv[tid]      = g_ent[(size_t)(b*EE+hidx)*64 + tid];
    else if (tid < 128)  tv[tid-64]   = g_ent[(size_t)(b*EE+tidx)*64 + (tid-64)];
    else if (tid < 160)  rv[tid-128]  = rel_emb[ridx*32 + (tid-128)];
    __syncthreads();
    float pre = b_r1[tid] + g_clsp[b*256 + tid];
    #pragma unroll 8
    for (int f=0;f<64;f++) pre = fmaf(hv[f], W_r1[f*256 + tid], pre);
    #pragma unroll 8
    for (int f=0;f<64;f++) pre = fmaf(tv[f], W_r1[(64+f)*256 + tid], pre);
    #pragma unroll 8
    for (int k=0;k<32;k++) pre = fmaf(rv[k], W_r1[(128+k)*256 + tid], pre);
    pre = fmaxf(pre, 0.f);
    float part = pre * W_r2[tid];
    #pragma unroll
    for (int off=16;off>0;off>>=1) part += __shfl_xor_sync(0xffffffffu,part,off);
    if ((tid&31)==0) red[tid>>5] = part;
    __syncthreads();
    if (tid==0){
        float s = 0.f;
        for (int i=0;i<8;i++) s += red[i];
        out[NER_TOTAL + bp] = s + b_r2[0];
    }
}

// ============================================================================
extern "C" void kernel_launch(void* const* d_in, const int* in_sizes, int n_in,
                              void* d_out, int out_size)
{
    (void)in_sizes; (void)n_in; (void)out_size;
    const float* seq       = (const float*)d_in[0];
    const int*   span_start= (const int*)d_in[1];
    const int*   span_len  = (const int*)d_in[2];
    const int*   ent_type  = (const int*)d_in[3];
    const int*   pair_head = (const int*)d_in[4];
    const int*   pair_tail = (const int*)d_in[5];
    const int*   pair_rel  = (const int*)d_in[6];
    const float* W_ner1    = (const float*)d_in[7];
    const float* b_ner1    = (const float*)d_in[8];
    const float* W_ner2    = (const float*)d_in[9];
    const float* b_ner2    = (const float*)d_in[10];
    const float* type_emb  = (const float*)d_in[11];
    const float* W_g1      = (const float*)d_in[12];
    const float* a_src1    = (const float*)d_in[13];
    const float* a_dst1    = (const float*)d_in[14];
    const float* b_g1      = (const float*)d_in[15];
    const float* g1_gamma  = (const float*)d_in[16];
    const float* g1_beta   = (const float*)d_in[17];
    const float* W_g2      = (const float*)d_in[18];
    const float* a_src2    = (const float*)d_in[19];
    const float* a_dst2    = (const float*)d_in[20];
    const float* b_g2      = (const float*)d_in[21];
    const float* g2_gamma  = (const float*)d_in[22];
    const float* g2_beta   = (const float*)d_in[23];
    const float* rel_emb   = (const float*)d_in[24];
    const float* W_r1      = (const float*)d_in[25];
    const float* b_r1      = (const float*)d_in[26];
    const float* W_r2      = (const float*)d_in[27];
    const float* b_r2      = (const float*)d_in[28];
    float* out = (float*)d_out;

    cudaFuncSetAttribute((const void*)pool_kernel,
                         cudaFuncAttributeMaxDynamicSharedMemorySize, 65536);

    ner_kernel<<<(BB*SS)/64, 256>>>(seq, W_ner1, b_ner1, W_ner2, b_ner2, out);
    pool_kernel<<<BB*EE, 256, LL*HH*sizeof(float)>>>(seq, span_start, span_len,
                                                     ent_type, type_emb);
    sim_kernel<<<BB*16, 256>>>();
    topk_kernel<<<BB, 128>>>();
    gat1_gemm_kernel<<<dim3((BB*EE)/64, 2), 256>>>(W_g1);
    sd1_kernel<<<BB*EE, 128>>>(a_src1, a_dst1);
    att1_kernel<<<BB*EE, 128>>>(b_g1, g1_gamma, g1_beta);
    gat2h_kernel<<<BB*EE, 64>>>(W_g2, a_src2, a_dst2);
    att2_kernel<<<BB*EE, 128>>>(b_g2, g2_gamma, g2_beta);
    cls_kernel<<<BB, 256>>>(seq, W_r1);
    pair_kernel<<<BB*PP, 256>>>(pair_head, pair_tail, pair_rel, rel_emb,
                                W_r1, b_r1, W_r2, b_r2, out);
}

// round 2
// speedup vs baseline: 1.1824x; 1.1824x over previous
#include <cuda_runtime.h>
#include <math.h>

#define BB 48
#define SS 512
#define HH 768
#define EE 128
#define LL 16
#define PP 256
#define NERC 11
#define NER_TOTAL (BB*SS*NERC)   // 270336

// ---------------- scratch (device globals; no allocation allowed) -------------
__device__ float g_x  [BB*EE*HH];    // pooled + type_emb
__device__ float g_xn [BB*EE*HH];    // normalized
__device__ float g_sim[BB*EE*EE];
__device__ unsigned char g_Adj[BB*EE*EE];   // A[b][s][t]
__device__ float g_h1 [BB*EE*512];
__device__ float g_s1 [BB*EE*4];
__device__ float g_d1 [BB*EE*4];
__device__ float g_g1v[BB*EE*512];
__device__ float g_h2 [BB*EE*64];
__device__ float g_s2 [BB*EE];
__device__ float g_d2 [BB*EE];
__device__ float g_ent[BB*EE*64];
__device__ float g_clsp[BB*256];

// packed f32x2 FMA (PTX-only; identical rounding per lane-half vs scalar fmaf)
__device__ __forceinline__ unsigned long long ffma2(unsigned long long a,
                                                    unsigned long long b,
                                                    unsigned long long c){
    unsigned long long d;
    asm("fma.rn.f32x2 %0, %1, %2, %3;" : "=l"(d) : "l"(a), "l"(b), "l"(c));
    return d;
}
union F2U { unsigned long long u; float2 f; };

// ============================================================================
// K1: NER head, fused relu(seq@W1+b1)@W2+b2 -> out[0:270336]
// M=24576 tiled 32, N=256, K=768 (48 chunks of 16). 256 thr, FFMA2, dbl-buffer.
// Dynamic smem layout (floats):
//   [0,2048)      As2  2 bufs x 32 rows x 32 (k-pairs duplicated)
//   [2048,10240)  Bs   2 bufs x 16 x 256
//   [10240,13056) W2s  256*11
//   [13056,13312) b1s
//   [13312,13328) b2s
// ============================================================================
__global__ __launch_bounds__(256) void ner_kernel(
    const float* __restrict__ seq, const float* __restrict__ W1,
    const float* __restrict__ b1,  const float* __restrict__ W2,
    const float* __restrict__ b2,  float* __restrict__ out)
{
    extern __shared__ float sm[];
    float* As = sm;              // +buf*1024 + m*32 + 2*kk
    float* Bs = sm + 2048;       // +buf*4096 + kk*256 + n
    float* W2s = sm + 10240;
    float* b1s = sm + 13056;
    float* b2s = sm + 13312;

    int tid = threadIdx.x, w = tid >> 5, tn = tid & 31;
    int m0 = blockIdx.x * 32;

    for (int i = tid; i < 256*NERC; i += 256) W2s[i] = W2[i];
    b1s[tid] = b1[tid];
    if (tid < NERC) b2s[tid] = b2[tid];

    unsigned long long acc2[4][4];
    #pragma unroll
    for (int i=0;i<4;i++)
        #pragma unroll
        for (int p=0;p<4;p++) acc2[i][p] = 0ull;

    int am = tid >> 3, aq = tid & 7;           // A loader: row, k-pair
    const float* aP = seq + (size_t)(m0+am)*HH + aq*2;
    int kr[4], nf[4];
    #pragma unroll
    for (int r=0;r<4;r++){ int lin = tid + 256*r; kr[r]=lin>>6; nf[r]=(lin&63)*4; }

    float2 ra; float4 rb[4];
    // chunk 0 prefetch
    ra = *(const float2*)(aP);
    #pragma unroll
    for (int r=0;r<4;r++) rb[r] = *(const float4*)&W1[kr[r]*256 + nf[r]];
    // store chunk 0 -> buf 0
    *(float4*)&As[am*32 + aq*4] = make_float4(ra.x, ra.x, ra.y, ra.y);
    #pragma unroll
    for (int r=0;r<4;r++) *(float4*)&Bs[kr[r]*256 + nf[r]] = rb[r];

    for (int c = 0; c < 48; c++){
        int cur = c & 1;
        __syncthreads();
        if (c + 1 < 48){
            int k0n = (c+1)*16;
            ra = *(const float2*)(aP + k0n);
            #pragma unroll
            for (int r=0;r<4;r++)
                rb[r] = *(const float4*)&W1[(k0n+kr[r])*256 + nf[r]];
        }
        const float* Ab = &As[cur*1024];
        const float* Bb = &Bs[cur*4096];
        #pragma unroll
        for (int kk=0;kk<16;kk++){
            ulonglong2 bl = *(const ulonglong2*)&Bb[kk*256 + tn*4];
            ulonglong2 bh = *(const ulonglong2*)&Bb[kk*256 + 128 + tn*4];
            unsigned long long bv0=bl.x, bv1=bl.y, bv2=bh.x, bv3=bh.y;
            #pragma unroll
            for (int i=0;i<4;i++){
                unsigned long long a2 = *(const unsigned long long*)&Ab[(w*4+i)*32 + kk*2];
                acc2[i][0] = ffma2(a2, bv0, acc2[i][0]);
                acc2[i][1] = ffma2(a2, bv1, acc2[i][1]);
                acc2[i][2] = ffma2(a2, bv2, acc2[i][2]);
                acc2[i][3] = ffma2(a2, bv3, acc2[i][3]);
            }
        }
        if (c + 1 < 48){
            __syncthreads();
            float* An = &As[(1-cur)*1024];
            float* Bn = &Bs[(1-cur)*4096];
            *(float4*)&An[am*32 + aq*4] = make_float4(ra.x, ra.x, ra.y, ra.y);
            #pragma unroll
            for (int r=0;r<4;r++) *(float4*)&Bn[kr[r]*256 + nf[r]] = rb[r];
        }
    }

    int cols[8];
    #pragma unroll
    for (int j=0;j<4;j++){ cols[j]=tn*4+j; cols[4+j]=128+tn*4+j; }

    #pragma unroll
    for (int i=0;i<4;i++){
        float rv[8];
        #pragma unroll
        for (int p=0;p<4;p++){
            F2U u; u.u = acc2[i][p];
            rv[2*p]   = u.f.x;
            rv[2*p+1] = u.f.y;
        }
        #pragma unroll
        for (int j=0;j<8;j++){
            float v = rv[j] + b1s[cols[j]];
            rv[j] = v > 0.f ? v : 0.f;
        }
        int row = m0 + w*4 + i;
        for (int jo=0; jo<NERC; jo++){
            float p = 0.f;
            #pragma unroll
            for (int j=0;j<8;j++) p = fmaf(rv[j], W2s[cols[j]*NERC + jo], p);
            #pragma unroll
            for (int off=16;off>0;off>>=1) p += __shfl_xor_sync(0xffffffffu,p,off);
            if (tn==0) out[row*NERC + jo] = p + b2s[jo];
        }
    }
}

// ============================================================================
// K2: span gather + mean + attention softmax + pooled + type_emb; also xn.
// ============================================================================
__global__ __launch_bounds__(256) void pool_kernel(
    const float* __restrict__ seq, const int* __restrict__ span_start,
    const int* __restrict__ span_len, const int* __restrict__ ent_type,
    const float* __restrict__ type_emb)
{
    extern __shared__ float tok[];          // 16 x 768
    __shared__ float meanv[HH];
    __shared__ float sc[LL];
    __shared__ float wv[LL];
    __shared__ float red[8];

    int be = blockIdx.x;
    int b = be / EE;
    int tid = threadIdx.x;
    int start = span_start[be];
    int len = span_len[be];
    float cnt = (float)(len + 1);

    const float4* src = (const float4*)&seq[(size_t)(b*SS + start)*HH];
    float4* dst4 = (float4*)tok;
    for (int q = tid; q < LL*HH/4; q += 256) dst4[q] = src[q];
    __syncthreads();

    for (int d = tid; d < HH; d += 256){
        float s = 0.f;
        for (int l = 0; l <= len; l++) s += tok[l*HH + d];
        meanv[d] = s / cnt;
    }
    __syncthreads();

    int w = tid >> 5, lane = tid & 31;
    for (int l = w; l < LL; l += 8){
        float p = 0.f;
        for (int d = lane; d < HH; d += 32) p = fmaf(tok[l*HH+d], meanv[d], p);
        #pragma unroll
        for (int off=16;off>0;off>>=1) p += __shfl_xor_sync(0xffffffffu,p,off);
        if (lane==0) sc[l] = p;
    }
    __syncthreads();

    if (tid == 0){
        float mx = -1e30f;
        for (int l=0;l<=len;l++) mx = fmaxf(mx, sc[l]);
        float s = 0.f;
        for (int l=0;l<=len;l++){ float e = expf(sc[l]-mx); wv[l]=e; s+=e; }
        float inv = 1.f/s;
        for (int l=0;l<=len;l++) wv[l] *= inv;
        for (int l=len+1;l<LL;l++) wv[l] = 0.f;
    }
    __syncthreads();

    const float* te = &type_emb[ent_type[be]*HH];
    float xv[3]; float nsq = 0.f;
    #pragma unroll
    for (int q = 0; q < 3; q++){
        int d = tid + q*256;
        float p = 0.f;
        for (int l = 0; l <= len; l++) p = fmaf(wv[l], tok[l*HH+d], p);
        float v = p + te[d];
        xv[q] = v;
        g_x[(size_t)be*HH + d] = v;
        nsq = fmaf(v, v, nsq);
    }
    #pragma unroll
    for (int off=16;off>0;off>>=1) nsq += __shfl_xor_sync(0xffffffffu,nsq,off);
    if (lane==0) red[w] = nsq;
    __syncthreads();
    float tot = 0.f;
    #pragma unroll
    for (int i=0;i<8;i++) tot += red[i];
    float inv = 1.f / fmaxf(sqrtf(tot), 1e-12f);
    #pragma unroll
    for (int q=0;q<3;q++){
        int d = tid + q*256;
        g_xn[(size_t)be*HH + d] = xv[q]*inv;
    }
}

// ============================================================================
// K3: sim = xn @ xn^T per batch. 64x64 tiles, 4x4/thread. grid 48*4.
// Xa row-major (broadcast reads); Xbt k-major.
// ============================================================================
__global__ __launch_bounds__(256) void sim_kernel()
{
    __shared__ float Xa[64][36];
    __shared__ float Xbt[32][65];
    int b = blockIdx.x >> 2;
    int tile = blockIdx.x & 3;
    int i0 = (tile >> 1)*64, j0 = (tile & 1)*64;
    int tid = threadIdx.x;
    int ty = tid >> 4, tx = tid & 15;
    const float* X = &g_xn[(size_t)b*EE*HH];
    float acc[4][4];
    #pragma unroll
    for (int i=0;i<4;i++)
        #pragma unroll
        for (int j=0;j<4;j++) acc[i][j]=0.f;

    int r = tid >> 2, q = tid & 3;
    for (int k0 = 0; k0 < HH; k0 += 32){
        __syncthreads();
        #pragma unroll
        for (int h=0;h<2;h++){
            int kq = q + 4*h;
            float4 va = *(const float4*)&X[(i0+r)*HH + k0 + kq*4];
            *(float4*)&Xa[r][kq*4] = va;
            float4 vb = *(const float4*)&X[(j0+r)*HH + k0 + kq*4];
            Xbt[kq*4+0][r] = vb.x;
            Xbt[kq*4+1][r] = vb.y;
            Xbt[kq*4+2][r] = vb.z;
            Xbt[kq*4+3][r] = vb.w;
        }
        __syncthreads();
        #pragma unroll
        for (int kk=0;kk<32;kk++){
            float a[4], c[4];
            #pragma unroll
            for (int i=0;i<4;i++) a[i] = Xa[ty*4+i][kk];
            #pragma unroll
            for (int j=0;j<4;j++) c[j] = Xbt[kk][tx*4+j];
            #pragma unroll
            for (int i=0;i<4;i++)
                #pragma unroll
                for (int j=0;j<4;j++)
                    acc[i][j] = fmaf(a[i], c[j], acc[i][j]);
        }
    }
    float* simb = &g_sim[(size_t)b*EE*EE];
    #pragma unroll
    for (int i=0;i<4;i++)
        #pragma unroll
        for (int j=0;j<4;j++)
            simb[(i0+ty*4+i)*EE + j0+tx*4+j] = acc[i][j];
}

// ============================================================================
// K4: warp-per-row top-6 -> adjacency. grid 768, block 256 (8 warps).
// Tie-break: max value, then lowest index (matches lax.top_k).
// ============================================================================
__global__ __launch_bounds__(256) void topk_kernel()
{
    int w = threadIdx.x >> 5, lane = threadIdx.x & 31;
    int row = blockIdx.x*8 + w;            // 0..6143
    int i = row & 127;
    const float* r = &g_sim[(size_t)row*EE];
    float v[4];
    #pragma unroll
    for (int q=0;q<4;q++) v[q] = r[lane + q*32];
    unsigned used = 0;
    int pick[6]; float pval[6];
    for (int k=0;k<6;k++){
        float bv = -1e30f; int bj = 128;
        #pragma unroll
        for (int q=0;q<4;q++){
            if (!((used>>q)&1u)){
                int j = lane + q*32;
                if (v[q] > bv){ bv = v[q]; bj = j; }
            }
        }
        #pragma unroll
        for (int off=16; off>0; off>>=1){
            float ov = __shfl_xor_sync(0xffffffffu, bv, off);
            int   oj = __shfl_xor_sync(0xffffffffu, bj, off);
            if (ov > bv || (ov == bv && oj < bj)){ bv = ov; bj = oj; }
        }
        pick[k]=bj; pval[k]=bv;
        if ((bj & 31) == lane) used |= 1u << (bj >> 5);
    }
    int jb = lane*4;
    unsigned char c0=0,c1=0,c2=0,c3=0;
    #pragma unroll
    for (int k=0;k<6;k++){
        if (pval[k] > 0.1f && pick[k] != i){
            int d = pick[k] - jb;
            if (d==0) c0=1; else if (d==1) c1=1; else if (d==2) c2=1; else if (d==3) c3=1;
        }
    }
    int ds = i - jb;
    if (ds>=0 && ds<4){ if(ds==0)c0=1; else if(ds==1)c1=1; else if(ds==2)c2=1; else c3=1; }
    *(uchar4*)&g_Adj[(size_t)row*EE + jb] = make_uchar4(c0,c1,c2,c3);
}

// ============================================================================
// K5: h1 = x @ W_g1 (6144x768 @ 768x512). M=32,N=256 tiles, FFMA2, dbl-buf.
// ============================================================================
__global__ __launch_bounds__(256) void gat1_gemm_kernel(const float* __restrict__ Wg1)
{
    __shared__ float As[2*1024];
    __shared__ float Bs[2*4096];
    int tid = threadIdx.x, w = tid>>5, tn = tid&31;
    int m0 = blockIdx.x*32, n0 = blockIdx.y*256;

    unsigned long long acc2[4][4];
    #pragma unroll
    for (int i=0;i<4;i++)
        #pragma unroll
        for (int p=0;p<4;p++) acc2[i][p]=0ull;

    int am = tid>>3, aq = tid&7;
    const float* aP = g_x + (size_t)(m0+am)*HH + aq*2;
    int kr[4], nf[4];
    #pragma unroll
    for (int r=0;r<4;r++){ int lin = tid + 256*r; kr[r]=lin>>6; nf[r]=(lin&63)*4; }

    float2 ra; float4 rb[4];
    ra = *(const float2*)(aP);
    #pragma unroll
    for (int r=0;r<4;r++) rb[r] = *(const float4*)&Wg1[kr[r]*512 + n0 + nf[r]];
    *(float4*)&As[am*32 + aq*4] = make_float4(ra.x, ra.x, ra.y, ra.y);
    #pragma unroll
    for (int r=0;r<4;r++) *(float4*)&Bs[kr[r]*256 + nf[r]] = rb[r];

    for (int c = 0; c < 48; c++){
        int cur = c & 1;
        __syncthreads();
        if (c + 1 < 48){
            int k0n = (c+1)*16;
            ra = *(const float2*)(aP + k0n);
            #pragma unroll
            for (int r=0;r<4;r++)
                rb[r] = *(const float4*)&Wg1[(k0n+kr[r])*512 + n0 + nf[r]];
        }
        const float* Ab = &As[cur*1024];
        const float* Bb = &Bs[cur*4096];
        #pragma unroll
        for (int kk=0;kk<16;kk++){
            ulonglong2 bl = *(const ulonglong2*)&Bb[kk*256 + tn*4];
            ulonglong2 bh = *(const ulonglong2*)&Bb[kk*256 + 128 + tn*4];
            unsigned long long bv0=bl.x, bv1=bl.y, bv2=bh.x, bv3=bh.y;
            #pragma unroll
            for (int i=0;i<4;i++){
                unsigned long long a2 = *(const unsigned long long*)&Ab[(w*4+i)*32 + kk*2];
                acc2[i][0] = ffma2(a2, bv0, acc2[i][0]);
                acc2[i][1] = ffma2(a2, bv1, acc2[i][1]);
                acc2[i][2] = ffma2(a2, bv2, acc2[i][2]);
                acc2[i][3] = ffma2(a2, bv3, acc2[i][3]);
            }
        }
        if (c + 1 < 48){
            __syncthreads();
            float* An = &As[(1-cur)*1024];
            float* Bn = &Bs[(1-cur)*4096];
            *(float4*)&An[am*32 + aq*4] = make_float4(ra.x, ra.x, ra.y, ra.y);
            #pragma unroll
            for (int r=0;r<4;r++) *(float4*)&Bn[kr[r]*256 + nf[r]] = rb[r];
        }
    }

    #pragma unroll
    for (int i=0;i<4;i++){
        int row = m0 + w*4 + i;
        F2U u0,u1,u2,u3;
        u0.u=acc2[i][0]; u1.u=acc2[i][1]; u2.u=acc2[i][2]; u3.u=acc2[i][3];
        *(float4*)&g_h1[(size_t)row*512 + n0 + tn*4] =
            make_float4(u0.f.x,u0.f.y,u1.f.x,u1.f.y);
        *(float4*)&g_h1[(size_t)row*512 + n0 + 128 + tn*4] =
            make_float4(u2.f.x,u2.f.y,u3.f.x,u3.f.y);
    }
}

// ============================================================================
// K6: per-row src/dst attention dots for GAT1 (4 heads x 128)
// ============================================================================
__global__ __launch_bounds__(128) void sd1_kernel(const float* __restrict__ a_src,
                                                  const float* __restrict__ a_dst)
{
    int row = blockIdx.x;
    int hd = threadIdx.x >> 5, lane = threadIdx.x & 31;
    const float* hrow = &g_h1[(size_t)row*512 + hd*128];
    float ps = 0.f, pd = 0.f;
    #pragma unroll
    for (int q=0;q<4;q++){
        float hv = hrow[lane + 32*q];
        ps = fmaf(hv, a_src[hd*128 + lane + 32*q], ps);
        pd = fmaf(hv, a_dst[hd*128 + lane + 32*q], pd);
    }
    #pragma unroll
    for (int off=16;off>0;off>>=1){
        ps += __shfl_xor_sync(0xffffffffu,ps,off);
        pd += __shfl_xor_sync(0xffffffffu,pd,off);
    }
    if (lane==0){ g_s1[row*4+hd]=ps; g_d1[row*4+hd]=pd; }
}

// ============================================================================
// K7: GAT1 attention + bias + LN + elu -> g1.  Block per (b, t).
// ============================================================================
__global__ __launch_bounds__(128) void att1_kernel(
    const float* __restrict__ b_g1, const float* __restrict__ gamma,
    const float* __restrict__ beta)
{
    __shared__ int act[EE];
    __shared__ int wcnt[4], woff[4];
    __shared__ int nact_s;
    __shared__ float wts[4][EE];
    __shared__ float red[4], red2[4];

    int be = blockIdx.x;
    int b = be / EE, t = be % EE;
    int tid = threadIdx.x, w = tid>>5, lane = tid&31;

    bool flag = g_Adj[(size_t)(b*EE + tid)*EE + t] != 0;
    unsigned mball = __ballot_sync(0xffffffffu, flag);
    if (lane==0) wcnt[w] = __popc(mball);
    __syncthreads();
    if (tid==0){ int o=0; for (int i2=0;i2<4;i2++){ woff[i2]=o; o+=wcnt[i2]; } nact_s=o; }
    __syncthreads();
    if (flag) act[woff[w] + __popc(mball & ((1u<<lane)-1u))] = tid;
    __syncthreads();
    int nact = nact_s;

    {   // warp w == head hd
        int hd = w;
        float dv = g_d1[be*4 + hd];
        float mx = -1e30f;
        for (int k=lane;k<nact;k+=32){
            float e = g_s1[(b*EE+act[k])*4 + hd] + dv;
            e = e > 0.f ? e : 0.2f*e;
            wts[hd][k] = e;
            mx = fmaxf(mx, e);
        }
        #pragma unroll
        for (int off=16;off>0;off>>=1) mx = fmaxf(mx, __shfl_xor_sync(0xffffffffu,mx,off));
        float sum = 0.f;
        for (int k=lane;k<nact;k+=32){
            float e = expf(wts[hd][k]-mx);
            wts[hd][k] = e; sum += e;
        }
        #pragma unroll
        for (int off=16;off>0;off>>=1) sum += __shfl_xor_sync(0xffffffffu,sum,off);
        float inv = 1.f/sum;
        for (int k=lane;k<nact;k+=32) wts[hd][k] *= inv;
    }
    __syncthreads();

    float ov[4];
    #pragma unroll
    for (int q=0;q<4;q++){
        int f = tid + q*128;
        float o = 0.f;
        for (int k=0;k<nact;k++)
            o = fmaf(wts[q][k], g_h1[(size_t)(b*EE+act[k])*512 + f], o);
        ov[q] = o + b_g1[f];
    }
    float ls = ov[0]+ov[1]+ov[2]+ov[3];
    #pragma unroll
    for (int off=16;off>0;off>>=1) ls += __shfl_xor_sync(0xffffffffu,ls,off);
    if (lane==0) red[w] = ls;
    __syncthreads();
    float mean = (red[0]+red[1]+red[2]+red[3]) * (1.f/512.f);
    float lv = 0.f;
    #pragma unroll
    for (int q=0;q<4;q++){ float d = ov[q]-mean; lv = fmaf(d,d,lv); }
    #pragma unroll
    for (int off=16;off>0;off>>=1) lv += __shfl_xor_sync(0xffffffffu,lv,off);
    if (lane==0) red2[w] = lv;
    __syncthreads();
    float var = (red2[0]+red2[1]+red2[2]+red2[3]) * (1.f/512.f);
    float rstd = rsqrtf(var + 1e-5f);
    #pragma unroll
    for (int q=0;q<4;q++){
        int f = tid + q*128;
        float y = (ov[q]-mean)*rstd*gamma[f] + beta[f];
        y = y > 0.f ? y : expm1f(y);
        g_g1v[(size_t)be*512 + f] = y;
    }
}

// ============================================================================
// K8: h2 = g1 @ W_g2 (512->64), plus s2/d2 dots. Block per row, 64 threads.
// ============================================================================
__global__ __launch_bounds__(64) void gat2h_kernel(
    const float* __restrict__ Wg2, const float* __restrict__ a_src2,
    const float* __restrict__ a_dst2)
{
    __shared__ float grow[512];
    __shared__ float rs[2], rd[2];
    int row = blockIdx.x, tid = threadIdx.x;
    for (int i=tid;i<512;i+=64) grow[i] = g_g1v[(size_t)row*512 + i];
    __syncthreads();
    float acc = 0.f;
    for (int k=0;k<512;k++) acc = fmaf(grow[k], Wg2[k*64 + tid], acc);
    g_h2[(size_t)row*64 + tid] = acc;
    float ps = acc * a_src2[tid];
    float pd = acc * a_dst2[tid];
    #pragma unroll
    for (int off=16;off>0;off>>=1){
        ps += __shfl_xor_sync(0xffffffffu,ps,off);
        pd += __shfl_xor_sync(0xffffffffu,pd,off);
    }
    int w = tid>>5, lane = tid&31;
    if (lane==0){ rs[w]=ps; rd[w]=pd; }
    __syncthreads();
    if (tid==0){ g_s2[row]=rs[0]+rs[1]; g_d2[row]=rd[0]+rd[1]; }
}

// ============================================================================
// K9: GAT2 attention + bias + LN + elu -> ent.  Block per (b, t).
// ============================================================================
__global__ __launch_bounds__(128) void att2_kernel(
    const float* __restrict__ b_g2, const float* __restrict__ gamma,
    const float* __restrict__ beta)
{
    __shared__ int act[EE];
    __shared__ int wcnt[4], woff[4];
    __shared__ int nact_s;
    __shared__ float wts[EE];
    __shared__ float red[2], red2[2];

    int be = blockIdx.x;
    int b = be / EE, t = be % EE;
    int tid = threadIdx.x, w = tid>>5, lane = tid&31;

    bool flag = g_Adj[(size_t)(b*EE + tid)*EE + t] != 0;
    unsigned mball = __ballot_sync(0xffffffffu, flag);
    if (lane==0) wcnt[w] = __popc(mball);
    __syncthreads();
    if (tid==0){ int o=0; for (int i2=0;i2<4;i2++){ woff[i2]=o; o+=wcnt[i2]; } nact_s=o; }
    __syncthreads();
    if (flag) act[woff[w] + __popc(mball & ((1u<<lane)-1u))] = tid;
    __syncthreads();
    int nact = nact_s;

    if (w == 0){
        float dv = g_d2[be];
        float mx = -1e30f;
        for (int k=lane;k<nact;k+=32){
            float e = g_s2[b*EE + act[k]] + dv;
            e = e > 0.f ? e : 0.2f*e;
            wts[k] = e;
            mx = fmaxf(mx, e);
        }
        #pragma unroll
        for (int off=16;off>0;off>>=1) mx = fmaxf(mx, __shfl_xor_sync(0xffffffffu,mx,off));
        float sum = 0.f;
        for (int k=lane;k<nact;k+=32){
            float e = expf(wts[k]-mx);
            wts[k] = e; sum += e;
        }
        #pragma unroll
        for (int off=16;off>0;off>>=1) sum += __shfl_xor_sync(0xffffffffu,sum,off);
        float inv = 1.f/sum;
        for (int k=lane;k<nact;k+=32) wts[k] *= inv;
    }
    __syncthreads();

    float o = 0.f;
    if (tid < 64){
        for (int k=0;k<nact;k++)
            o = fmaf(wts[k], g_h2[(size_t)(b*EE+act[k])*64 + tid], o);
        o += b_g2[tid];
    }
    float ls = (tid<64) ? o : 0.f;
    #pragma unroll
    for (int off=16;off>0;off>>=1) ls += __shfl_xor_sync(0xffffffffu,ls,off);
    if (w < 2 && lane==0) red[w] = ls;
    __syncthreads();
    float mean = (red[0]+red[1]) * (1.f/64.f);
    float dv2 = (tid<64) ? (o-mean) : 0.f;
    float lv = dv2*dv2;
    #pragma unroll
    for (int off=16;off>0;off>>=1) lv += __shfl_xor_sync(0xffffffffu,lv,off);
    if (w < 2 && lane==0) red2[w] = lv;
    __syncthreads();
    float var = (red2[0]+red2[1]) * (1.f/64.f);
    if (tid < 64){
        float y = (o-mean)*rsqrtf(var+1e-5f)*gamma[tid] + beta[tid];
        y = y > 0.f ? y : expm1f(y);
        g_ent[(size_t)be*64 + tid] = y;
    }
}

// ============================================================================
// K10: per-batch cls contribution through W_r1 rows [160:928]
// ============================================================================
__global__ __launch_bounds__(256) void cls_kernel(const float* __restrict__ seq,
                                                  const float* __restrict__ W_r1)
{
    __shared__ float c[HH];
    int b = blockIdx.x, tid = threadIdx.x;
    for (int d=tid; d<HH; d+=256) c[d] = seq[(size_t)b*SS*HH + d];
    __syncthreads();
    float acc = 0.f;
    for (int d=0; d<HH; d++) acc = fmaf(c[d], W_r1[(160+d)*256 + tid], acc);
    g_clsp[b*256 + tid] = acc;
}

// ============================================================================
// K11: relation head per pair: relu(feat@W_r1+b_r1)@W_r2+b_r2
// ============================================================================
__global__ __launch_bounds__(256) void pair_kernel(
    const int* __restrict__ pair_head, const int* __restrict__ pair_tail,
    const int* __restrict__ pair_rel,  const float* __restrict__ rel_emb,
    const float* __restrict__ W_r1,    const float* __restrict__ b_r1,
    const float* __restrict__ W_r2,    const float* __restrict__ b_r2,
    float* __restrict__ out)
{
    __shared__ float hv[64], tv[64], rv[32];
    __shared__ float red[8];
    int bp = blockIdx.x;
    int b = bp / PP;
    int tid = threadIdx.x;
    int hidx = pair_head[bp], tidx = pair_tail[bp], ridx = pair_rel[bp];
    if (tid < 64)        hv[tid]      = g_ent[(size_t)(b*EE+hidx)*64 + tid];
    else if (tid < 128)  tv[tid-64]   = g_ent[(size_t)(b*EE+tidx)*64 + (tid-64)];
    else if (tid < 160)  rv[tid-128]  = rel_emb[ridx*32 + (tid-128)];
    __syncthreads();
    float pre = b_r1[tid] + g_clsp[b*256 + tid];
    #pragma unroll 8
    for (int f=0;f<64;f++) pre = fmaf(hv[f], W_r1[f*256 + tid], pre);
    #pragma unroll 8
    for (int f=0;f<64;f++) pre = fmaf(tv[f], W_r1[(64+f)*256 + tid], pre);
    #pragma unroll 8
    for (int k=0;k<32;k++) pre = fmaf(rv[k], W_r1[(128+k)*256 + tid], pre);
    pre = fmaxf(pre, 0.f);
    float part = pre * W_r2[tid];
    #pragma unroll
    for (int off=16;off>0;off>>=1) part += __shfl_xor_sync(0xffffffffu,part,off);
    if ((tid&31)==0) red[tid>>5] = part;
    __syncthreads();
    if (tid==0){
        float s = 0.f;
        for (int i=0;i<8;i++) s += red[i];
        out[NER_TOTAL + bp] = s + b_r2[0];
    }
}

// ============================================================================
extern "C" void kernel_launch(void* const* d_in, const int* in_sizes, int n_in,
                              void* d_out, int out_size)
{
    (void)in_sizes; (void)n_in; (void)out_size;
    const float* seq       = (const float*)d_in[0];
    const int*   span_start= (const int*)d_in[1];
    const int*   span_len  = (const int*)d_in[2];
    const int*   ent_type  = (const int*)d_in[3];
    const int*   pair_head = (const int*)d_in[4];
    const int*   pair_tail = (const int*)d_in[5];
    const int*   pair_rel  = (const int*)d_in[6];
    const float* W_ner1    = (const float*)d_in[7];
    const float* b_ner1    = (const float*)d_in[8];
    const float* W_ner2    = (const float*)d_in[9];
    const float* b_ner2    = (const float*)d_in[10];
    const float* type_emb  = (const float*)d_in[11];
    const float* W_g1      = (const float*)d_in[12];
    const float* a_src1    = (const float*)d_in[13];
    const float* a_dst1    = (const float*)d_in[14];
    const float* b_g1      = (const float*)d_in[15];
    const float* g1_gamma  = (const float*)d_in[16];
    const float* g1_beta   = (const float*)d_in[17];
    const float* W_g2      = (const float*)d_in[18];
    const float* a_src2    = (const float*)d_in[19];
    const float* a_dst2    = (const float*)d_in[20];
    const float* b_g2      = (const float*)d_in[21];
    const float* g2_gamma  = (const float*)d_in[22];
    const float* g2_beta   = (const float*)d_in[23];
    const float* rel_emb   = (const float*)d_in[24];
    const float* W_r1      = (const float*)d_in[25];
    const float* b_r1      = (const float*)d_in[26];
    const float* W_r2      = (const float*)d_in[27];
    const float* b_r2      = (const float*)d_in[28];
    float* out = (float*)d_out;

    cudaFuncSetAttribute((const void*)pool_kernel,
                         cudaFuncAttributeMaxDynamicSharedMemorySize, 65536);
    cudaFuncSetAttribute((const void*)ner_kernel,
                         cudaFuncAttributeMaxDynamicSharedMemorySize, 13328*4);

    ner_kernel<<<(BB*SS)/32, 256, 13328*4>>>(seq, W_ner1, b_ner1, W_ner2, b_ner2, out);
    pool_kernel<<<BB*EE, 256, LL*HH*sizeof(float)>>>(seq, span_start, span_len,
                                                     ent_type, type_emb);
    sim_kernel<<<BB*4, 256>>>();
    topk_kernel<<<(BB*EE)/8, 256>>>();
    gat1_gemm_kernel<<<dim3((BB*EE)/32, 2), 256>>>(W_g1);
    sd1_kernel<<<BB*EE, 128>>>(a_src1, a_dst1);
    att1_kernel<<<BB*EE, 128>>>(b_g1, g1_gamma, g1_beta);
    gat2h_kernel<<<BB*EE, 64>>>(W_g2, a_src2, a_dst2);
    att2_kernel<<<BB*EE, 128>>>(b_g2, g2_gamma, g2_beta);
    cls_kernel<<<BB, 256>>>(seq, W_r1);
    pair_kernel<<<BB*PP, 256>>>(pair_head, pair_tail, pair_rel, rel_emb,
                                W_r1, b_r1, W_r2, b_r2, out);
}

// round 3
// speedup vs baseline: 1.4025x; 1.1861x over previous
#include <cuda_runtime.h>
#include <math.h>

#define BB 48
#define SS 512
#define HH 768
#define EE 128
#define LL 16
#define PP 256
#define NERC 11
#define NER_TOTAL (BB*SS*NERC)   // 270336

// ---------------- scratch (device globals; no allocation allowed) -------------
__device__ __align__(16) float g_x  [BB*EE*HH];
__device__ __align__(16) float g_xn [BB*EE*HH];
__device__ __align__(16) float g_sim[BB*EE*EE];
__device__ unsigned char g_Adj[BB*EE*EE];
__device__ __align__(16) float g_h1 [BB*EE*512];
__device__ float g_s1 [BB*EE*4];
__device__ float g_d1 [BB*EE*4];
__device__ __align__(16) float g_g1v[BB*EE*512];
__device__ __align__(16) float g_h2 [BB*EE*64];
__device__ float g_s2 [BB*EE];
__device__ float g_d2 [BB*EE];
__device__ __align__(16) float g_ent[BB*EE*64];
__device__ __align__(16) float g_clsp[BB*256];
__device__ __align__(16) float g_hid[BB*SS*256];   // ner hidden
__device__ __align__(16) float g_He [BB*EE*256];
__device__ __align__(16) float g_Te [BB*EE*256];
__device__ __align__(16) float g_Rp [9*256];

__device__ __forceinline__ unsigned long long ffma2(unsigned long long a,
                                                    unsigned long long b,
                                                    unsigned long long c){
    unsigned long long d;
    asm("fma.rn.f32x2 %0, %1, %2, %3;" : "=l"(d) : "l"(a), "l"(b), "l"(c));
    return d;
}
union F2U { unsigned long long u; float2 f; };

__device__ __forceinline__ void cpa16(void* s, const void* g){
    unsigned sa = (unsigned)__cvta_generic_to_shared(s);
    asm volatile("cp.async.ca.shared.global [%0], [%1], 16;" :: "r"(sa), "l"(g));
}

// ============================================================================
// Generic GEMM: C[M][N] = A[M][K] @ B[K][N]  (ldc == ldb == N)
// 64(M) x 128(N) tile, 128 threads, 8x8 per-thread tile, FFMA2, cp.async dbl-buf.
// sel picks A/C from device globals / external: 0=ner 1=gat1 2=He 3=Te
// ============================================================================
__global__ __launch_bounds__(128, 3) void gemm_kernel(
    int sel, const float* __restrict__ Aext, const float* __restrict__ B,
    const float* __restrict__ bias, int lda, int ldb, int K, int dorelu)
{
    __shared__ __align__(16) float2 As2[2][16][64];
    __shared__ __align__(16) float  Bs [2][16][128];

    const float* A; float* C;
    if (sel == 0){ A = Aext;  C = g_hid; }
    else if (sel == 1){ A = g_x;   C = g_h1; }
    else if (sel == 2){ A = g_ent; C = g_He; }
    else              { A = g_ent; C = g_Te; }

    int tid = threadIdx.x;
    int tm = tid >> 4, tn = tid & 15;
    int m0 = blockIdx.x * 64, n0 = blockIdx.y * 128;
    int nch = K >> 4;

    unsigned long long acc[8][4];
    #pragma unroll
    for (int i=0;i<8;i++)
        #pragma unroll
        for (int p=0;p<4;p++) acc[i][p] = 0ull;

    int lr = tid >> 1, lc8 = (tid & 1) * 8;
    const float* aP = A + (size_t)(m0 + lr) * lda + lc8;
    int bkk[4], bc4[4];
    #pragma unroll
    for (int i=0;i<4;i++){ int q = i*128 + tid; bkk[i] = q >> 5; bc4[i] = (q & 31) * 4; }

    float4 pa0, pa1;
    pa0 = *(const float4*)(aP);
    pa1 = *(const float4*)(aP + 4);
    #pragma unroll
    for (int i=0;i<4;i++)
        cpa16(&Bs[0][bkk[i]][bc4[i]], B + (size_t)bkk[i]*ldb + n0 + bc4[i]);
    asm volatile("cp.async.commit_group;");
    {
        float v[8] = {pa0.x,pa0.y,pa0.z,pa0.w,pa1.x,pa1.y,pa1.z,pa1.w};
        #pragma unroll
        for (int j=0;j<8;j++) As2[0][lc8+j][lr] = make_float2(v[j],v[j]);
    }

    for (int c = 0; c < nch; c++){
        int cb = c & 1, nb = cb ^ 1;
        if (c + 1 < nch){
            int k0n = (c+1)*16;
            pa0 = *(const float4*)(aP + k0n);
            pa1 = *(const float4*)(aP + k0n + 4);
            #pragma unroll
            for (int i=0;i<4;i++)
                cpa16(&Bs[nb][bkk[i]][bc4[i]],
                      B + (size_t)(k0n + bkk[i])*ldb + n0 + bc4[i]);
            asm volatile("cp.async.commit_group;");
            asm volatile("cp.async.wait_group 1;");
        } else {
            asm volatile("cp.async.wait_group 0;");
        }
        __syncthreads();
        #pragma unroll
        for (int kk=0;kk<16;kk++){
            unsigned long long b2[4];
            #pragma unroll
            for (int p=0;p<4;p++)
                b2[p] = *(const unsigned long long*)&Bs[cb][kk][2*(tn + 16*p)];
            #pragma unroll
            for (int i=0;i<8;i++){
                unsigned long long a2 =
                    *(const unsigned long long*)&As2[cb][kk][tm*8+i];
                acc[i][0] = ffma2(a2, b2[0], acc[i][0]);
                acc[i][1] = ffma2(a2, b2[1], acc[i][1]);
                acc[i][2] = ffma2(a2, b2[2], acc[i][2]);
                acc[i][3] = ffma2(a2, b2[3], acc[i][3]);
            }
        }
        __syncthreads();
        if (c + 1 < nch){
            float v[8] = {pa0.x,pa0.y,pa0.z,pa0.w,pa1.x,pa1.y,pa1.z,pa1.w};
            #pragma unroll
            for (int j=0;j<8;j++) As2[nb][lc8+j][lr] = make_float2(v[j],v[j]);
        }
    }

    float2 bv[4];
    #pragma unroll
    for (int p=0;p<4;p++){
        int col = n0 + 32*p + 2*tn;
        if (bias) bv[p] = *(const float2*)&bias[col];
        else      bv[p] = make_float2(0.f, 0.f);
    }
    #pragma unroll
    for (int i=0;i<8;i++){
        size_t row = m0 + tm*8 + i;
        #pragma unroll
        for (int p=0;p<4;p++){
            F2U u; u.u = acc[i][p];
            float x0 = u.f.x + bv[p].x, x1 = u.f.y + bv[p].y;
            if (dorelu){ x0 = fmaxf(x0, 0.f); x1 = fmaxf(x1, 0.f); }
            *(float2*)&C[row*ldb + n0 + 32*p + 2*tn] = make_float2(x0, x1);
        }
    }
}

// ============================================================================
// ner_head: out = g_hid @ W2 + b2.  Warp per row, 8 rows/block.
// ============================================================================
__global__ __launch_bounds__(256) void ner_head(
    const float* __restrict__ W2, const float* __restrict__ b2,
    float* __restrict__ out)
{
    __shared__ float W2t[NERC][256];
    __shared__ float b2s[NERC];
    int tid = threadIdx.x;
    for (int i = tid; i < 256*NERC; i += 256){
        int c = i / NERC, jo = i % NERC;
        W2t[jo][c] = W2[i];
    }
    if (tid < NERC) b2s[tid] = b2[tid];
    __syncthreads();
    int w = tid >> 5, lane = tid & 31;
    int row = blockIdx.x*8 + w;
    const float* hr = &g_hid[(size_t)row*256 + lane*8];
    float4 v0 = *(const float4*)hr;
    float4 v1 = *(const float4*)(hr + 4);
    #pragma unroll
    for (int jo = 0; jo < NERC; jo++){
        const float* wr = &W2t[jo][lane*8];
        float4 w0 = *(const float4*)wr;
        float4 w1 = *(const float4*)(wr + 4);
        float p = 0.f;
        p = fmaf(v0.x, w0.x, p); p = fmaf(v0.y, w0.y, p);
        p = fmaf(v0.z, w0.z, p); p = fmaf(v0.w, w0.w, p);
        p = fmaf(v1.x, w1.x, p); p = fmaf(v1.y, w1.y, p);
        p = fmaf(v1.z, w1.z, p); p = fmaf(v1.w, w1.w, p);
        #pragma unroll
        for (int off=16;off>0;off>>=1) p += __shfl_xor_sync(0xffffffffu,p,off);
        if (lane == 0) out[row*NERC + jo] = p + b2s[jo];
    }
}

// ============================================================================
// K2: span pooling (unchanged from R2)
// ============================================================================
__global__ __launch_bounds__(256) void pool_kernel(
    const float* __restrict__ seq, const int* __restrict__ span_start,
    const int* __restrict__ span_len, const int* __restrict__ ent_type,
    const float* __restrict__ type_emb)
{
    extern __shared__ float tok[];          // 16 x 768
    __shared__ float meanv[HH];
    __shared__ float sc[LL];
    __shared__ float wv[LL];
    __shared__ float red[8];

    int be = blockIdx.x;
    int b = be / EE;
    int tid = threadIdx.x;
    int start = span_start[be];
    int len = span_len[be];
    float cnt = (float)(len + 1);

    const float4* src = (const float4*)&seq[(size_t)(b*SS + start)*HH];
    float4* dst4 = (float4*)tok;
    for (int q = tid; q < LL*HH/4; q += 256) dst4[q] = src[q];
    __syncthreads();

    for (int d = tid; d < HH; d += 256){
        float s = 0.f;
        for (int l = 0; l <= len; l++) s += tok[l*HH + d];
        meanv[d] = s / cnt;
    }
    __syncthreads();

    int w = tid >> 5, lane = tid & 31;
    for (int l = w; l < LL; l += 8){
        float p = 0.f;
        for (int d = lane; d < HH; d += 32) p = fmaf(tok[l*HH+d], meanv[d], p);
        #pragma unroll
        for (int off=16;off>0;off>>=1) p += __shfl_xor_sync(0xffffffffu,p,off);
        if (lane==0) sc[l] = p;
    }
    __syncthreads();

    if (tid == 0){
        float mx = -1e30f;
        for (int l=0;l<=len;l++) mx = fmaxf(mx, sc[l]);
        float s = 0.f;
        for (int l=0;l<=len;l++){ float e = expf(sc[l]-mx); wv[l]=e; s+=e; }
        float inv = 1.f/s;
        for (int l=0;l<=len;l++) wv[l] *= inv;
        for (int l=len+1;l<LL;l++) wv[l] = 0.f;
    }
    __syncthreads();

    const float* te = &type_emb[ent_type[be]*HH];
    float xv[3]; float nsq = 0.f;
    #pragma unroll
    for (int q = 0; q < 3; q++){
        int d = tid + q*256;
        float p = 0.f;
        for (int l = 0; l <= len; l++) p = fmaf(wv[l], tok[l*HH+d], p);
        float v = p + te[d];
        xv[q] = v;
        g_x[(size_t)be*HH + d] = v;
        nsq = fmaf(v, v, nsq);
    }
    #pragma unroll
    for (int off=16;off>0;off>>=1) nsq += __shfl_xor_sync(0xffffffffu,nsq,off);
    if (lane==0) red[w] = nsq;
    __syncthreads();
    float tot = 0.f;
    #pragma unroll
    for (int i=0;i<8;i++) tot += red[i];
    float inv = 1.f / fmaxf(sqrtf(tot), 1e-12f);
    #pragma unroll
    for (int q=0;q<3;q++){
        int d = tid + q*256;
        g_xn[(size_t)be*HH + d] = xv[q]*inv;
    }
}

// ============================================================================
// K3: sim = xn @ xn^T per batch (unchanged from R2)
// ============================================================================
__global__ __launch_bounds__(256) void sim_kernel()
{
    __shared__ float Xa[64][36];
    __shared__ float Xbt[32][65];
    int b = blockIdx.x >> 2;
    int tile = blockIdx.x & 3;
    int i0 = (tile >> 1)*64, j0 = (tile & 1)*64;
    int tid = threadIdx.x;
    int ty = tid >> 4, tx = tid & 15;
    const float* X = &g_xn[(size_t)b*EE*HH];
    float acc[4][4];
    #pragma unroll
    for (int i=0;i<4;i++)
        #pragma unroll
        for (int j=0;j<4;j++) acc[i][j]=0.f;

    int r = tid >> 2, q = tid & 3;
    for (int k0 = 0; k0 < HH; k0 += 32){
        __syncthreads();
        #pragma unroll
        for (int h=0;h<2;h++){
            int kq = q + 4*h;
            float4 va = *(const float4*)&X[(i0+r)*HH + k0 + kq*4];
            *(float4*)&Xa[r][kq*4] = va;
            float4 vb = *(const float4*)&X[(j0+r)*HH + k0 + kq*4];
            Xbt[kq*4+0][r] = vb.x;
            Xbt[kq*4+1][r] = vb.y;
            Xbt[kq*4+2][r] = vb.z;
            Xbt[kq*4+3][r] = vb.w;
        }
        __syncthreads();
        #pragma unroll
        for (int kk=0;kk<32;kk++){
            float a[4], c[4];
            #pragma unroll
            for (int i=0;i<4;i++) a[i] = Xa[ty*4+i][kk];
            #pragma unroll
            for (int j=0;j<4;j++) c[j] = Xbt[kk][tx*4+j];
            #pragma unroll
            for (int i=0;i<4;i++)
                #pragma unroll
                for (int j=0;j<4;j++)
                    acc[i][j] = fmaf(a[i], c[j], acc[i][j]);
        }
    }
    float* simb = &g_sim[(size_t)b*EE*EE];
    #pragma unroll
    for (int i=0;i<4;i++)
        #pragma unroll
        for (int j=0;j<4;j++)
            simb[(i0+ty*4+i)*EE + j0+tx*4+j] = acc[i][j];
}

// ============================================================================
// K4: warp-per-row top-6 -> adjacency (unchanged from R2)
// ============================================================================
__global__ __launch_bounds__(256) void topk_kernel()
{
    int w = threadIdx.x >> 5, lane = threadIdx.x & 31;
    int row = blockIdx.x*8 + w;
    int i = row & 127;
    const float* r = &g_sim[(size_t)row*EE];
    float v[4];
    #pragma unroll
    for (int q=0;q<4;q++) v[q] = r[lane + q*32];
    unsigned used = 0;
    int pick[6]; float pval[6];
    for (int k=0;k<6;k++){
        float bv = -1e30f; int bj = 128;
        #pragma unroll
        for (int q=0;q<4;q++){
            if (!((used>>q)&1u)){
                int j = lane + q*32;
                if (v[q] > bv){ bv = v[q]; bj = j; }
            }
        }
        #pragma unroll
        for (int off=16; off>0; off>>=1){
            float ov = __shfl_xor_sync(0xffffffffu, bv, off);
            int   oj = __shfl_xor_sync(0xffffffffu, bj, off);
            if (ov > bv || (ov == bv && oj < bj)){ bv = ov; bj = oj; }
        }
        pick[k]=bj; pval[k]=bv;
        if ((bj & 31) == lane) used |= 1u << (bj >> 5);
    }
    int jb = lane*4;
    unsigned char c0=0,c1=0,c2=0,c3=0;
    #pragma unroll
    for (int k=0;k<6;k++){
        if (pval[k] > 0.1f && pick[k] != i){
            int d = pick[k] - jb;
            if (d==0) c0=1; else if (d==1) c1=1; else if (d==2) c2=1; else if (d==3) c3=1;
        }
    }
    int ds = i - jb;
    if (ds>=0 && ds<4){ if(ds==0)c0=1; else if(ds==1)c1=1; else if(ds==2)c2=1; else c3=1; }
    *(uchar4*)&g_Adj[(size_t)row*EE + jb] = make_uchar4(c0,c1,c2,c3);
}

// ============================================================================
// K6: per-row src/dst dots for GAT1 (unchanged)
// ============================================================================
__global__ __launch_bounds__(128) void sd1_kernel(const float* __restrict__ a_src,
                                                  const float* __restrict__ a_dst)
{
    int row = blockIdx.x;
    int hd = threadIdx.x >> 5, lane = threadIdx.x & 31;
    const float* hrow = &g_h1[(size_t)row*512 + hd*128];
    float ps = 0.f, pd = 0.f;
    #pragma unroll
    for (int q=0;q<4;q++){
        float hv = hrow[lane + 32*q];
        ps = fmaf(hv, a_src[hd*128 + lane + 32*q], ps);
        pd = fmaf(hv, a_dst[hd*128 + lane + 32*q], pd);
    }
    #pragma unroll
    for (int off=16;off>0;off>>=1){
        ps += __shfl_xor_sync(0xffffffffu,ps,off);
        pd += __shfl_xor_sync(0xffffffffu,pd,off);
    }
    if (lane==0){ g_s1[row*4+hd]=ps; g_d1[row*4+hd]=pd; }
}

// ============================================================================
// K7: GAT1 attention + LN + elu (unchanged)
// ============================================================================
__global__ __launch_bounds__(128) void att1_kernel(
    const float* __restrict__ b_g1, const float* __restrict__ gamma,
    const float* __restrict__ beta)
{
    __shared__ int act[EE];
    __shared__ int wcnt[4], woff[4];
    __shared__ int nact_s;
    __shared__ float wts[4][EE];
    __shared__ float red[4], red2[4];

    int be = blockIdx.x;
    int b = be / EE, t = be % EE;
    int tid = threadIdx.x, w = tid>>5, lane = tid&31;

    bool flag = g_Adj[(size_t)(b*EE + tid)*EE + t] != 0;
    unsigned mball = __ballot_sync(0xffffffffu, flag);
    if (lane==0) wcnt[w] = __popc(mball);
    __syncthreads();
    if (tid==0){ int o=0; for (int i2=0;i2<4;i2++){ woff[i2]=o; o+=wcnt[i2]; } nact_s=o; }
    __syncthreads();
    if (flag) act[woff[w] + __popc(mball & ((1u<<lane)-1u))] = tid;
    __syncthreads();
    int nact = nact_s;

    {
        int hd = w;
        float dv = g_d1[be*4 + hd];
        float mx = -1e30f;
        for (int k=lane;k<nact;k+=32){
            float e = g_s1[(b*EE+act[k])*4 + hd] + dv;
            e = e > 0.f ? e : 0.2f*e;
            wts[hd][k] = e;
            mx = fmaxf(mx, e);
        }
        #pragma unroll
        for (int off=16;off>0;off>>=1) mx = fmaxf(mx, __shfl_xor_sync(0xffffffffu,mx,off));
        float sum = 0.f;
        for (int k=lane;k<nact;k+=32){
            float e = expf(wts[hd][k]-mx);
            wts[hd][k] = e; sum += e;
        }
        #pragma unroll
        for (int off=16;off>0;off>>=1) sum += __shfl_xor_sync(0xffffffffu,sum,off);
        float inv = 1.f/sum;
        for (int k=lane;k<nact;k+=32) wts[hd][k] *= inv;
    }
    __syncthreads();

    float ov[4];
    #pragma unroll
    for (int q=0;q<4;q++){
        int f = tid + q*128;
        float o = 0.f;
        for (int k=0;k<nact;k++)
            o = fmaf(wts[q][k], g_h1[(size_t)(b*EE+act[k])*512 + f], o);
        ov[q] = o + b_g1[f];
    }
    float ls = ov[0]+ov[1]+ov[2]+ov[3];
    #pragma unroll
    for (int off=16;off>0;off>>=1) ls += __shfl_xor_sync(0xffffffffu,ls,off);
    if (lane==0) red[w] = ls;
    __syncthreads();
    float mean = (red[0]+red[1]+red[2]+red[3]) * (1.f/512.f);
    float lv = 0.f;
    #pragma unroll
    for (int q=0;q<4;q++){ float d = ov[q]-mean; lv = fmaf(d,d,lv); }
    #pragma unroll
    for (int off=16;off>0;off>>=1) lv += __shfl_xor_sync(0xffffffffu,lv,off);
    if (lane==0) red2[w] = lv;
    __syncthreads();
    float var = (red2[0]+red2[1]+red2[2]+red2[3]) * (1.f/512.f);
    float rstd = rsqrtf(var + 1e-5f);
    #pragma unroll
    for (int q=0;q<4;q++){
        int f = tid + q*128;
        float y = (ov[q]-mean)*rstd*gamma[f] + beta[f];
        y = y > 0.f ? y : expm1f(y);
        g_g1v[(size_t)be*512 + f] = y;
    }
}

// ============================================================================
// K8: h2 = g1 @ W_g2 + s2/d2 dots (unchanged)
// ============================================================================
__global__ __launch_bounds__(64) void gat2h_kernel(
    const float* __restrict__ Wg2, const float* __restrict__ a_src2,
    const float* __restrict__ a_dst2)
{
    __shared__ float grow[512];
    __shared__ float rs[2], rd[2];
    int row = blockIdx.x, tid = threadIdx.x;
    for (int i=tid;i<512;i+=64) grow[i] = g_g1v[(size_t)row*512 + i];
    __syncthreads();
    float acc = 0.f;
    for (int k=0;k<512;k++) acc = fmaf(grow[k], Wg2[k*64 + tid], acc);
    g_h2[(size_t)row*64 + tid] = acc;
    float ps = acc * a_src2[tid];
    float pd = acc * a_dst2[tid];
    #pragma unroll
    for (int off=16;off>0;off>>=1){
        ps += __shfl_xor_sync(0xffffffffu,ps,off);
        pd += __shfl_xor_sync(0xffffffffu,pd,off);
    }
    int w = tid>>5, lane = tid&31;
    if (lane==0){ rs[w]=ps; rd[w]=pd; }
    __syncthreads();
    if (tid==0){ g_s2[row]=rs[0]+rs[1]; g_d2[row]=rd[0]+rd[1]; }
}

// ============================================================================
// K9: GAT2 attention + LN + elu (unchanged)
// ============================================================================
__global__ __launch_bounds__(128) void att2_kernel(
    const float* __restrict__ b_g2, const float* __restrict__ gamma,
    const float* __restrict__ beta)
{
    __shared__ int act[EE];
    __shared__ int wcnt[4], woff[4];
    __shared__ int nact_s;
    __shared__ float wts[EE];
    __shared__ float red[2], red2[2];

    int be = blockIdx.x;
    int b = be / EE, t = be % EE;
    int tid = threadIdx.x, w = tid>>5, lane = tid&31;

    bool flag = g_Adj[(size_t)(b*EE + tid)*EE + t] != 0;
    unsigned mball = __ballot_sync(0xffffffffu, flag);
    if (lane==0) wcnt[w] = __popc(mball);
    __syncthreads();
    if (tid==0){ int o=0; for (int i2=0;i2<4;i2++){ woff[i2]=o; o+=wcnt[i2]; } nact_s=o; }
    __syncthreads();
    if (flag) act[woff[w] + __popc(mball & ((1u<<lane)-1u))] = tid;
    __syncthreads();
    int nact = nact_s;

    if (w == 0){
        float dv = g_d2[be];
        float mx = -1e30f;
        for (int k=lane;k<nact;k+=32){
            float e = g_s2[b*EE + act[k]] + dv;
            e = e > 0.f ? e : 0.2f*e;
            wts[k] = e;
            mx = fmaxf(mx, e);
        }
        #pragma unroll
        for (int off=16;off>0;off>>=1) mx = fmaxf(mx, __shfl_xor_sync(0xffffffffu,mx,off));
        float sum = 0.f;
        for (int k=lane;k<nact;k+=32){
            float e = expf(wts[k]-mx);
            wts[k] = e; sum += e;
        }
        #pragma unroll
        for (int off=16;off>0;off>>=1) sum += __shfl_xor_sync(0xffffffffu,sum,off);
        float inv = 1.f/sum;
        for (int k=lane;k<nact;k+=32) wts[k] *= inv;
    }
    __syncthreads();

    float o = 0.f;
    if (tid < 64){
        for (int k=0;k<nact;k++)
            o = fmaf(wts[k], g_h2[(size_t)(b*EE+act[k])*64 + tid], o);
        o += b_g2[tid];
    }
    float ls = (tid<64) ? o : 0.f;
    #pragma unroll
    for (int off=16;off>0;off>>=1) ls += __shfl_xor_sync(0xffffffffu,ls,off);
    if (w < 2 && lane==0) red[w] = ls;
    __syncthreads();
    float mean = (red[0]+red[1]) * (1.f/64.f);
    float dv2 = (tid<64) ? (o-mean) : 0.f;
    float lv = dv2*dv2;
    #pragma unroll
    for (int off=16;off>0;off>>=1) lv += __shfl_xor_sync(0xffffffffu,lv,off);
    if (w < 2 && lane==0) red2[w] = lv;
    __syncthreads();
    float var = (red2[0]+red2[1]) * (1.f/64.f);
    if (tid < 64){
        float y = (o-mean)*rsqrtf(var+1e-5f)*gamma[tid] + beta[tid];
        y = y > 0.f ? y : expm1f(y);
        g_ent[(size_t)be*64 + tid] = y;
    }
}

// ============================================================================
// K10: per-batch cls contribution + b_r1  -> g_clsp
// ============================================================================
__global__ __launch_bounds__(256) void cls_kernel(const float* __restrict__ seq,
                                                  const float* __restrict__ W_r1,
                                                  const float* __restrict__ b_r1)
{
    __shared__ float c[HH];
    int b = blockIdx.x, tid = threadIdx.x;
    for (int d=tid; d<HH; d+=256) c[d] = seq[(size_t)b*SS*HH + d];
    __syncthreads();
    float acc = b_r1[tid];
    for (int d=0; d<HH; d++) acc = fmaf(c[d], W_r1[(160+d)*256 + tid], acc);
    g_clsp[b*256 + tid] = acc;
}

// ============================================================================
// K10b: Rp[r] = rel_emb[r] @ W_r1[128:160]
// ============================================================================
__global__ __launch_bounds__(256) void rp_kernel(const float* __restrict__ rel_emb,
                                                 const float* __restrict__ W_r1)
{
    __shared__ float re[32];
    int r = blockIdx.x, tid = threadIdx.x;
    if (tid < 32) re[tid] = rel_emb[r*32 + tid];
    __syncthreads();
    float s = 0.f;
    #pragma unroll 8
    for (int k=0;k<32;k++) s = fmaf(re[k], W_r1[(128+k)*256 + tid], s);
    g_Rp[r*256 + tid] = s;
}

// ============================================================================
// K11: relation head per pair via factored projections. Warp per pair.
// ============================================================================
__global__ __launch_bounds__(256) void pair_kernel(
    const int* __restrict__ pair_head, const int* __restrict__ pair_tail,
    const int* __restrict__ pair_rel,  const float* __restrict__ W_r2,
    const float* __restrict__ b_r2,    float* __restrict__ out)
{
    int w = threadIdx.x >> 5, lane = threadIdx.x & 31;
    int bp = blockIdx.x*8 + w;          // 0..12287
    int b = bp >> 8;
    int h = pair_head[bp], t = pair_tail[bp], r = pair_rel[bp];
    const float* He = &g_He[(size_t)(b*EE+h)*256 + lane*8];
    const float* Te = &g_Te[(size_t)(b*EE+t)*256 + lane*8];
    const float* Rp = &g_Rp[r*256 + lane*8];
    const float* Cp = &g_clsp[b*256 + lane*8];
    float s = 0.f;
    #pragma unroll
    for (int q=0;q<2;q++){
        float4 a  = *(const float4*)(He + 4*q);
        float4 bb = *(const float4*)(Te + 4*q);
        float4 c  = *(const float4*)(Rp + 4*q);
        float4 d  = *(const float4*)(Cp + 4*q);
        float4 w4 = *(const float4*)&W_r2[lane*8 + 4*q];
        float h0 = fmaxf(a.x+bb.x+c.x+d.x, 0.f); s = fmaf(h0, w4.x, s);
        float h1 = fmaxf(a.y+bb.y+c.y+d.y, 0.f); s = fmaf(h1, w4.y, s);
        float h2 = fmaxf(a.z+bb.z+c.z+d.z, 0.f); s = fmaf(h2, w4.z, s);
        float h3 = fmaxf(a.w+bb.w+c.w+d.w, 0.f); s = fmaf(h3, w4.w, s);
    }
    #pragma unroll
    for (int off=16;off>0;off>>=1) s += __shfl_xor_sync(0xffffffffu,s,off);
    if (lane == 0) out[NER_TOTAL + bp] = s + b_r2[0];
}

// ============================================================================
extern "C" void kernel_launch(void* const* d_in, const int* in_sizes, int n_in,
                              void* d_out, int out_size)
{
    (void)in_sizes; (void)n_in; (void)out_size;
    const float* seq       = (const float*)d_in[0];
    const int*   span_start= (const int*)d_in[1];
    const int*   span_len  = (const int*)d_in[2];
    const int*   ent_type  = (const int*)d_in[3];
    const int*   pair_head = (const int*)d_in[4];
    const int*   pair_tail = (const int*)d_in[5];
    const int*   pair_rel  = (const int*)d_in[6];
    const float* W_ner1    = (const float*)d_in[7];
    const float* b_ner1    = (const float*)d_in[8];
    const float* W_ner2    = (const float*)d_in[9];
    const float* b_ner2    = (const float*)d_in[10];
    const float* type_emb  = (const float*)d_in[11];
    const float* W_g1      = (const float*)d_in[12];
    const float* a_src1    = (const float*)d_in[13];
    const float* a_dst1    = (const float*)d_in[14];
    const float* b_g1      = (const float*)d_in[15];
    const float* g1_gamma  = (const float*)d_in[16];
    const float* g1_beta   = (const float*)d_in[17];
    const float* W_g2      = (const float*)d_in[18];
    const float* a_src2    = (const float*)d_in[19];
    const float* a_dst2    = (const float*)d_in[20];
    const float* b_g2      = (const float*)d_in[21];
    const float* g2_gamma  = (const float*)d_in[22];
    const float* g2_beta   = (const float*)d_in[23];
    const float* rel_emb   = (const float*)d_in[24];
    const float* W_r1      = (const float*)d_in[25];
    const float* b_r1      = (const float*)d_in[26];
    const float* W_r2      = (const float*)d_in[27];
    const float* b_r2      = (const float*)d_in[28];
    float* out = (float*)d_out;

    cudaFuncSetAttribute((const void*)pool_kernel,
                         cudaFuncAttributeMaxDynamicSharedMemorySize, 65536);

    // NER branch
    gemm_kernel<<<dim3((BB*SS)/64, 2), 128>>>(0, seq, W_ner1, b_ner1, HH, 256, HH, 1);
    ner_head<<<(BB*SS)/8, 256>>>(W_ner2, b_ner2, out);

    // span pooling / graph build
    pool_kernel<<<BB*EE, 256, LL*HH*sizeof(float)>>>(seq, span_start, span_len,
                                                     ent_type, type_emb);
    sim_kernel<<<BB*4, 256>>>();
    topk_kernel<<<(BB*EE)/8, 256>>>();

    // GAT1
    gemm_kernel<<<dim3((BB*EE)/64, 4), 128>>>(1, nullptr, W_g1, nullptr, HH, 512, HH, 0);
    sd1_kernel<<<BB*EE, 128>>>(a_src1, a_dst1);
    att1_kernel<<<BB*EE, 128>>>(b_g1, g1_gamma, g1_beta);

    // GAT2
    gat2h_kernel<<<BB*EE, 64>>>(W_g2, a_src2, a_dst2);
    att2_kernel<<<BB*EE, 128>>>(b_g2, g2_gamma, g2_beta);

    // relation head (factored)
    gemm_kernel<<<dim3((BB*EE)/64, 2), 128>>>(2, nullptr, W_r1,          nullptr, 64, 256, 64, 0);
    gemm_kernel<<<dim3((BB*EE)/64, 2), 128>>>(3, nullptr, W_r1 + 64*256, nullptr, 64, 256, 64, 0);
    rp_kernel<<<9, 256>>>(rel_emb, W_r1);
    cls_kernel<<<BB, 256>>>(seq, W_r1, b_r1);
    pair_kernel<<<(BB*PP)/8, 256>>>(pair_head, pair_tail, pair_rel,
                                    W_r2, b_r2, out);
}

// round 4
// speedup vs baseline: 1.4842x; 1.0583x over previous
#include <cuda_runtime.h>
#include <math.h>

#define BB 48
#define SS 512
#define HH 768
#define EE 128
#define LL 16
#define PP 256
#define NERC 11
#define NER_TOTAL (BB*SS*NERC)   // 270336

// ---------------- scratch (device globals; no allocation allowed) -------------
__device__ __align__(16) float g_x  [BB*EE*HH];
__device__ __align__(16) float g_xn [BB*EE*HH];
__device__ __align__(16) float g_sim[BB*EE*EE];
__device__ unsigned char g_Adj[BB*EE*EE];
__device__ __align__(16) float g_h1 [BB*EE*512];
__device__ float g_s1 [BB*EE*4];
__device__ float g_d1 [BB*EE*4];
__device__ __align__(16) float g_g1v[BB*EE*512];
__device__ __align__(16) float g_h2 [BB*EE*64];
__device__ float g_s2 [BB*EE];
__device__ float g_d2 [BB*EE];
__device__ __align__(16) float g_ent[BB*EE*64];
__device__ __align__(16) float g_clsp[BB*256];
__device__ __align__(16) float g_hid[BB*SS*256];   // ner hidden
__device__ __align__(16) float g_He [BB*EE*256];
__device__ __align__(16) float g_Te [BB*EE*256];
__device__ __align__(16) float g_Rp [9*256];

__device__ __forceinline__ unsigned long long ffma2(unsigned long long a,
                                                    unsigned long long b,
                                                    unsigned long long c){
    unsigned long long d;
    asm("fma.rn.f32x2 %0, %1, %2, %3;" : "=l"(d) : "l"(a), "l"(b), "l"(c));
    return d;
}
union F2U { unsigned long long u; float2 f; };

__device__ __forceinline__ void cpa16(void* s, const void* g){
    unsigned sa = (unsigned)__cvta_generic_to_shared(s);
    asm volatile("cp.async.ca.shared.global [%0], [%1], 16;" :: "r"(sa), "l"(g));
}

// ============================================================================
// Generic GEMM: C[M][N] = A[M][K] @ B[K][N]  (ldc == ldb == N)
// 64(M) x 128(N) tile, 128 threads, 8x8 per-thread tile, FFMA2, cp.async dbl-buf.
// sel: 0=ner 1=gat1 2=He 3=Te
// ============================================================================
__global__ __launch_bounds__(128, 3) void gemm_kernel(
    int sel, const float* __restrict__ Aext, const float* __restrict__ B,
    const float* __restrict__ bias, int lda, int ldb, int K, int dorelu)
{
    __shared__ __align__(16) float2 As2[2][16][64];
    __shared__ __align__(16) float  Bs [2][16][128];

    const float* A; float* C;
    if (sel == 0){ A = Aext;  C = g_hid; }
    else if (sel == 1){ A = g_x;   C = g_h1; }
    else if (sel == 2){ A = g_ent; C = g_He; }
    else              { A = g_ent; C = g_Te; }

    int tid = threadIdx.x;
    int tm = tid >> 4, tn = tid & 15;
    int m0 = blockIdx.x * 64, n0 = blockIdx.y * 128;
    int nch = K >> 4;

    unsigned long long acc[8][4];
    #pragma unroll
    for (int i=0;i<8;i++)
        #pragma unroll
        for (int p=0;p<4;p++) acc[i][p] = 0ull;

    int lr = tid >> 1, lc8 = (tid & 1) * 8;
    const float* aP = A + (size_t)(m0 + lr) * lda + lc8;
    int bkk[4], bc4[4];
    #pragma unroll
    for (int i=0;i<4;i++){ int q = i*128 + tid; bkk[i] = q >> 5; bc4[i] = (q & 31) * 4; }

    float4 pa0, pa1;
    pa0 = *(const float4*)(aP);
    pa1 = *(const float4*)(aP + 4);
    #pragma unroll
    for (int i=0;i<4;i++)
        cpa16(&Bs[0][bkk[i]][bc4[i]], B + (size_t)bkk[i]*ldb + n0 + bc4[i]);
    asm volatile("cp.async.commit_group;");
    {
        float v[8] = {pa0.x,pa0.y,pa0.z,pa0.w,pa1.x,pa1.y,pa1.z,pa1.w};
        #pragma unroll
        for (int j=0;j<8;j++) As2[0][lc8+j][lr] = make_float2(v[j],v[j]);
    }

    for (int c = 0; c < nch; c++){
        int cb = c & 1, nb = cb ^ 1;
        if (c + 1 < nch){
            int k0n = (c+1)*16;
            pa0 = *(const float4*)(aP + k0n);
            pa1 = *(const float4*)(aP + k0n + 4);
            #pragma unroll
            for (int i=0;i<4;i++)
                cpa16(&Bs[nb][bkk[i]][bc4[i]],
                      B + (size_t)(k0n + bkk[i])*ldb + n0 + bc4[i]);
            asm volatile("cp.async.commit_group;");
            asm volatile("cp.async.wait_group 1;");
        } else {
            asm volatile("cp.async.wait_group 0;");
        }
        __syncthreads();
        #pragma unroll
        for (int kk=0;kk<16;kk++){
            unsigned long long b2[4];
            #pragma unroll
            for (int p=0;p<4;p++)
                b2[p] = *(const unsigned long long*)&Bs[cb][kk][2*(tn + 16*p)];
            #pragma unroll
            for (int i=0;i<8;i++){
                unsigned long long a2 =
                    *(const unsigned long long*)&As2[cb][kk][tm*8+i];
                acc[i][0] = ffma2(a2, b2[0], acc[i][0]);
                acc[i][1] = ffma2(a2, b2[1], acc[i][1]);
                acc[i][2] = ffma2(a2, b2[2], acc[i][2]);
                acc[i][3] = ffma2(a2, b2[3], acc[i][3]);
            }
        }
        __syncthreads();
        if (c + 1 < nch){
            float v[8] = {pa0.x,pa0.y,pa0.z,pa0.w,pa1.x,pa1.y,pa1.z,pa1.w};
            #pragma unroll
            for (int j=0;j<8;j++) As2[nb][lc8+j][lr] = make_float2(v[j],v[j]);
        }
    }

    float2 bv[4];
    #pragma unroll
    for (int p=0;p<4;p++){
        int col = n0 + 32*p + 2*tn;
        if (bias) bv[p] = *(const float2*)&bias[col];
        else      bv[p] = make_float2(0.f, 0.f);
    }
    #pragma unroll
    for (int i=0;i<8;i++){
        size_t row = m0 + tm*8 + i;
        #pragma unroll
        for (int p=0;p<4;p++){
            F2U u; u.u = acc[i][p];
            float x0 = u.f.x + bv[p].x, x1 = u.f.y + bv[p].y;
            if (dorelu){ x0 = fmaxf(x0, 0.f); x1 = fmaxf(x1, 0.f); }
            *(float2*)&C[row*ldb + n0 + 32*p + 2*tn] = make_float2(x0, x1);
        }
    }
}

// ============================================================================
// ner_head: out = g_hid @ W2 + b2.  Warp per row, 8 rows/block.
// ============================================================================
__global__ __launch_bounds__(256) void ner_head(
    const float* __restrict__ W2, const float* __restrict__ b2,
    float* __restrict__ out)
{
    __shared__ float W2t[NERC][256];
    __shared__ float b2s[NERC];
    int tid = threadIdx.x;
    for (int i = tid; i < 256*NERC; i += 256){
        int c = i / NERC, jo = i % NERC;
        W2t[jo][c] = W2[i];
    }
    if (tid < NERC) b2s[tid] = b2[tid];
    __syncthreads();
    int w = tid >> 5, lane = tid & 31;
    int row = blockIdx.x*8 + w;
    const float* hr = &g_hid[(size_t)row*256 + lane*8];
    float4 v0 = *(const float4*)hr;
    float4 v1 = *(const float4*)(hr + 4);
    #pragma unroll
    for (int jo = 0; jo < NERC; jo++){
        const float* wr = &W2t[jo][lane*8];
        float4 w0 = *(const float4*)wr;
        float4 w1 = *(const float4*)(wr + 4);
        float p = 0.f;
        p = fmaf(v0.x, w0.x, p); p = fmaf(v0.y, w0.y, p);
        p = fmaf(v0.z, w0.z, p); p = fmaf(v0.w, w0.w, p);
        p = fmaf(v1.x, w1.x, p); p = fmaf(v1.y, w1.y, p);
        p = fmaf(v1.z, w1.z, p); p = fmaf(v1.w, w1.w, p);
        #pragma unroll
        for (int off=16;off>0;off>>=1) p += __shfl_xor_sync(0xffffffffu,p,off);
        if (lane == 0) out[row*NERC + jo] = p + b2s[jo];
    }
}

// ============================================================================
// K2: span pooling (unchanged)
// ============================================================================
__global__ __launch_bounds__(256) void pool_kernel(
    const float* __restrict__ seq, const int* __restrict__ span_start,
    const int* __restrict__ span_len, const int* __restrict__ ent_type,
    const float* __restrict__ type_emb)
{
    extern __shared__ float tok[];          // 16 x 768
    __shared__ float meanv[HH];
    __shared__ float sc[LL];
    __shared__ float wv[LL];
    __shared__ float red[8];

    int be = blockIdx.x;
    int b = be / EE;
    int tid = threadIdx.x;
    int start = span_start[be];
    int len = span_len[be];
    float cnt = (float)(len + 1);

    const float4* src = (const float4*)&seq[(size_t)(b*SS + start)*HH];
    float4* dst4 = (float4*)tok;
    for (int q = tid; q < LL*HH/4; q += 256) dst4[q] = src[q];
    __syncthreads();

    for (int d = tid; d < HH; d += 256){
        float s = 0.f;
        for (int l = 0; l <= len; l++) s += tok[l*HH + d];
        meanv[d] = s / cnt;
    }
    __syncthreads();

    int w = tid >> 5, lane = tid & 31;
    for (int l = w; l < LL; l += 8){
        float p = 0.f;
        for (int d = lane; d < HH; d += 32) p = fmaf(tok[l*HH+d], meanv[d], p);
        #pragma unroll
        for (int off=16;off>0;off>>=1) p += __shfl_xor_sync(0xffffffffu,p,off);
        if (lane==0) sc[l] = p;
    }
    __syncthreads();

    if (tid == 0){
        float mx = -1e30f;
        for (int l=0;l<=len;l++) mx = fmaxf(mx, sc[l]);
        float s = 0.f;
        for (int l=0;l<=len;l++){ float e = expf(sc[l]-mx); wv[l]=e; s+=e; }
        float inv = 1.f/s;
        for (int l=0;l<=len;l++) wv[l] *= inv;
        for (int l=len+1;l<LL;l++) wv[l] = 0.f;
    }
    __syncthreads();

    const float* te = &type_emb[ent_type[be]*HH];
    float xv[3]; float nsq = 0.f;
    #pragma unroll
    for (int q = 0; q < 3; q++){
        int d = tid + q*256;
        float p = 0.f;
        for (int l = 0; l <= len; l++) p = fmaf(wv[l], tok[l*HH+d], p);
        float v = p + te[d];
        xv[q] = v;
        g_x[(size_t)be*HH + d] = v;
        nsq = fmaf(v, v, nsq);
    }
    #pragma unroll
    for (int off=16;off>0;off>>=1) nsq += __shfl_xor_sync(0xffffffffu,nsq,off);
    if (lane==0) red[w] = nsq;
    __syncthreads();
    float tot = 0.f;
    #pragma unroll
    for (int i=0;i<8;i++) tot += red[i];
    float inv = 1.f / fmaxf(sqrtf(tot), 1e-12f);
    #pragma unroll
    for (int q=0;q<3;q++){
        int d = tid + q*256;
        g_xn[(size_t)be*HH + d] = xv[q]*inv;
    }
}

// ============================================================================
// K3: sim = xn @ xn^T. FFMA2, 64x128 tile, 128 thr, dbl-buf, in-smem transpose.
// grid = 48 batches x 2 row-tiles.
// ============================================================================
__global__ __launch_bounds__(128) void sim_kernel()
{
    __shared__ __align__(16) float2 As2[2][16][64];
    __shared__ float Xt[2][16][132];

    int b = blockIdx.x >> 1;
    int i0 = (blockIdx.x & 1) * 64;
    const float* X = &g_xn[(size_t)b*EE*HH];
    int tid = threadIdx.x;
    int tm = tid >> 4, tn = tid & 15;

    unsigned long long acc[8][4];
    #pragma unroll
    for (int i=0;i<8;i++)
        #pragma unroll
        for (int p=0;p<4;p++) acc[i][p] = 0ull;

    int ar = tid >> 1, akq = (tid & 1) * 8;   // A loader: row, k-offset
    const float* aP = X + (size_t)(i0 + ar)*HH + akq;
    const float* xP = X + (size_t)tid*HH;     // Xt loader: source row = tid

    float4 pa0, pa1, px[4];
    pa0 = *(const float4*)(aP);
    pa1 = *(const float4*)(aP + 4);
    #pragma unroll
    for (int q=0;q<4;q++) px[q] = *(const float4*)(xP + 4*q);
    {
        float v[8] = {pa0.x,pa0.y,pa0.z,pa0.w,pa1.x,pa1.y,pa1.z,pa1.w};
        #pragma unroll
        for (int j=0;j<8;j++) As2[0][akq+j][ar] = make_float2(v[j],v[j]);
        #pragma unroll
        for (int q=0;q<4;q++){
            Xt[0][4*q+0][tid] = px[q].x;
            Xt[0][4*q+1][tid] = px[q].y;
            Xt[0][4*q+2][tid] = px[q].z;
            Xt[0][4*q+3][tid] = px[q].w;
        }
    }

    for (int c = 0; c < 48; c++){
        int cb = c & 1, nb = cb ^ 1;
        __syncthreads();
        if (c + 1 < 48){
            int k0n = (c+1)*16;
            pa0 = *(const float4*)(aP + k0n);
            pa1 = *(const float4*)(aP + k0n + 4);
            #pragma unroll
            for (int q=0;q<4;q++) px[q] = *(const float4*)(xP + k0n + 4*q);
        }
        #pragma unroll
        for (int kk=0;kk<16;kk++){
            unsigned long long b2[4];
            #pragma unroll
            for (int p=0;p<4;p++)
                b2[p] = *(const unsigned long long*)&Xt[cb][kk][2*(tn + 16*p)];
            #pragma unroll
            for (int i=0;i<8;i++){
                unsigned long long a2 =
                    *(const unsigned long long*)&As2[cb][kk][tm*8+i];
                acc[i][0] = ffma2(a2, b2[0], acc[i][0]);
                acc[i][1] = ffma2(a2, b2[1], acc[i][1]);
                acc[i][2] = ffma2(a2, b2[2], acc[i][2]);
                acc[i][3] = ffma2(a2, b2[3], acc[i][3]);
            }
        }
        if (c + 1 < 48){
            float v[8] = {pa0.x,pa0.y,pa0.z,pa0.w,pa1.x,pa1.y,pa1.z,pa1.w};
            #pragma unroll
            for (int j=0;j<8;j++) As2[nb][akq+j][ar] = make_float2(v[j],v[j]);
            #pragma unroll
            for (int q=0;q<4;q++){
                Xt[nb][4*q+0][tid] = px[q].x;
                Xt[nb][4*q+1][tid] = px[q].y;
                Xt[nb][4*q+2][tid] = px[q].z;
                Xt[nb][4*q+3][tid] = px[q].w;
            }
        }
    }

    float* simb = &g_sim[(size_t)b*EE*EE];
    #pragma unroll
    for (int i=0;i<8;i++){
        int row = i0 + tm*8 + i;
        #pragma unroll
        for (int p=0;p<4;p++){
            F2U u; u.u = acc[i][p];
            *(float2*)&simb[row*EE + 2*(tn + 16*p)] = u.f;
        }
    }
}

// ============================================================================
// K4: warp-per-row top-6 -> adjacency (unchanged)
// ============================================================================
__global__ __launch_bounds__(256) void topk_kernel()
{
    int w = threadIdx.x >> 5, lane = threadIdx.x & 31;
    int row = blockIdx.x*8 + w;
    int i = row & 127;
    const float* r = &g_sim[(size_t)row*EE];
    float v[4];
    #pragma unroll
    for (int q=0;q<4;q++) v[q] = r[lane + q*32];
    unsigned used = 0;
    int pick[6]; float pval[6];
    for (int k=0;k<6;k++){
        float bv = -1e30f; int bj = 128;
        #pragma unroll
        for (int q=0;q<4;q++){
            if (!((used>>q)&1u)){
                int j = lane + q*32;
                if (v[q] > bv){ bv = v[q]; bj = j; }
            }
        }
        #pragma unroll
        for (int off=16; off>0; off>>=1){
            float ov = __shfl_xor_sync(0xffffffffu, bv, off);
            int   oj = __shfl_xor_sync(0xffffffffu, bj, off);
            if (ov > bv || (ov == bv && oj < bj)){ bv = ov; bj = oj; }
        }
        pick[k]=bj; pval[k]=bv;
        if ((bj & 31) == lane) used |= 1u << (bj >> 5);
    }
    int jb = lane*4;
    unsigned char c0=0,c1=0,c2=0,c3=0;
    #pragma unroll
    for (int k=0;k<6;k++){
        if (pval[k] > 0.1f && pick[k] != i){
            int d = pick[k] - jb;
            if (d==0) c0=1; else if (d==1) c1=1; else if (d==2) c2=1; else if (d==3) c3=1;
        }
    }
    int ds = i - jb;
    if (ds>=0 && ds<4){ if(ds==0)c0=1; else if(ds==1)c1=1; else if(ds==2)c2=1; else c3=1; }
    *(uchar4*)&g_Adj[(size_t)row*EE + jb] = make_uchar4(c0,c1,c2,c3);
}

// ============================================================================
// K6: per-row src/dst dots for GAT1 (unchanged)
// ============================================================================
__global__ __launch_bounds__(128) void sd1_kernel(const float* __restrict__ a_src,
                                                  const float* __restrict__ a_dst)
{
    int row = blockIdx.x;
    int hd = threadIdx.x >> 5, lane = threadIdx.x & 31;
    const float* hrow = &g_h1[(size_t)row*512 + hd*128];
    float ps = 0.f, pd = 0.f;
    #pragma unroll
    for (int q=0;q<4;q++){
        float hv = hrow[lane + 32*q];
        ps = fmaf(hv, a_src[hd*128 + lane + 32*q], ps);
        pd = fmaf(hv, a_dst[hd*128 + lane + 32*q], pd);
    }
    #pragma unroll
    for (int off=16;off>0;off>>=1){
        ps += __shfl_xor_sync(0xffffffffu,ps,off);
        pd += __shfl_xor_sync(0xffffffffu,pd,off);
    }
    if (lane==0){ g_s1[row*4+hd]=ps; g_d1[row*4+hd]=pd; }
}

// ============================================================================
// K7: GAT1 attention + LN + elu (unchanged)
// ============================================================================
__global__ __launch_bounds__(128) void att1_kernel(
    const float* __restrict__ b_g1, const float* __restrict__ gamma,
    const float* __restrict__ beta)
{
    __shared__ int act[EE];
    __shared__ int wcnt[4], woff[4];
    __shared__ int nact_s;
    __shared__ float wts[4][EE];
    __shared__ float red[4], red2[4];

    int be = blockIdx.x;
    int b = be / EE, t = be % EE;
    int tid = threadIdx.x, w = tid>>5, lane = tid&31;

    bool flag = g_Adj[(size_t)(b*EE + tid)*EE + t] != 0;
    unsigned mball = __ballot_sync(0xffffffffu, flag);
    if (lane==0) wcnt[w] = __popc(mball);
    __syncthreads();
    if (tid==0){ int o=0; for (int i2=0;i2<4;i2++){ woff[i2]=o; o+=wcnt[i2]; } nact_s=o; }
    __syncthreads();
    if (flag) act[woff[w] + __popc(mball & ((1u<<lane)-1u))] = tid;
    __syncthreads();
    int nact = nact_s;

    {
        int hd = w;
        float dv = g_d1[be*4 + hd];
        float mx = -1e30f;
        for (int k=lane;k<nact;k+=32){
            float e = g_s1[(b*EE+act[k])*4 + hd] + dv;
            e = e > 0.f ? e : 0.2f*e;
            wts[hd][k] = e;
            mx = fmaxf(mx, e);
        }
        #pragma unroll
        for (int off=16;off>0;off>>=1) mx = fmaxf(mx, __shfl_xor_sync(0xffffffffu,mx,off));
        float sum = 0.f;
        for (int k=lane;k<nact;k+=32){
            float e = expf(wts[hd][k]-mx);
            wts[hd][k] = e; sum += e;
        }
        #pragma unroll
        for (int off=16;off>0;off>>=1) sum += __shfl_xor_sync(0xffffffffu,sum,off);
        float inv = 1.f/sum;
        for (int k=lane;k<nact;k+=32) wts[hd][k] *= inv;
    }
    __syncthreads();

    float ov[4];
    #pragma unroll
    for (int q=0;q<4;q++){
        int f = tid + q*128;
        float o = 0.f;
        for (int k=0;k<nact;k++)
            o = fmaf(wts[q][k], g_h1[(size_t)(b*EE+act[k])*512 + f], o);
        ov[q] = o + b_g1[f];
    }
    float ls = ov[0]+ov[1]+ov[2]+ov[3];
    #pragma unroll
    for (int off=16;off>0;off>>=1) ls += __shfl_xor_sync(0xffffffffu,ls,off);
    if (lane==0) red[w] = ls;
    __syncthreads();
    float mean = (red[0]+red[1]+red[2]+red[3]) * (1.f/512.f);
    float lv = 0.f;
    #pragma unroll
    for (int q=0;q<4;q++){ float d = ov[q]-mean; lv = fmaf(d,d,lv); }
    #pragma unroll
    for (int off=16;off>0;off>>=1) lv += __shfl_xor_sync(0xffffffffu,lv,off);
    if (lane==0) red2[w] = lv;
    __syncthreads();
    float var = (red2[0]+red2[1]+red2[2]+red2[3]) * (1.f/512.f);
    float rstd = rsqrtf(var + 1e-5f);
    #pragma unroll
    for (int q=0;q<4;q++){
        int f = tid + q*128;
        float y = (ov[q]-mean)*rstd*gamma[f] + beta[f];
        y = y > 0.f ? y : expm1f(y);
        g_g1v[(size_t)be*512 + f] = y;
    }
}

// ============================================================================
// K8: h2 = g1 @ W_g2 + s2/d2 dots (unchanged)
// ============================================================================
__global__ __launch_bounds__(64) void gat2h_kernel(
    const float* __restrict__ Wg2, const float* __restrict__ a_src2,
    const float* __restrict__ a_dst2)
{
    __shared__ float grow[512];
    __shared__ float rs[2], rd[2];
    int row = blockIdx.x, tid = threadIdx.x;
    for (int i=tid;i<512;i+=64) grow[i] = g_g1v[(size_t)row*512 + i];
    __syncthreads();
    float acc = 0.f;
    for (int k=0;k<512;k++) acc = fmaf(grow[k], Wg2[k*64 + tid], acc);
    g_h2[(size_t)row*64 + tid] = acc;
    float ps = acc * a_src2[tid];
    float pd = acc * a_dst2[tid];
    #pragma unroll
    for (int off=16;off>0;off>>=1){
        ps += __shfl_xor_sync(0xffffffffu,ps,off);
        pd += __shfl_xor_sync(0xffffffffu,pd,off);
    }
    int w = tid>>5, lane = tid&31;
    if (lane==0){ rs[w]=ps; rd[w]=pd; }
    __syncthreads();
    if (tid==0){ g_s2[row]=rs[0]+rs[1]; g_d2[row]=rd[0]+rd[1]; }
}

// ============================================================================
// K9: GAT2 attention + LN + elu (unchanged)
// ============================================================================
__global__ __launch_bounds__(128) void att2_kernel(
    const float* __restrict__ b_g2, const float* __restrict__ gamma,
    const float* __restrict__ beta)
{
    __shared__ int act[EE];
    __shared__ int wcnt[4], woff[4];
    __shared__ int nact_s;
    __shared__ float wts[EE];
    __shared__ float red[2], red2[2];

    int be = blockIdx.x;
    int b = be / EE, t = be % EE;
    int tid = threadIdx.x, w = tid>>5, lane = tid&31;

    bool flag = g_Adj[(size_t)(b*EE + tid)*EE + t] != 0;
    unsigned mball = __ballot_sync(0xffffffffu, flag);
    if (lane==0) wcnt[w] = __popc(mball);
    __syncthreads();
    if (tid==0){ int o=0; for (int i2=0;i2<4;i2++){ woff[i2]=o; o+=wcnt[i2]; } nact_s=o; }
    __syncthreads();
    if (flag) act[woff[w] + __popc(mball & ((1u<<lane)-1u))] = tid;
    __syncthreads();
    int nact = nact_s;

    if (w == 0){
        float dv = g_d2[be];
        float mx = -1e30f;
        for (int k=lane;k<nact;k+=32){
            float e = g_s2[b*EE + act[k]] + dv;
            e = e > 0.f ? e : 0.2f*e;
            wts[k] = e;
            mx = fmaxf(mx, e);
        }
        #pragma unroll
        for (int off=16;off>0;off>>=1) mx = fmaxf(mx, __shfl_xor_sync(0xffffffffu,mx,off));
        float sum = 0.f;
        for (int k=lane;k<nact;k+=32){
            float e = expf(wts[k]-mx);
            wts[k] = e; sum += e;
        }
        #pragma unroll
        for (int off=16;off>0;off>>=1) sum += __shfl_xor_sync(0xffffffffu,sum,off);
        float inv = 1.f/sum;
        for (int k=lane;k<nact;k+=32) wts[k] *= inv;
    }
    __syncthreads();

    float o = 0.f;
    if (tid < 64){
        for (int k=0;k<nact;k++)
            o = fmaf(wts[k], g_h2[(size_t)(b*EE+act[k])*64 + tid], o);
        o += b_g2[tid];
    }
    float ls = (tid<64) ? o : 0.f;
    #pragma unroll
    for (int off=16;off>0;off>>=1) ls += __shfl_xor_sync(0xffffffffu,ls,off);
    if (w < 2 && lane==0) red[w] = ls;
    __syncthreads();
    float mean = (red[0]+red[1]) * (1.f/64.f);
    float dv2 = (tid<64) ? (o-mean) : 0.f;
    float lv = dv2*dv2;
    #pragma unroll
    for (int off=16;off>0;off>>=1) lv += __shfl_xor_sync(0xffffffffu,lv,off);
    if (w < 2 && lane==0) red2[w] = lv;
    __syncthreads();
    float var = (red2[0]+red2[1]) * (1.f/64.f);
    if (tid < 64){
        float y = (o-mean)*rsqrtf(var+1e-5f)*gamma[tid] + beta[tid];
        y = y > 0.f ? y : expm1f(y);
        g_ent[(size_t)be*64 + tid] = y;
    }
}

// ============================================================================
// K10: per-batch cls contribution + b_r1  -> g_clsp
// ============================================================================
__global__ __launch_bounds__(256) void cls_kernel(const float* __restrict__ seq,
                                                  const float* __restrict__ W_r1,
                                                  const float* __restrict__ b_r1)
{
    __shared__ float c[HH];
    int b = blockIdx.x, tid = threadIdx.x;
    for (int d=tid; d<HH; d+=256) c[d] = seq[(size_t)b*SS*HH + d];
    __syncthreads();
    float acc = b_r1[tid];
    for (int d=0; d<HH; d++) acc = fmaf(c[d], W_r1[(160+d)*256 + tid], acc);
    g_clsp[b*256 + tid] = acc;
}

// ============================================================================
// K10b: Rp[r] = rel_emb[r] @ W_r1[128:160]
// ============================================================================
__global__ __launch_bounds__(256) void rp_kernel(const float* __restrict__ rel_emb,
                                                 const float* __restrict__ W_r1)
{
    __shared__ float re[32];
    int r = blockIdx.x, tid = threadIdx.x;
    if (tid < 32) re[tid] = rel_emb[r*32 + tid];
    __syncthreads();
    float s = 0.f;
    #pragma unroll 8
    for (int k=0;k<32;k++) s = fmaf(re[k], W_r1[(128+k)*256 + tid], s);
    g_Rp[r*256 + tid] = s;
}

// ============================================================================
// K11: relation head per pair (factored). Warp per pair.
// ============================================================================
__global__ __launch_bounds__(256) void pair_kernel(
    const int* __restrict__ pair_head, const int* __restrict__ pair_tail,
    const int* __restrict__ pair_rel,  const float* __restrict__ W_r2,
    const float* __restrict__ b_r2,    float* __restrict__ out)
{
    int w = threadIdx.x >> 5, lane = threadIdx.x & 31;
    int bp = blockIdx.x*8 + w;
    int b = bp >> 8;
    int h = pair_head[bp], t = pair_tail[bp], r = pair_rel[bp];
    const float* He = &g_He[(size_t)(b*EE+h)*256 + lane*8];
    const float* Te = &g_Te[(size_t)(b*EE+t)*256 + lane*8];
    const float* Rp = &g_Rp[r*256 + lane*8];
    const float* Cp = &g_clsp[b*256 + lane*8];
    float s = 0.f;
    #pragma unroll
    for (int q=0;q<2;q++){
        float4 a  = *(const float4*)(He + 4*q);
        float4 bb = *(const float4*)(Te + 4*q);
        float4 c  = *(const float4*)(Rp + 4*q);
        float4 d  = *(const float4*)(Cp + 4*q);
        float4 w4 = *(const float4*)&W_r2[lane*8 + 4*q];
        float h0 = fmaxf(a.x+bb.x+c.x+d.x, 0.f); s = fmaf(h0, w4.x, s);
        float h1 = fmaxf(a.y+bb.y+c.y+d.y, 0.f); s = fmaf(h1, w4.y, s);
        float h2 = fmaxf(a.z+bb.z+c.z+d.z, 0.f); s = fmaf(h2, w4.z, s);
        float h3 = fmaxf(a.w+bb.w+c.w+d.w, 0.f); s = fmaf(h3, w4.w, s);
    }
    #pragma unroll
    for (int off=16;off>0;off>>=1) s += __shfl_xor_sync(0xffffffffu,s,off);
    if (lane == 0) out[NER_TOTAL + bp] = s + b_r2[0];
}

// ============================================================================
extern "C" void kernel_launch(void* const* d_in, const int* in_sizes, int n_in,
                              void* d_out, int out_size)
{
    (void)in_sizes; (void)n_in; (void)out_size;
    const float* seq       = (const float*)d_in[0];
    const int*   span_start= (const int*)d_in[1];
    const int*   span_len  = (const int*)d_in[2];
    const int*   ent_type  = (const int*)d_in[3];
    const int*   pair_head = (const int*)d_in[4];
    const int*   pair_tail = (const int*)d_in[5];
    const int*   pair_rel  = (const int*)d_in[6];
    const float* W_ner1    = (const float*)d_in[7];
    const float* b_ner1    = (const float*)d_in[8];
    const float* W_ner2    = (const float*)d_in[9];
    const float* b_ner2    = (const float*)d_in[10];
    const float* type_emb  = (const float*)d_in[11];
    const float* W_g1      = (const float*)d_in[12];
    const float* a_src1    = (const float*)d_in[13];
    const float* a_dst1    = (const float*)d_in[14];
    const float* b_g1      = (const float*)d_in[15];
    const float* g1_gamma  = (const float*)d_in[16];
    const float* g1_beta   = (const float*)d_in[17];
    const float* W_g2      = (const float*)d_in[18];
    const float* a_src2    = (const float*)d_in[19];
    const float* a_dst2    = (const float*)d_in[20];
    const float* b_g2      = (const float*)d_in[21];
    const float* g2_gamma  = (const float*)d_in[22];
    const float* g2_beta   = (const float*)d_in[23];
    const float* rel_emb   = (const float*)d_in[24];
    const float* W_r1      = (const float*)d_in[25];
    const float* b_r1      = (const float*)d_in[26];
    const float* W_r2      = (const float*)d_in[27];
    const float* b_r2      = (const float*)d_in[28];
    float* out = (float*)d_out;

    // one-time side stream + fork/join events (created on the correctness call,
    // reused on the capture call so capture-time alloc delta stays 0)
    static cudaStream_t sA = nullptr;
    static cudaEvent_t evRoot = nullptr, evA = nullptr;
    if (!sA){
        cudaStreamCreateWithFlags(&sA, cudaStreamNonBlocking);
        cudaEventCreateWithFlags(&evRoot, cudaEventDisableTiming);
        cudaEventCreateWithFlags(&evA, cudaEventDisableTiming);
    }

    cudaFuncSetAttribute((const void*)pool_kernel,
                         cudaFuncAttributeMaxDynamicSharedMemorySize, 65536);

    // ---- fork: NER branch on side stream (independent of graph chain) ----
    cudaEventRecord(evRoot, 0);
    cudaStreamWaitEvent(sA, evRoot, 0);
    gemm_kernel<<<dim3((BB*SS)/64, 2), 128, 0, sA>>>(0, seq, W_ner1, b_ner1, HH, 256, HH, 1);
    ner_head<<<(BB*SS)/8, 256, 0, sA>>>(W_ner2, b_ner2, out);
    cudaEventRecord(evA, sA);

    // ---- main chain ----
    cls_kernel<<<BB, 256>>>(seq, W_r1, b_r1);
    rp_kernel<<<9, 256>>>(rel_emb, W_r1);
    pool_kernel<<<BB*EE, 256, LL*HH*sizeof(float)>>>(seq, span_start, span_len,
                                                     ent_type, type_emb);
    sim_kernel<<<BB*2, 128>>>();
    topk_kernel<<<(BB*EE)/8, 256>>>();

    gemm_kernel<<<dim3((BB*EE)/64, 4), 128>>>(1, nullptr, W_g1, nullptr, HH, 512, HH, 0);
    sd1_kernel<<<BB*EE, 128>>>(a_src1, a_dst1);
    att1_kernel<<<BB*EE, 128>>>(b_g1, g1_gamma, g1_beta);

    gat2h_kernel<<<BB*EE, 64>>>(W_g2, a_src2, a_dst2);
    att2_kernel<<<BB*EE, 128>>>(b_g2, g2_gamma, g2_beta);

    gemm_kernel<<<dim3((BB*EE)/64, 2), 128>>>(2, nullptr, W_r1,          nullptr, 64, 256, 64, 0);
    gemm_kernel<<<dim3((BB*EE)/64, 2), 128>>>(3, nullptr, W_r1 + 64*256, nullptr, 64, 256, 64, 0);
    pair_kernel<<<(BB*PP)/8, 256>>>(pair_head, pair_tail, pair_rel,
                                    W_r2, b_r2, out);

    // ---- join ----
    cudaStreamWaitEvent(0, evA, 0);
}

// round 7
// speedup vs baseline: 1.5847x; 1.0678x over previous
#include <cuda_runtime.h>
#include <cuda_bf16.h>
#include <cstdint>
#include <math.h>

#define BB 48
#define SS 512
#define HH 768
#define EE 128
#define LL 16
#define PP 256
#define NERC 11
#define NER_TOTAL (BB*SS*NERC)   // 270336

// ---------------- scratch (device globals; no allocation allowed) -------------
__device__ __align__(16) float g_x  [BB*EE*HH];
__device__ __align__(16) float g_xn [BB*EE*HH];
__device__ __align__(16) float g_sim[BB*EE*EE];
__device__ unsigned char g_Adj[BB*EE*EE];
__device__ __align__(16) float g_h1 [BB*EE*512];
__device__ float g_s1 [BB*EE*4];
__device__ float g_d1 [BB*EE*4];
__device__ __align__(16) float g_g1v[BB*EE*512];
__device__ __align__(16) float g_h2 [BB*EE*64];
__device__ float g_s2 [BB*EE];
__device__ float g_d2 [BB*EE];
__device__ __align__(16) float g_ent[BB*EE*64];
__device__ __align__(16) float g_clsp[BB*256];
__device__ __align__(16) float g_hid[BB*SS*256];
__device__ __align__(16) float g_He [BB*EE*256];
__device__ __align__(16) float g_Te [BB*EE*256];
__device__ __align__(16) float g_Rp [9*256];
__device__ __align__(16) __nv_bfloat16 g_W1t_hi [256*768];
__device__ __align__(16) __nv_bfloat16 g_W1t_lo [256*768];
__device__ __align__(16) __nv_bfloat16 g_Wg1t_hi[512*768];
__device__ __align__(16) __nv_bfloat16 g_Wg1t_lo[512*768];
__device__ __align__(16) __nv_bfloat16 g_seq_hi [BB*SS*HH];
__device__ __align__(16) __nv_bfloat16 g_seq_lo [BB*SS*HH];
__device__ __align__(16) __nv_bfloat16 g_x_hi   [BB*EE*HH];
__device__ __align__(16) __nv_bfloat16 g_x_lo   [BB*EE*HH];

// ---------------- helpers ----------------
__device__ __forceinline__ unsigned long long ffma2(unsigned long long a,
                                                    unsigned long long b,
                                                    unsigned long long c){
    unsigned long long d;
    asm("fma.rn.f32x2 %0, %1, %2, %3;" : "=l"(d) : "l"(a), "l"(b), "l"(c));
    return d;
}
union F2U { unsigned long long u; float2 f; };
__device__ __forceinline__ void cpa16(void* s, const void* g){
    unsigned sa = (unsigned)__cvta_generic_to_shared(s);
    asm volatile("cp.async.ca.shared.global [%0], [%1], 16;" :: "r"(sa), "l"(g));
}
__device__ __forceinline__ void mma16816(float* c, const unsigned* a, const unsigned* b){
    asm volatile("mma.sync.aligned.m16n8k16.row.col.f32.bf16.bf16.f32 "
        "{%0,%1,%2,%3}, {%4,%5,%6,%7}, {%8,%9}, {%0,%1,%2,%3};"
        : "+f"(c[0]), "+f"(c[1]), "+f"(c[2]), "+f"(c[3])
        : "r"(a[0]), "r"(a[1]), "r"(a[2]), "r"(a[3]), "r"(b[0]), "r"(b[1]));
}

// ============================================================================
// presplit: X fp32 -> Xhi/Xlo bf16 (hi = rn(x), lo = rn(x - hi)). 8 elems/thread.
// ============================================================================
__global__ __launch_bounds__(256) void presplit_kernel(
    const float* __restrict__ X,
    __nv_bfloat16* __restrict__ oh, __nv_bfloat16* __restrict__ ol)
{
    size_t i = (size_t)blockIdx.x*256 + threadIdx.x;
    float4 f0 = *(const float4*)(X + i*8);
    float4 f1 = *(const float4*)(X + i*8 + 4);
    float xs[8] = {f0.x,f0.y,f0.z,f0.w,f1.x,f1.y,f1.z,f1.w};
    union { __nv_bfloat16 h[8]; uint4 v; } H, L;
    #pragma unroll
    for (int j=0;j<8;j++){
        H.h[j] = __float2bfloat16(xs[j]);
        L.h[j] = __float2bfloat16(xs[j] - __bfloat162float(H.h[j]));
    }
    *(uint4*)(oh + i*8) = H.v;
    *(uint4*)(ol + i*8) = L.v;
}

// ============================================================================
// tsplit: Wt_hi/lo[n][k] = bf16-split(W[k][n]).  32x32 smem transpose tiles.
// ============================================================================
__global__ void tsplit_kernel(const float* __restrict__ W, int N,
                              __nv_bfloat16* __restrict__ oh,
                              __nv_bfloat16* __restrict__ ol)
{
    __shared__ float t[32][33];
    int n0 = blockIdx.x*32, k0 = blockIdx.y*32;
    int tx = threadIdx.x, ty = threadIdx.y;
    for (int r = ty; r < 32; r += 8)
        t[r][tx] = W[(size_t)(k0+r)*N + n0+tx];
    __syncthreads();
    for (int r = ty; r < 32; r += 8){
        float v = t[tx][r];
        __nv_bfloat16 h = __float2bfloat16(v);
        __nv_bfloat16 l = __float2bfloat16(v - __bfloat162float(h));
        oh[(size_t)(n0+r)*HH + k0+tx] = h;
        ol[(size_t)(n0+r)*HH + k0+tx] = l;
    }
}

// ============================================================================
// mma_direct: C[M,N] += Asplit[M,768] @ Btsplit[N,768]^T  (3-term bf16 hi/lo)
// No smem. Fragments loaded straight from global per the PTX m16n8k16 map.
// 128x128 CTA tile, 8 warps (4m x 2n), warp tile 32x64.
// ============================================================================
__global__ __launch_bounds__(256) void mma_direct(
    const __nv_bfloat16* __restrict__ Ah, const __nv_bfloat16* __restrict__ Al,
    const __nv_bfloat16* __restrict__ Bh, const __nv_bfloat16* __restrict__ Bl,
    float* __restrict__ C, int N,
    const float* __restrict__ bias, int dorelu)
{
    int lane = threadIdx.x & 31, wid = threadIdx.x >> 5;
    int wm = wid & 3, wn = wid >> 2;
    int m0 = blockIdx.x*128, n0 = blockIdx.y*128;
    int g = lane >> 2, tg = lane & 3;

    float acc[2][8][4];
    #pragma unroll
    for (int mt=0;mt<2;mt++)
        #pragma unroll
        for (int nt=0;nt<8;nt++)
            #pragma unroll
            for (int q=0;q<4;q++) acc[mt][nt][q] = 0.f;

    const __nv_bfloat16* aph = Ah + (size_t)(m0 + wm*32 + g)*HH + tg*2;
    const __nv_bfloat16* apl = Al + (size_t)(m0 + wm*32 + g)*HH + tg*2;
    const __nv_bfloat16* bph = Bh + (size_t)(n0 + wn*64 + g)*HH + tg*2;
    const __nv_bfloat16* bpl = Bl + (size_t)(n0 + wn*64 + g)*HH + tg*2;

    for (int kc = 0; kc < HH; kc += 16){
        unsigned ah[2][4], al[2][4];
        #pragma unroll
        for (int mt=0; mt<2; mt++){
            const __nv_bfloat16* ph = aph + (size_t)mt*16*HH + kc;
            const __nv_bfloat16* pl = apl + (size_t)mt*16*HH + kc;
            ah[mt][0] = *(const unsigned*)(ph);
            ah[mt][1] = *(const unsigned*)(ph + 8*HH);
            ah[mt][2] = *(const unsigned*)(ph + 8);
            ah[mt][3] = *(const unsigned*)(ph + 8*HH + 8);
            al[mt][0] = *(const unsigned*)(pl);
            al[mt][1] = *(const unsigned*)(pl + 8*HH);
            al[mt][2] = *(const unsigned*)(pl + 8);
            al[mt][3] = *(const unsigned*)(pl + 8*HH + 8);
        }
        unsigned bhf[8][2], blf[8][2];
        #pragma unroll
        for (int nt=0; nt<8; nt++){
            const __nv_bfloat16* ph = bph + (size_t)nt*8*HH + kc;
            const __nv_bfloat16* pl = bpl + (size_t)nt*8*HH + kc;
            bhf[nt][0] = *(const unsigned*)(ph);
            bhf[nt][1] = *(const unsigned*)(ph + 8);
            blf[nt][0] = *(const unsigned*)(pl);
            blf[nt][1] = *(const unsigned*)(pl + 8);
        }
        #pragma unroll
        for (int mt=0; mt<2; mt++)
            #pragma unroll
            for (int nt=0; nt<8; nt++){
                mma16816(acc[mt][nt], ah[mt], bhf[nt]);
                mma16816(acc[mt][nt], ah[mt], blf[nt]);
                mma16816(acc[mt][nt], al[mt], bhf[nt]);
            }
    }

    #pragma unroll
    for (int mt=0; mt<2; mt++){
        int rbase = m0 + wm*32 + mt*16 + g;
        #pragma unroll
        for (int nt=0; nt<8; nt++){
            int col = n0 + wn*64 + nt*8 + tg*2;
            float b0 = 0.f, b1 = 0.f;
            if (bias){ b0 = bias[col]; b1 = bias[col+1]; }
            float v0 = acc[mt][nt][0] + b0, v1 = acc[mt][nt][1] + b1;
            float v2 = acc[mt][nt][2] + b0, v3 = acc[mt][nt][3] + b1;
            if (dorelu){
                v0 = fmaxf(v0,0.f); v1 = fmaxf(v1,0.f);
                v2 = fmaxf(v2,0.f); v3 = fmaxf(v3,0.f);
            }
            *(float2*)&C[(size_t)rbase*N + col]     = make_float2(v0, v1);
            *(float2*)&C[(size_t)(rbase+8)*N + col] = make_float2(v2, v3);
        }
    }
}

// ============================================================================
// Small-GEMM (He/Te): FFMA2, 64x128 tile.
// ============================================================================
__global__ __launch_bounds__(128, 3) void gemm_kernel(
    int sel, const float* __restrict__ B, int ldb, int K)
{
    __shared__ __align__(16) float2 As2[2][16][64];
    __shared__ __align__(16) float  Bs [2][16][128];

    const float* A = g_ent;
    float* C = (sel == 2) ? g_He : g_Te;

    int tid = threadIdx.x;
    int tm = tid >> 4, tn = tid & 15;
    int m0 = blockIdx.x * 64, n0 = blockIdx.y * 128;
    int nch = K >> 4;

    unsigned long long acc[8][4];
    #pragma unroll
    for (int i=0;i<8;i++)
        #pragma unroll
        for (int p=0;p<4;p++) acc[i][p] = 0ull;

    int lr = tid >> 1, lc8 = (tid & 1) * 8;
    const float* aP = A + (size_t)(m0 + lr) * K + lc8;
    int bkk[4], bc4[4];
    #pragma unroll
    for (int i=0;i<4;i++){ int q = i*128 + tid; bkk[i] = q >> 5; bc4[i] = (q & 31) * 4; }

    float4 pa0, pa1;
    pa0 = *(const float4*)(aP);
    pa1 = *(const float4*)(aP + 4);
    #pragma unroll
    for (int i=0;i<4;i++)
        cpa16(&Bs[0][bkk[i]][bc4[i]], B + (size_t)bkk[i]*ldb + n0 + bc4[i]);
    asm volatile("cp.async.commit_group;");
    {
        float v[8] = {pa0.x,pa0.y,pa0.z,pa0.w,pa1.x,pa1.y,pa1.z,pa1.w};
        #pragma unroll
        for (int j=0;j<8;j++) As2[0][lc8+j][lr] = make_float2(v[j],v[j]);
    }

    for (int c = 0; c < nch; c++){
        int cb = c & 1, nb = cb ^ 1;
        if (c + 1 < nch){
            int k0n = (c+1)*16;
            pa0 = *(const float4*)(aP + k0n);
            pa1 = *(const float4*)(aP + k0n + 4);
            #pragma unroll
            for (int i=0;i<4;i++)
                cpa16(&Bs[nb][bkk[i]][bc4[i]],
                      B + (size_t)(k0n + bkk[i])*ldb + n0 + bc4[i]);
            asm volatile("cp.async.commit_group;");
            asm volatile("cp.async.wait_group 1;");
        } else {
            asm volatile("cp.async.wait_group 0;");
        }
        __syncthreads();
        #pragma unroll
        for (int kk=0;kk<16;kk++){
            unsigned long long b2[4];
            #pragma unroll
            for (int p=0;p<4;p++)
                b2[p] = *(const unsigned long long*)&Bs[cb][kk][2*(tn + 16*p)];
            #pragma unroll
            for (int i=0;i<8;i++){
                unsigned long long a2 =
                    *(const unsigned long long*)&As2[cb][kk][tm*8+i];
                acc[i][0] = ffma2(a2, b2[0], acc[i][0]);
                acc[i][1] = ffma2(a2, b2[1], acc[i][1]);
                acc[i][2] = ffma2(a2, b2[2], acc[i][2]);
                acc[i][3] = ffma2(a2, b2[3], acc[i][3]);
            }
        }
        __syncthreads();
        if (c + 1 < nch){
            float v[8] = {pa0.x,pa0.y,pa0.z,pa0.w,pa1.x,pa1.y,pa1.z,pa1.w};
            #pragma unroll
            for (int j=0;j<8;j++) As2[nb][lc8+j][lr] = make_float2(v[j],v[j]);
        }
    }

    #pragma unroll
    for (int i=0;i<8;i++){
        size_t row = m0 + tm*8 + i;
        #pragma unroll
        for (int p=0;p<4;p++){
            F2U u; u.u = acc[i][p];
            *(float2*)&C[row*ldb + n0 + 32*p + 2*tn] = u.f;
        }
    }
}

// ============================================================================
// ner_head: out = g_hid @ W2 + b2.  Warp per row, 8 rows/block.
// ============================================================================
__global__ __launch_bounds__(256) void ner_head(
    const float* __restrict__ W2, const float* __restrict__ b2,
    float* __restrict__ out)
{
    __shared__ float W2t[NERC][256];
    __shared__ float b2s[NERC];
    int tid = threadIdx.x;
    for (int i = tid; i < 256*NERC; i += 256){
        int c = i / NERC, jo = i % NERC;
        W2t[jo][c] = W2[i];
    }
    if (tid < NERC) b2s[tid] = b2[tid];
    __syncthreads();
    int w = tid >> 5, lane = tid & 31;
    int row = blockIdx.x*8 + w;
    const float* hr = &g_hid[(size_t)row*256 + lane*8];
    float4 v0 = *(const float4*)hr;
    float4 v1 = *(const float4*)(hr + 4);
    #pragma unroll
    for (int jo = 0; jo < NERC; jo++){
        const float* wr = &W2t[jo][lane*8];
        float4 w0 = *(const float4*)wr;
        float4 w1 = *(const float4*)(wr + 4);
        float p = 0.f;
        p = fmaf(v0.x, w0.x, p); p = fmaf(v0.y, w0.y, p);
        p = fmaf(v0.z, w0.z, p); p = fmaf(v0.w, w0.w, p);
        p = fmaf(v1.x, w1.x, p); p = fmaf(v1.y, w1.y, p);
        p = fmaf(v1.z, w1.z, p); p = fmaf(v1.w, w1.w, p);
        #pragma unroll
        for (int off=16;off>0;off>>=1) p += __shfl_xor_sync(0xffffffffu,p,off);
        if (lane == 0) out[row*NERC + jo] = p + b2s[jo];
    }
}

// ============================================================================
// pool_kernel (+ writes g_x_hi / g_x_lo for the gat1 MMA)
// ============================================================================
__global__ __launch_bounds__(256) void pool_kernel(
    const float* __restrict__ seq, const int* __restrict__ span_start,
    const int* __restrict__ span_len, const int* __restrict__ ent_type,
    const float* __restrict__ type_emb)
{
    extern __shared__ float tok[];
    __shared__ float meanv[HH];
    __shared__ float sc[LL];
    __shared__ float wv[LL];
    __shared__ float red[8];

    int be = blockIdx.x;
    int b = be / EE;
    int tid = threadIdx.x;
    int start = span_start[be];
    int len = span_len[be];
    float cnt = (float)(len + 1);

    const float4* src = (const float4*)&seq[(size_t)(b*SS + start)*HH];
    float4* dst4 = (float4*)tok;
    for (int q = tid; q < LL*HH/4; q += 256) dst4[q] = src[q];
    __syncthreads();

    for (int d = tid; d < HH; d += 256){
        float s = 0.f;
        for (int l = 0; l <= len; l++) s += tok[l*HH + d];
        meanv[d] = s / cnt;
    }
    __syncthreads();

    int w = tid >> 5, lane = tid & 31;
    for (int l = w; l < LL; l += 8){
        float p = 0.f;
        for (int d = lane; d < HH; d += 32) p = fmaf(tok[l*HH+d], meanv[d], p);
        #pragma unroll
        for (int off=16;off>0;off>>=1) p += __shfl_xor_sync(0xffffffffu,p,off);
        if (lane==0) sc[l] = p;
    }
    __syncthreads();

    if (tid == 0){
        float mx = -1e30f;
        for (int l=0;l<=len;l++) mx = fmaxf(mx, sc[l]);
        float s = 0.f;
        for (int l=0;l<=len;l++){ float e = expf(sc[l]-mx); wv[l]=e; s+=e; }
        float inv = 1.f/s;
        for (int l=0;l<=len;l++) wv[l] *= inv;
        for (int l=len+1;l<LL;l++) wv[l] = 0.f;
    }
    __syncthreads();

    const float* te = &type_emb[ent_type[be]*HH];
    float xv[3]; float nsq = 0.f;
    #pragma unroll
    for (int q = 0; q < 3; q++){
        int d = tid + q*256;
        float p = 0.f;
        for (int l = 0; l <= len; l++) p = fmaf(wv[l], tok[l*HH+d], p);
        float v = p + te[d];
        xv[q] = v;
        g_x[(size_t)be*HH + d] = v;
        __nv_bfloat16 h = __float2bfloat16(v);
        g_x_hi[(size_t)be*HH + d] = h;
        g_x_lo[(size_t)be*HH + d] = __float2bfloat16(v - __bfloat162float(h));
        nsq = fmaf(v, v, nsq);
    }
    #pragma unroll
    for (int off=16;off>0;off>>=1) nsq += __shfl_xor_sync(0xffffffffu,nsq,off);
    if (lane==0) red[w] = nsq;
    __syncthreads();
    float tot = 0.f;
    #pragma unroll
    for (int i=0;i<8;i++) tot += red[i];
    float inv = 1.f / fmaxf(sqrtf(tot), 1e-12f);
    #pragma unroll
    for (int q=0;q<3;q++){
        int d = tid + q*256;
        g_xn[(size_t)be*HH + d] = xv[q]*inv;
    }
}

// ============================================================================
// sim_kernel (FFMA2, unchanged)
// ============================================================================
__global__ __launch_bounds__(128) void sim_kernel()
{
    __shared__ __align__(16) float2 As2[2][16][64];
    __shared__ float Xt[2][16][132];

    int b = blockIdx.x >> 1;
    int i0 = (blockIdx.x & 1) * 64;
    const float* X = &g_xn[(size_t)b*EE*HH];
    int tid = threadIdx.x;
    int tm = tid >> 4, tn = tid & 15;

    unsigned long long acc[8][4];
    #pragma unroll
    for (int i=0;i<8;i++)
        #pragma unroll
        for (int p=0;p<4;p++) acc[i][p] = 0ull;

    int ar = tid >> 1, akq = (tid & 1) * 8;
    const float* aP = X + (size_t)(i0 + ar)*HH + akq;
    const float* xP = X + (size_t)tid*HH;

    float4 pa0, pa1, px[4];
    pa0 = *(const float4*)(aP);
    pa1 = *(const float4*)(aP + 4);
    #pragma unroll
    for (int q=0;q<4;q++) px[q] = *(const float4*)(xP + 4*q);
    {
        float v[8] = {pa0.x,pa0.y,pa0.z,pa0.w,pa1.x,pa1.y,pa1.z,pa1.w};
        #pragma unroll
        for (int j=0;j<8;j++) As2[0][akq+j][ar] = make_float2(v[j],v[j]);
        #pragma unroll
        for (int q=0;q<4;q++){
            Xt[0][4*q+0][tid] = px[q].x;
            Xt[0][4*q+1][tid] = px[q].y;
            Xt[0][4*q+2][tid] = px[q].z;
            Xt[0][4*q+3][tid] = px[q].w;
        }
    }

    for (int c = 0; c < 48; c++){
        int cb = c & 1, nb = cb ^ 1;
        __syncthreads();
        if (c + 1 < 48){
            int k0n = (c+1)*16;
            pa0 = *(const float4*)(aP + k0n);
            pa1 = *(const float4*)(aP + k0n + 4);
            #pragma unroll
            for (int q=0;q<4;q++) px[q] = *(const float4*)(xP + k0n + 4*q);
        }
        #pragma unroll
        for (int kk=0;kk<16;kk++){
            unsigned long long b2[4];
            #pragma unroll
            for (int p=0;p<4;p++)
                b2[p] = *(const unsigned long long*)&Xt[cb][kk][2*(tn + 16*p)];
            #pragma unroll
            for (int i=0;i<8;i++){
                unsigned long long a2 =
                    *(const unsigned long long*)&As2[cb][kk][tm*8+i];
                acc[i][0] = ffma2(a2, b2[0], acc[i][0]);
                acc[i][1] = ffma2(a2, b2[1], acc[i][1]);
                acc[i][2] = ffma2(a2, b2[2], acc[i][2]);
                acc[i][3] = ffma2(a2, b2[3], acc[i][3]);
            }
        }
        if (c + 1 < 48){
            float v[8] = {pa0.x,pa0.y,pa0.z,pa0.w,pa1.x,pa1.y,pa1.z,pa1.w};
            #pragma unroll
            for (int j=0;j<8;j++) As2[nb][akq+j][ar] = make_float2(v[j],v[j]);
            #pragma unroll
            for (int q=0;q<4;q++){
                Xt[nb][4*q+0][tid] = px[q].x;
                Xt[nb][4*q+1][tid] = px[q].y;
                Xt[nb][4*q+2][tid] = px[q].z;
                Xt[nb][4*q+3][tid] = px[q].w;
            }
        }
    }

    float* simb = &g_sim[(size_t)b*EE*EE];
    #pragma unroll
    for (int i=0;i<8;i++){
        int row = i0 + tm*8 + i;
        #pragma unroll
        for (int p=0;p<4;p++){
            F2U u; u.u = acc[i][p];
            *(float2*)&simb[row*EE + 2*(tn + 16*p)] = u.f;
        }
    }
}

// ============================================================================
// topk_kernel (unchanged)
// ============================================================================
__global__ __launch_bounds__(256) void topk_kernel()
{
    int w = threadIdx.x >> 5, lane = threadIdx.x & 31;
    int row = blockIdx.x*8 + w;
    int i = row & 127;
    const float* r = &g_sim[(size_t)row*EE];
    float v[4];
    #pragma unroll
    for (int q=0;q<4;q++) v[q] = r[lane + q*32];
    unsigned used = 0;
    int pick[6]; float pval[6];
    for (int k=0;k<6;k++){
        float bv = -1e30f; int bj = 128;
        #pragma unroll
        for (int q=0;q<4;q++){
            if (!((used>>q)&1u)){
                int j = lane + q*32;
                if (v[q] > bv){ bv = v[q]; bj = j; }
            }
        }
        #pragma unroll
        for (int off=16; off>0; off>>=1){
            float ov = __shfl_xor_sync(0xffffffffu, bv, off);
            int   oj = __shfl_xor_sync(0xffffffffu, bj, off);
            if (ov > bv || (ov == bv && oj < bj)){ bv = ov; bj = oj; }
        }
        pick[k]=bj; pval[k]=bv;
        if ((bj & 31) == lane) used |= 1u << (bj >> 5);
    }
    int jb = lane*4;
    unsigned char c0=0,c1=0,c2=0,c3=0;
    #pragma unroll
    for (int k=0;k<6;k++){
        if (pval[k] > 0.1f && pick[k] != i){
            int d = pick[k] - jb;
            if (d==0) c0=1; else if (d==1) c1=1; else if (d==2) c2=1; else if (d==3) c3=1;
        }
    }
    int ds = i - jb;
    if (ds>=0 && ds<4){ if(ds==0)c0=1; else if(ds==1)c1=1; else if(ds==2)c2=1; else c3=1; }
    *(uchar4*)&g_Adj[(size_t)row*EE + jb] = make_uchar4(c0,c1,c2,c3);
}

// ============================================================================
// sd1_kernel (unchanged)
// ============================================================================
__global__ __launch_bounds__(128) void sd1_kernel(const float* __restrict__ a_src,
                                                  const float* __restrict__ a_dst)
{
    int row = blockIdx.x;
    int hd = threadIdx.x >> 5, lane = threadIdx.x & 31;
    const float* hrow = &g_h1[(size_t)row*512 + hd*128];
    float ps = 0.f, pd = 0.f;
    #pragma unroll
    for (int q=0;q<4;q++){
        float hv = hrow[lane + 32*q];
        ps = fmaf(hv, a_src[hd*128 + lane + 32*q], ps);
        pd = fmaf(hv, a_dst[hd*128 + lane + 32*q], pd);
    }
    #pragma unroll
    for (int off=16;off>0;off>>=1){
        ps += __shfl_xor_sync(0xffffffffu,ps,off);
        pd += __shfl_xor_sync(0xffffffffu,pd,off);
    }
    if (lane==0){ g_s1[row*4+hd]=ps; g_d1[row*4+hd]=pd; }
}

// ============================================================================
// att1_kernel (unchanged)
// ============================================================================
__global__ __launch_bounds__(128) void att1_kernel(
    const float* __restrict__ b_g1, const float* __restrict__ gamma,
    const float* __restrict__ beta)
{
    __shared__ int act[EE];
    __shared__ int wcnt[4], woff[4];
    __shared__ int nact_s;
    __shared__ float wts[4][EE];
    __shared__ float red[4], red2[4];

    int be = blockIdx.x;
    int b = be / EE, t = be % EE;
    int tid = threadIdx.x, w = tid>>5, lane = tid&31;

    bool flag = g_Adj[(size_t)(b*EE + tid)*EE + t] != 0;
    unsigned mball = __ballot_sync(0xffffffffu, flag);
    if (lane==0) wcnt[w] = __popc(mball);
    __syncthreads();
    if (tid==0){ int o=0; for (int i2=0;i2<4;i2++){ woff[i2]=o; o+=wcnt[i2]; } nact_s=o; }
    __syncthreads();
    if (flag) act[woff[w] + __popc(mball & ((1u<<lane)-1u))] = tid;
    __syncthreads();
    int nact = nact_s;

    {
        int hd = w;
        float dv = g_d1[be*4 + hd];
        float mx = -1e30f;
        for (int k=lane;k<nact;k+=32){
            float e = g_s1[(b*EE+act[k])*4 + hd] + dv;
            e = e > 0.f ? e : 0.2f*e;
            wts[hd][k] = e;
            mx = fmaxf(mx, e);
        }
        #pragma unroll
        for (int off=16;off>0;off>>=1) mx = fmaxf(mx, __shfl_xor_sync(0xffffffffu,mx,off));
        float sum = 0.f;
        for (int k=lane;k<nact;k+=32){
            float e = expf(wts[hd][k]-mx);
            wts[hd][k] = e; sum += e;
        }
        #pragma unroll
        for (int off=16;off>0;off>>=1) sum += __shfl_xor_sync(0xffffffffu,sum,off);
        float inv = 1.f/sum;
        for (int k=lane;k<nact;k+=32) wts[hd][k] *= inv;
    }
    __syncthreads();

    float ov[4];
    #pragma unroll
    for (int q=0;q<4;q++){
        int f = tid + q*128;
        float o = 0.f;
        for (int k=0;k<nact;k++)
            o = fmaf(wts[q][k], g_h1[(size_t)(b*EE+act[k])*512 + f], o);
        ov[q] = o + b_g1[f];
    }
    float ls = ov[0]+ov[1]+ov[2]+ov[3];
    #pragma unroll
    for (int off=16;off>0;off>>=1) ls += __shfl_xor_sync(0xffffffffu,ls,off);
    if (lane==0) red[w] = ls;
    __syncthreads();
    float mean = (red[0]+red[1]+red[2]+red[3]) * (1.f/512.f);
    float lv = 0.f;
    #pragma unroll
    for (int q=0;q<4;q++){ float d = ov[q]-mean; lv = fmaf(d,d,lv); }
    #pragma unroll
    for (int off=16;off>0;off>>=1) lv += __shfl_xor_sync(0xffffffffu,lv,off);
    if (lane==0) red2[w] = lv;
    __syncthreads();
    float var = (red2[0]+red2[1]+red2[2]+red2[3]) * (1.f/512.f);
    float rstd = rsqrtf(var + 1e-5f);
    #pragma unroll
    for (int q=0;q<4;q++){
        int f = tid + q*128;
        float y = (ov[q]-mean)*rstd*gamma[f] + beta[f];
        y = y > 0.f ? y : expm1f(y);
        g_g1v[(size_t)be*512 + f] = y;
    }
}

// ============================================================================
// gat2h_kernel (unchanged)
// ============================================================================
__global__ __launch_bounds__(64) void gat2h_kernel(
    const float* __restrict__ Wg2, const float* __restrict__ a_src2,
    const float* __restrict__ a_dst2)
{
    __shared__ float grow[512];
    __shared__ float rs[2], rd[2];
    int row = blockIdx.x, tid = threadIdx.x;
    for (int i=tid;i<512;i+=64) grow[i] = g_g1v[(size_t)row*512 + i];
    __syncthreads();
    float acc = 0.f;
    for (int k=0;k<512;k++) acc = fmaf(grow[k], Wg2[k*64 + tid], acc);
    g_h2[(size_t)row*64 + tid] = acc;
    float ps = acc * a_src2[tid];
    float pd = acc * a_dst2[tid];
    #pragma unroll
    for (int off=16;off>0;off>>=1){
        ps += __shfl_xor_sync(0xffffffffu,ps,off);
        pd += __shfl_xor_sync(0xffffffffu,pd,off);
    }
    int w = tid>>5, lane = tid&31;
    if (lane==0){ rs[w]=ps; rd[w]=pd; }
    __syncthreads();
    if (tid==0){ g_s2[row]=rs[0]+rs[1]; g_d2[row]=rd[0]+rd[1]; }
}

// ============================================================================
// att2_kernel (unchanged)
// ============================================================================
__global__ __launch_bounds__(128) void att2_kernel(
    const float* __restrict__ b_g2, const float* __restrict__ gamma,
    const float* __restrict__ beta)
{
    __shared__ int act[EE];
    __shared__ int wcnt[4], woff[4];
    __shared__ int nact_s;
    __shared__ float wts[EE];
    __shared__ float red[2], red2[2];

    int be = blockIdx.x;
    int b = be / EE, t = be % EE;
    int tid = threadIdx.x, w = tid>>5, lane = tid&31;

    bool flag = g_Adj[(size_t)(b*EE + tid)*EE + t] != 0;
    unsigned mball = __ballot_sync(0xffffffffu, flag);
    if (lane==0) wcnt[w] = __popc(mball);
    __syncthreads();
    if (tid==0){ int o=0; for (int i2=0;i2<4;i2++){ woff[i2]=o; o+=wcnt[i2]; } nact_s=o; }
    __syncthreads();
    if (flag) act[woff[w] + __popc(mball & ((1u<<lane)-1u))] = tid;
    __syncthreads();
    int nact = nact_s;

    if (w == 0){
        float dv = g_d2[be];
        float mx = -1e30f;
        for (int k=lane;k<nact;k+=32){
            float e = g_s2[b*EE + act[k]] + dv;
            e = e > 0.f ? e : 0.2f*e;
            wts[k] = e;
            mx = fmaxf(mx, e);
        }
        #pragma unroll
        for (int off=16;off>0;off>>=1) mx = fmaxf(mx, __shfl_xor_sync(0xffffffffu,mx,off));
        float sum = 0.f;
        for (int k=lane;k<nact;k+=32){
            float e = expf(wts[k]-mx);
            wts[k] = e; sum += e;
        }
        #pragma unroll
        for (int off=16;off>0;off>>=1) sum += __shfl_xor_sync(0xffffffffu,sum,off);
        float inv = 1.f/sum;
        for (int k=lane;k<nact;k+=32) wts[k] *= inv;
    }
    __syncthreads();

    float o = 0.f;
    if (tid < 64){
        for (int k=0;k<nact;k++)
            o = fmaf(wts[k], g_h2[(size_t)(b*EE+act[k])*64 + tid], o);
        o += b_g2[tid];
    }
    float ls = (tid<64) ? o : 0.f;
    #pragma unroll
    for (int off=16;off>0;off>>=1) ls += __shfl_xor_sync(0xffffffffu,ls,off);
    if (w < 2 && lane==0) red[w] = ls;
    __syncthreads();
    float mean = (red[0]+red[1]) * (1.f/64.f);
    float dv2 = (tid<64) ? (o-mean) : 0.f;
    float lv = dv2*dv2;
    #pragma unroll
    for (int off=16;off>0;off>>=1) lv += __shfl_xor_sync(0xffffffffu,lv,off);
    if (w < 2 && lane==0) red2[w] = lv;
    __syncthreads();
    float var = (red2[0]+red2[1]) * (1.f/64.f);
    if (tid < 64){
        float y = (o-mean)*rsqrtf(var+1e-5f)*gamma[tid] + beta[tid];
        y = y > 0.f ? y : expm1f(y);
        g_ent[(size_t)be*64 + tid] = y;
    }
}

// ============================================================================
// cls / rp / pair (unchanged)
// ============================================================================
__global__ __launch_bounds__(256) void cls_kernel(const float* __restrict__ seq,
                                                  const float* __restrict__ W_r1,
                                                  const float* __restrict__ b_r1)
{
    __shared__ float c[HH];
    int b = blockIdx.x, tid = threadIdx.x;
    for (int d=tid; d<HH; d+=256) c[d] = seq[(size_t)b*SS*HH + d];
    __syncthreads();
    float acc = b_r1[tid];
    for (int d=0; d<HH; d++) acc = fmaf(c[d], W_r1[(160+d)*256 + tid], acc);
    g_clsp[b*256 + tid] = acc;
}

__global__ __launch_bounds__(256) void rp_kernel(const float* __restrict__ rel_emb,
                                                 const float* __restrict__ W_r1)
{
    __shared__ float re[32];
    int r = blockIdx.x, tid = threadIdx.x;
    if (tid < 32) re[tid] = rel_emb[r*32 + tid];
    __syncthreads();
    float s = 0.f;
    #pragma unroll 8
    for (int k=0;k<32;k++) s = fmaf(re[k], W_r1[(128+k)*256 + tid], s);
    g_Rp[r*256 + tid] = s;
}

__global__ __launch_bounds__(256) void pair_kernel(
    const int* __restrict__ pair_head, const int* __restrict__ pair_tail,
    const int* __restrict__ pair_rel,  const float* __restrict__ W_r2,
    const float* __restrict__ b_r2,    float* __restrict__ out)
{
    int w = threadIdx.x >> 5, lane = threadIdx.x & 31;
    int bp = blockIdx.x*8 + w;
    int b = bp >> 8;
    int h = pair_head[bp], t = pair_tail[bp], r = pair_rel[bp];
    const float* He = &g_He[(size_t)(b*EE+h)*256 + lane*8];
    const float* Te = &g_Te[(size_t)(b*EE+t)*256 + lane*8];
    const float* Rp = &g_Rp[r*256 + lane*8];
    const float* Cp = &g_clsp[b*256 + lane*8];
    float s = 0.f;
    #pragma unroll
    for (int q=0;q<2;q++){
        float4 a  = *(const float4*)(He + 4*q);
        float4 bb = *(const float4*)(Te + 4*q);
        float4 c  = *(const float4*)(Rp + 4*q);
        float4 d  = *(const float4*)(Cp + 4*q);
        float4 w4 = *(const float4*)&W_r2[lane*8 + 4*q];
        float h0 = fmaxf(a.x+bb.x+c.x+d.x, 0.f); s = fmaf(h0, w4.x, s);
        float h1 = fmaxf(a.y+bb.y+c.y+d.y, 0.f); s = fmaf(h1, w4.y, s);
        float h2 = fmaxf(a.z+bb.z+c.z+d.z, 0.f); s = fmaf(h2, w4.z, s);
        float h3 = fmaxf(a.w+bb.w+c.w+d.w, 0.f); s = fmaf(h3, w4.w, s);
    }
    #pragma unroll
    for (int off=16;off>0;off>>=1) s += __shfl_xor_sync(0xffffffffu,s,off);
    if (lane == 0) out[NER_TOTAL + bp] = s + b_r2[0];
}

// ============================================================================
extern "C" void kernel_launch(void* const* d_in, const int* in_sizes, int n_in,
                              void* d_out, int out_size)
{
    (void)in_sizes; (void)n_in; (void)out_size;
    const float* seq       = (const float*)d_in[0];
    const int*   span_start= (const int*)d_in[1];
    const int*   span_len  = (const int*)d_in[2];
    const int*   ent_type  = (const int*)d_in[3];
    const int*   pair_head = (const int*)d_in[4];
    const int*   pair_tail = (const int*)d_in[5];
    const int*   pair_rel  = (const int*)d_in[6];
    const float* W_ner1    = (const float*)d_in[7];
    const float* b_ner1    = (const float*)d_in[8];
    const float* W_ner2    = (const float*)d_in[9];
    const float* b_ner2    = (const float*)d_in[10];
    const float* type_emb  = (const float*)d_in[11];
    const float* W_g1      = (const float*)d_in[12];
    const float* a_src1    = (const float*)d_in[13];
    const float* a_dst1    = (const float*)d_in[14];
    const float* b_g1      = (const float*)d_in[15];
    const float* g1_gamma  = (const float*)d_in[16];
    const float* g1_beta   = (const float*)d_in[17];
    const float* W_g2      = (const float*)d_in[18];
    const float* a_src2    = (const float*)d_in[19];
    const float* a_dst2    = (const float*)d_in[20];
    const float* b_g2      = (const float*)d_in[21];
    const float* g2_gamma  = (const float*)d_in[22];
    const float* g2_beta   = (const float*)d_in[23];
    const float* rel_emb   = (const float*)d_in[24];
    const float* W_r1      = (const float*)d_in[25];
    const float* b_r1      = (const float*)d_in[26];
    const float* W_r2      = (const float*)d_in[27];
    const float* b_r2      = (const float*)d_in[28];
    float* out = (float*)d_out;

    static cudaStream_t sA = nullptr;
    static cudaEvent_t evRoot = nullptr, evT = nullptr, evA = nullptr;
    if (!sA){
        cudaStreamCreateWithFlags(&sA, cudaStreamNonBlocking);
        cudaEventCreateWithFlags(&evRoot, cudaEventDisableTiming);
        cudaEventCreateWithFlags(&evT, cudaEventDisableTiming);
        cudaEventCreateWithFlags(&evA, cudaEventDisableTiming);
    }

    __nv_bfloat16* seq_hi = nullptr; __nv_bfloat16* seq_lo = nullptr;
    __nv_bfloat16* w1h = nullptr; __nv_bfloat16* w1l = nullptr;
    __nv_bfloat16* wg1h = nullptr; __nv_bfloat16* wg1l = nullptr;
    __nv_bfloat16* xh = nullptr; __nv_bfloat16* xl = nullptr;
    cudaGetSymbolAddress((void**)&seq_hi, g_seq_hi);
    cudaGetSymbolAddress((void**)&seq_lo, g_seq_lo);
    cudaGetSymbolAddress((void**)&w1h,  g_W1t_hi);
    cudaGetSymbolAddress((void**)&w1l,  g_W1t_lo);
    cudaGetSymbolAddress((void**)&wg1h, g_Wg1t_hi);
    cudaGetSymbolAddress((void**)&wg1l, g_Wg1t_lo);
    cudaGetSymbolAddress((void**)&xh,   g_x_hi);
    cudaGetSymbolAddress((void**)&xl,   g_x_lo);
    float* hid = nullptr; float* h1 = nullptr;
    cudaGetSymbolAddress((void**)&hid, g_hid);
    cudaGetSymbolAddress((void**)&h1,  g_h1);

    cudaFuncSetAttribute((const void*)pool_kernel,
                         cudaFuncAttributeMaxDynamicSharedMemorySize, 65536);

    // ---- fork: weight/act splits + NER branch + cls/rp on side stream ----
    cudaEventRecord(evRoot, 0);
    cudaStreamWaitEvent(sA, evRoot, 0);
    tsplit_kernel<<<dim3(8,24),  dim3(32,8), 0, sA>>>(W_ner1, 256, w1h,  w1l);
    tsplit_kernel<<<dim3(16,24), dim3(32,8), 0, sA>>>(W_g1,   512, wg1h, wg1l);
    cudaEventRecord(evT, sA);
    presplit_kernel<<<(BB*SS*HH)/(256*8), 256, 0, sA>>>(seq, seq_hi, seq_lo);
    mma_direct<<<dim3((BB*SS)/128, 2), 256, 0, sA>>>(seq_hi, seq_lo, w1h, w1l,
                                                     hid, 256, b_ner1, 1);
    ner_head<<<(BB*SS)/8, 256, 0, sA>>>(W_ner2, b_ner2, out);
    cls_kernel<<<BB, 256, 0, sA>>>(seq, W_r1, b_r1);
    rp_kernel<<<9, 256, 0, sA>>>(rel_emb, W_r1);
    cudaEventRecord(evA, sA);

    // ---- main chain ----
    pool_kernel<<<BB*EE, 256, LL*HH*sizeof(float)>>>(seq, span_start, span_len,
                                                     ent_type, type_emb);
    sim_kernel<<<BB*2, 128>>>();
    topk_kernel<<<(BB*EE)/8, 256>>>();

    cudaStreamWaitEvent(0, evT, 0);
    mma_direct<<<dim3((BB*EE)/128, 4), 256>>>(xh, xl, wg1h, wg1l,
                                              h1, 512, nullptr, 0);
    sd1_kernel<<<BB*EE, 128>>>(a_src1, a_dst1);
    att1_kernel<<<BB*EE, 128>>>(b_g1, g1_gamma, g1_beta);

    gat2h_kernel<<<BB*EE, 64>>>(W_g2, a_src2, a_dst2);
    att2_kernel<<<BB*EE, 128>>>(b_g2, g2_gamma, g2_beta);

    gemm_kernel<<<dim3((BB*EE)/64, 2), 128>>>(2, W_r1,          256, 64);
    gemm_kernel<<<dim3((BB*EE)/64, 2), 128>>>(3, W_r1 + 64*256, 256, 64);

    cudaStreamWaitEvent(0, evA, 0);
    pair_kernel<<<(BB*PP)/8, 256>>>(pair_head, pair_tail, pair_rel,
                                    W_r2, b_r2, out);
}

// round 8
// speedup vs baseline: 2.0086x; 1.2675x over previous
#include <cuda_runtime.h>
#include <cuda_bf16.h>
#include <cstdint>
#include <math.h>

#define BB 48
#define SS 512
#define HH 768
#define EE 128
#define LL 16
#define PP 256
#define NERC 11
#define NER_TOTAL (BB*SS*NERC)   // 270336

// ---------------- scratch (device globals; no allocation allowed) -------------
__device__ __align__(16) float g_x  [BB*EE*HH];
__device__ __align__(16) float g_xn [BB*EE*HH];
__device__ __align__(16) float g_sim[BB*EE*EE];
__device__ unsigned char g_Adj[BB*EE*EE];
__device__ __align__(16) float g_h1 [BB*EE*512];
__device__ float g_s1 [BB*EE*4];
__device__ float g_d1 [BB*EE*4];
__device__ __align__(16) float g_g1v[BB*EE*512];
__device__ __align__(16) float g_h2 [BB*EE*64];
__device__ float g_s2 [BB*EE];
__device__ float g_d2 [BB*EE];
__device__ __align__(16) float g_ent[BB*EE*64];
__device__ __align__(16) float g_clsp[BB*256];
__device__ __align__(16) float g_hid[BB*SS*256];
__device__ __align__(16) float g_He [BB*EE*256];
__device__ __align__(16) float g_Te [BB*EE*256];
__device__ __align__(16) float g_Rp [9*256];
// packed mma fragments: uint4 per (tile16, kchunk, lane)
__device__ uint4 g_pSh[1536*48*32];   // seq A hi   (37.7 MB)
__device__ uint4 g_pSl[1536*48*32];   // seq A lo
__device__ uint4 g_pXh[384*48*32];    // x   A hi   (9.4 MB)
__device__ uint4 g_pXl[384*48*32];
__device__ uint4 g_pW1h[16*48*32];    // W_ner1^T B hi
__device__ uint4 g_pW1l[16*48*32];
__device__ uint4 g_pG1h[32*48*32];    // W_g1^T  B hi
__device__ uint4 g_pG1l[32*48*32];

// ---------------- helpers ----------------
__device__ __forceinline__ unsigned long long ffma2(unsigned long long a,
                                                    unsigned long long b,
                                                    unsigned long long c){
    unsigned long long d;
    asm("fma.rn.f32x2 %0, %1, %2, %3;" : "=l"(d) : "l"(a), "l"(b), "l"(c));
    return d;
}
union F2U { unsigned long long u; float2 f; };
__device__ __forceinline__ void cpa16(void* s, const void* g){
    unsigned sa = (unsigned)__cvta_generic_to_shared(s);
    asm volatile("cp.async.ca.shared.global [%0], [%1], 16;" :: "r"(sa), "l"(g));
}
__device__ __forceinline__ void mma16816(float* c, const unsigned* a, const unsigned* b){
    asm volatile("mma.sync.aligned.m16n8k16.row.col.f32.bf16.bf16.f32 "
        "{%0,%1,%2,%3}, {%4,%5,%6,%7}, {%8,%9}, {%0,%1,%2,%3};"
        : "+f"(c[0]), "+f"(c[1]), "+f"(c[2]), "+f"(c[3])
        : "r"(a[0]), "r"(a[1]), "r"(a[2]), "r"(a[3]), "r"(b[0]), "r"(b[1]));
}
// split (x,y) into bf16x2 hi word + bf16x2 lo-residual word (low 16 bits = x)
__device__ __forceinline__ void bsplit2(float x, float y, unsigned& h, unsigned& l){
    __nv_bfloat16 hx = __float2bfloat16(x);
    __nv_bfloat16 hy = __float2bfloat16(y);
    __nv_bfloat16 lx = __float2bfloat16(x - __bfloat162float(hx));
    __nv_bfloat16 ly = __float2bfloat16(y - __bfloat162float(hy));
    unsigned short ux = *(unsigned short*)&hx, uy = *(unsigned short*)&hy;
    unsigned short vx = *(unsigned short*)&lx, vy = *(unsigned short*)&ly;
    h = (unsigned)ux | ((unsigned)uy << 16);
    l = (unsigned)vx | ((unsigned)vy << 16);
}

// ============================================================================
// pack_a: fp32 A[M,768] -> packed fragment uint4 arrays (hi, lo).
// One warp per (tile16, kchunk) unit. Word order = mma A frag a0..a3.
// ============================================================================
__global__ __launch_bounds__(256) void pack_a(const float* __restrict__ A,
                                              uint4* __restrict__ oh,
                                              uint4* __restrict__ ol)
{
    int unit = blockIdx.x*8 + (threadIdx.x >> 5);
    int lane = threadIdx.x & 31;
    int tile = unit / 48, c = unit % 48;
    int g = lane >> 2, tg = lane & 3;
    const float* base = A + (size_t)tile*16*HH + c*16;
    float2 r0 = *(const float2*)(base + (size_t)g*HH + tg*2);
    float2 r1 = *(const float2*)(base + (size_t)(g+8)*HH + tg*2);
    float2 r2 = *(const float2*)(base + (size_t)g*HH + 8 + tg*2);
    float2 r3 = *(const float2*)(base + (size_t)(g+8)*HH + 8 + tg*2);
    uint4 H, L;
    bsplit2(r0.x, r0.y, H.x, L.x);
    bsplit2(r1.x, r1.y, H.y, L.y);
    bsplit2(r2.x, r2.y, H.z, L.z);
    bsplit2(r3.x, r3.y, H.w, L.w);
    size_t o = (size_t)unit*32 + lane;
    oh[o] = H; ol[o] = L;
}

// ============================================================================
// pack_b: fp32 W[768,N] (k-major) -> transposed packed B fragments.
// One warp per (n16-tile, kchunk). uint4 = {nt_even b0, nt_even b1, nt_odd b0, nt_odd b1}.
// ============================================================================
__global__ __launch_bounds__(256) void pack_b(const float* __restrict__ W, int N,
                                              uint4* __restrict__ oh,
                                              uint4* __restrict__ ol)
{
    int unit = blockIdx.x*8 + (threadIdx.x >> 5);
    int lane = threadIdx.x & 31;
    int nt = unit / 48, c = unit % 48;
    int g = lane >> 2, tg = lane & 3;
    const float* p = W + (size_t)(c*16)*N + nt*16;
    float x0 = p[(tg*2)*N + g],       x1 = p[(tg*2+1)*N + g];
    float x2 = p[(8+tg*2)*N + g],     x3 = p[(8+tg*2+1)*N + g];
    float x4 = p[(tg*2)*N + g+8],     x5 = p[(tg*2+1)*N + g+8];
    float x6 = p[(8+tg*2)*N + g+8],   x7 = p[(8+tg*2+1)*N + g+8];
    uint4 H, L;
    bsplit2(x0, x1, H.x, L.x);
    bsplit2(x2, x3, H.y, L.y);
    bsplit2(x4, x5, H.z, L.z);
    bsplit2(x6, x7, H.w, L.w);
    size_t o = (size_t)unit*32 + lane;
    oh[o] = H; ol[o] = L;
}

// ============================================================================
// mma_packed: C[M,N] = A @ B^T via packed fragments, 3-term bf16 hi/lo.
// 128x128 CTA, 8 warps (4m x 2n). 12 LDG.128/warp/chunk + 1-chunk reg prefetch.
// ============================================================================
__global__ __launch_bounds__(256) void mma_packed(
    const uint4* __restrict__ Ah, const uint4* __restrict__ Al,
    const uint4* __restrict__ Bh, const uint4* __restrict__ Bl,
    float* __restrict__ C, int N,
    const float* __restrict__ bias, int dorelu)
{
    int lane = threadIdx.x & 31, wid = threadIdx.x >> 5;
    int wm = wid & 3, wn = wid >> 2;
    int m0 = blockIdx.x*128, n0 = blockIdx.y*128;
    int g = lane >> 2, tg = lane & 3;

    float acc[2][8][4];
    #pragma unroll
    for (int mt=0;mt<2;mt++)
        #pragma unroll
        for (int nt=0;nt<8;nt++)
            #pragma unroll
            for (int q=0;q<4;q++) acc[mt][nt][q] = 0.f;

    const uint4* pAh[2]; const uint4* pAl[2];
    #pragma unroll
    for (int mt=0; mt<2; mt++){
        size_t t = (size_t)((m0>>4) + wm*2 + mt)*48*32 + lane;
        pAh[mt] = Ah + t; pAl[mt] = Al + t;
    }
    const uint4* pBh[4]; const uint4* pBl[4];
    #pragma unroll
    for (int j=0; j<4; j++){
        size_t t = (size_t)((n0>>4) + wn*4 + j)*48*32 + lane;
        pBh[j] = Bh + t; pBl[j] = Bl + t;
    }

    uint4 cAh[2], cAl[2], cBh[4], cBl[4];
    #pragma unroll
    for (int mt=0; mt<2; mt++){ cAh[mt] = pAh[mt][0]; cAl[mt] = pAl[mt][0]; }
    #pragma unroll
    for (int j=0; j<4; j++){ cBh[j] = pBh[j][0]; cBl[j] = pBl[j][0]; }

    for (int c = 0; c < 48; c++){
        uint4 nAh[2], nAl[2], nBh[4], nBl[4];
        if (c < 47){
            int o = (c+1)*32;
            #pragma unroll
            for (int mt=0; mt<2; mt++){ nAh[mt] = pAh[mt][o]; nAl[mt] = pAl[mt][o]; }
            #pragma unroll
            for (int j=0; j<4; j++){ nBh[j] = pBh[j][o]; nBl[j] = pBl[j][o]; }
        }
        #pragma unroll
        for (int mt=0; mt<2; mt++){
            unsigned aH[4] = {cAh[mt].x, cAh[mt].y, cAh[mt].z, cAh[mt].w};
            unsigned aL[4] = {cAl[mt].x, cAl[mt].y, cAl[mt].z, cAl[mt].w};
            #pragma unroll
            for (int j=0; j<4; j++){
                unsigned bHe[2] = {cBh[j].x, cBh[j].y};
                unsigned bHo[2] = {cBh[j].z, cBh[j].w};
                unsigned bLe[2] = {cBl[j].x, cBl[j].y};
                unsigned bLo[2] = {cBl[j].z, cBl[j].w};
                mma16816(acc[mt][2*j],   aH, bHe);
                mma16816(acc[mt][2*j],   aH, bLe);
                mma16816(acc[mt][2*j],   aL, bHe);
                mma16816(acc[mt][2*j+1], aH, bHo);
                mma16816(acc[mt][2*j+1], aH, bLo);
                mma16816(acc[mt][2*j+1], aL, bHo);
            }
        }
        if (c < 47){
            #pragma unroll
            for (int mt=0; mt<2; mt++){ cAh[mt] = nAh[mt]; cAl[mt] = nAl[mt]; }
            #pragma unroll
            for (int j=0; j<4; j++){ cBh[j] = nBh[j]; cBl[j] = nBl[j]; }
        }
    }

    #pragma unroll
    for (int mt=0; mt<2; mt++){
        int rbase = m0 + wm*32 + mt*16 + g;
        #pragma unroll
        for (int nt=0; nt<8; nt++){
            int col = n0 + wn*64 + nt*8 + tg*2;
            float b0 = 0.f, b1 = 0.f;
            if (bias){ b0 = bias[col]; b1 = bias[col+1]; }
            float v0 = acc[mt][nt][0] + b0, v1 = acc[mt][nt][1] + b1;
            float v2 = acc[mt][nt][2] + b0, v3 = acc[mt][nt][3] + b1;
            if (dorelu){
                v0 = fmaxf(v0,0.f); v1 = fmaxf(v1,0.f);
                v2 = fmaxf(v2,0.f); v3 = fmaxf(v3,0.f);
            }
            *(float2*)&C[(size_t)rbase*N + col]     = make_float2(v0, v1);
            *(float2*)&C[(size_t)(rbase+8)*N + col] = make_float2(v2, v3);
        }
    }
}

// ============================================================================
// Small-GEMM (He/Te): FFMA2, 64x128 tile.
// ============================================================================
__global__ __launch_bounds__(128, 3) void gemm_kernel(
    int sel, const float* __restrict__ B, int ldb, int K)
{
    __shared__ __align__(16) float2 As2[2][16][64];
    __shared__ __align__(16) float  Bs [2][16][128];

    const float* A = g_ent;
    float* C = (sel == 2) ? g_He : g_Te;

    int tid = threadIdx.x;
    int tm = tid >> 4, tn = tid & 15;
    int m0 = blockIdx.x * 64, n0 = blockIdx.y * 128;
    int nch = K >> 4;

    unsigned long long acc[8][4];
    #pragma unroll
    for (int i=0;i<8;i++)
        #pragma unroll
        for (int p=0;p<4;p++) acc[i][p] = 0ull;

    int lr = tid >> 1, lc8 = (tid & 1) * 8;
    const float* aP = A + (size_t)(m0 + lr) * K + lc8;
    int bkk[4], bc4[4];
    #pragma unroll
    for (int i=0;i<4;i++){ int q = i*128 + tid; bkk[i] = q >> 5; bc4[i] = (q & 31) * 4; }

    float4 pa0, pa1;
    pa0 = *(const float4*)(aP);
    pa1 = *(const float4*)(aP + 4);
    #pragma unroll
    for (int i=0;i<4;i++)
        cpa16(&Bs[0][bkk[i]][bc4[i]], B + (size_t)bkk[i]*ldb + n0 + bc4[i]);
    asm volatile("cp.async.commit_group;");
    {
        float v[8] = {pa0.x,pa0.y,pa0.z,pa0.w,pa1.x,pa1.y,pa1.z,pa1.w};
        #pragma unroll
        for (int j=0;j<8;j++) As2[0][lc8+j][lr] = make_float2(v[j],v[j]);
    }

    for (int c = 0; c < nch; c++){
        int cb = c & 1, nb = cb ^ 1;
        if (c + 1 < nch){
            int k0n = (c+1)*16;
            pa0 = *(const float4*)(aP + k0n);
            pa1 = *(const float4*)(aP + k0n + 4);
            #pragma unroll
            for (int i=0;i<4;i++)
                cpa16(&Bs[nb][bkk[i]][bc4[i]],
                      B + (size_t)(k0n + bkk[i])*ldb + n0 + bc4[i]);
            asm volatile("cp.async.commit_group;");
            asm volatile("cp.async.wait_group 1;");
        } else {
            asm volatile("cp.async.wait_group 0;");
        }
        __syncthreads();
        #pragma unroll
        for (int kk=0;kk<16;kk++){
            unsigned long long b2[4];
            #pragma unroll
            for (int p=0;p<4;p++)
                b2[p] = *(const unsigned long long*)&Bs[cb][kk][2*(tn + 16*p)];
            #pragma unroll
            for (int i=0;i<8;i++){
                unsigned long long a2 =
                    *(const unsigned long long*)&As2[cb][kk][tm*8+i];
                acc[i][0] = ffma2(a2, b2[0], acc[i][0]);
                acc[i][1] = ffma2(a2, b2[1], acc[i][1]);
                acc[i][2] = ffma2(a2, b2[2], acc[i][2]);
                acc[i][3] = ffma2(a2, b2[3], acc[i][3]);
            }
        }
        __syncthreads();
        if (c + 1 < nch){
            float v[8] = {pa0.x,pa0.y,pa0.z,pa0.w,pa1.x,pa1.y,pa1.z,pa1.w};
            #pragma unroll
            for (int j=0;j<8;j++) As2[nb][lc8+j][lr] = make_float2(v[j],v[j]);
        }
    }

    #pragma unroll
    for (int i=0;i<8;i++){
        size_t row = m0 + tm*8 + i;
        #pragma unroll
        for (int p=0;p<4;p++){
            F2U u; u.u = acc[i][p];
            *(float2*)&C[row*ldb + n0 + 32*p + 2*tn] = u.f;
        }
    }
}

// ============================================================================
// ner_head: out = g_hid @ W2 + b2.  Warp per row, 8 rows/block.
// ============================================================================
__global__ __launch_bounds__(256) void ner_head(
    const float* __restrict__ W2, const float* __restrict__ b2,
    float* __restrict__ out)
{
    __shared__ float W2t[NERC][256];
    __shared__ float b2s[NERC];
    int tid = threadIdx.x;
    for (int i = tid; i < 256*NERC; i += 256){
        int c = i / NERC, jo = i % NERC;
        W2t[jo][c] = W2[i];
    }
    if (tid < NERC) b2s[tid] = b2[tid];
    __syncthreads();
    int w = tid >> 5, lane = tid & 31;
    int row = blockIdx.x*8 + w;
    const float* hr = &g_hid[(size_t)row*256 + lane*8];
    float4 v0 = *(const float4*)hr;
    float4 v1 = *(const float4*)(hr + 4);
    #pragma unroll
    for (int jo = 0; jo < NERC; jo++){
        const float* wr = &W2t[jo][lane*8];
        float4 w0 = *(const float4*)wr;
        float4 w1 = *(const float4*)(wr + 4);
        float p = 0.f;
        p = fmaf(v0.x, w0.x, p); p = fmaf(v0.y, w0.y, p);
        p = fmaf(v0.z, w0.z, p); p = fmaf(v0.w, w0.w, p);
        p = fmaf(v1.x, w1.x, p); p = fmaf(v1.y, w1.y, p);
        p = fmaf(v1.z, w1.z, p); p = fmaf(v1.w, w1.w, p);
        #pragma unroll
        for (int off=16;off>0;off>>=1) p += __shfl_xor_sync(0xffffffffu,p,off);
        if (lane == 0) out[row*NERC + jo] = p + b2s[jo];
    }
}

// ============================================================================
// pool_kernel (fp32 only; packing of g_x handled by pack_a afterwards)
// ============================================================================
__global__ __launch_bounds__(256) void pool_kernel(
    const float* __restrict__ seq, const int* __restrict__ span_start,
    const int* __restrict__ span_len, const int* __restrict__ ent_type,
    const float* __restrict__ type_emb)
{
    extern __shared__ float tok[];
    __shared__ float meanv[HH];
    __shared__ float sc[LL];
    __shared__ float wv[LL];
    __shared__ float red[8];

    int be = blockIdx.x;
    int b = be / EE;
    int tid = threadIdx.x;
    int start = span_start[be];
    int len = span_len[be];
    float cnt = (float)(len + 1);

    const float4* src = (const float4*)&seq[(size_t)(b*SS + start)*HH];
    float4* dst4 = (float4*)tok;
    for (int q = tid; q < LL*HH/4; q += 256) dst4[q] = src[q];
    __syncthreads();

    for (int d = tid; d < HH; d += 256){
        float s = 0.f;
        for (int l = 0; l <= len; l++) s += tok[l*HH + d];
        meanv[d] = s / cnt;
    }
    __syncthreads();

    int w = tid >> 5, lane = tid & 31;
    for (int l = w; l < LL; l += 8){
        float p = 0.f;
        for (int d = lane; d < HH; d += 32) p = fmaf(tok[l*HH+d], meanv[d], p);
        #pragma unroll
        for (int off=16;off>0;off>>=1) p += __shfl_xor_sync(0xffffffffu,p,off);
        if (lane==0) sc[l] = p;
    }
    __syncthreads();

    if (tid == 0){
        float mx = -1e30f;
        for (int l=0;l<=len;l++) mx = fmaxf(mx, sc[l]);
        float s = 0.f;
        for (int l=0;l<=len;l++){ float e = expf(sc[l]-mx); wv[l]=e; s+=e; }
        float inv = 1.f/s;
        for (int l=0;l<=len;l++) wv[l] *= inv;
        for (int l=len+1;l<LL;l++) wv[l] = 0.f;
    }
    __syncthreads();

    const float* te = &type_emb[ent_type[be]*HH];
    float xv[3]; float nsq = 0.f;
    #pragma unroll
    for (int q = 0; q < 3; q++){
        int d = tid + q*256;
        float p = 0.f;
        for (int l = 0; l <= len; l++) p = fmaf(wv[l], tok[l*HH+d], p);
        float v = p + te[d];
        xv[q] = v;
        g_x[(size_t)be*HH + d] = v;
        nsq = fmaf(v, v, nsq);
    }
    #pragma unroll
    for (int off=16;off>0;off>>=1) nsq += __shfl_xor_sync(0xffffffffu,nsq,off);
    if (lane==0) red[w] = nsq;
    __syncthreads();
    float tot = 0.f;
    #pragma unroll
    for (int i=0;i<8;i++) tot += red[i];
    float inv = 1.f / fmaxf(sqrtf(tot), 1e-12f);
    #pragma unroll
    for (int q=0;q<3;q++){
        int d = tid + q*256;
        g_xn[(size_t)be*HH + d] = xv[q]*inv;
    }
}

// ============================================================================
// sim_kernel (FFMA2, unchanged)
// ============================================================================
__global__ __launch_bounds__(128) void sim_kernel()
{
    __shared__ __align__(16) float2 As2[2][16][64];
    __shared__ float Xt[2][16][132];

    int b = blockIdx.x >> 1;
    int i0 = (blockIdx.x & 1) * 64;
    const float* X = &g_xn[(size_t)b*EE*HH];
    int tid = threadIdx.x;
    int tm = tid >> 4, tn = tid & 15;

    unsigned long long acc[8][4];
    #pragma unroll
    for (int i=0;i<8;i++)
        #pragma unroll
        for (int p=0;p<4;p++) acc[i][p] = 0ull;

    int ar = tid >> 1, akq = (tid & 1) * 8;
    const float* aP = X + (size_t)(i0 + ar)*HH + akq;
    const float* xP = X + (size_t)tid*HH;

    float4 pa0, pa1, px[4];
    pa0 = *(const float4*)(aP);
    pa1 = *(const float4*)(aP + 4);
    #pragma unroll
    for (int q=0;q<4;q++) px[q] = *(const float4*)(xP + 4*q);
    {
        float v[8] = {pa0.x,pa0.y,pa0.z,pa0.w,pa1.x,pa1.y,pa1.z,pa1.w};
        #pragma unroll
        for (int j=0;j<8;j++) As2[0][akq+j][ar] = make_float2(v[j],v[j]);
        #pragma unroll
        for (int q=0;q<4;q++){
            Xt[0][4*q+0][tid] = px[q].x;
            Xt[0][4*q+1][tid] = px[q].y;
            Xt[0][4*q+2][tid] = px[q].z;
            Xt[0][4*q+3][tid] = px[q].w;
        }
    }

    for (int c = 0; c < 48; c++){
        int cb = c & 1, nb = cb ^ 1;
        __syncthreads();
        if (c + 1 < 48){
            int k0n = (c+1)*16;
            pa0 = *(const float4*)(aP + k0n);
            pa1 = *(const float4*)(aP + k0n + 4);
            #pragma unroll
            for (int q=0;q<4;q++) px[q] = *(const float4*)(xP + k0n + 4*q);
        }
        #pragma unroll
        for (int kk=0;kk<16;kk++){
            unsigned long long b2[4];
            #pragma unroll
            for (int p=0;p<4;p++)
                b2[p] = *(const unsigned long long*)&Xt[cb][kk][2*(tn + 16*p)];
            #pragma unroll
            for (int i=0;i<8;i++){
                unsigned long long a2 =
                    *(const unsigned long long*)&As2[cb][kk][tm*8+i];
                acc[i][0] = ffma2(a2, b2[0], acc[i][0]);
                acc[i][1] = ffma2(a2, b2[1], acc[i][1]);
                acc[i][2] = ffma2(a2, b2[2], acc[i][2]);
                acc[i][3] = ffma2(a2, b2[3], acc[i][3]);
            }
        }
        if (c + 1 < 48){
            float v[8] = {pa0.x,pa0.y,pa0.z,pa0.w,pa1.x,pa1.y,pa1.z,pa1.w};
            #pragma unroll
            for (int j=0;j<8;j++) As2[nb][akq+j][ar] = make_float2(v[j],v[j]);
            #pragma unroll
            for (int q=0;q<4;q++){
                Xt[nb][4*q+0][tid] = px[q].x;
                Xt[nb][4*q+1][tid] = px[q].y;
                Xt[nb][4*q+2][tid] = px[q].z;
                Xt[nb][4*q+3][tid] = px[q].w;
            }
        }
    }

    float* simb = &g_sim[(size_t)b*EE*EE];
    #pragma unroll
    for (int i=0;i<8;i++){
        int row = i0 + tm*8 + i;
        #pragma unroll
        for (int p=0;p<4;p++){
            F2U u; u.u = acc[i][p];
            *(float2*)&simb[row*EE + 2*(tn + 16*p)] = u.f;
        }
    }
}

// ============================================================================
// topk_kernel (unchanged)
// ============================================================================
__global__ __launch_bounds__(256) void topk_kernel()
{
    int w = threadIdx.x >> 5, lane = threadIdx.x & 31;
    int row = blockIdx.x*8 + w;
    int i = row & 127;
    const float* r = &g_sim[(size_t)row*EE];
    float v[4];
    #pragma unroll
    for (int q=0;q<4;q++) v[q] = r[lane + q*32];
    unsigned used = 0;
    int pick[6]; float pval[6];
    for (int k=0;k<6;k++){
        float bv = -1e30f; int bj = 128;
        #pragma unroll
        for (int q=0;q<4;q++){
            if (!((used>>q)&1u)){
                int j = lane + q*32;
                if (v[q] > bv){ bv = v[q]; bj = j; }
            }
        }
        #pragma unroll
        for (int off=16; off>0; off>>=1){
            float ov = __shfl_xor_sync(0xffffffffu, bv, off);
            int   oj = __shfl_xor_sync(0xffffffffu, bj, off);
            if (ov > bv || (ov == bv && oj < bj)){ bv = ov; bj = oj; }
        }
        pick[k]=bj; pval[k]=bv;
        if ((bj & 31) == lane) used |= 1u << (bj >> 5);
    }
    int jb = lane*4;
    unsigned char c0=0,c1=0,c2=0,c3=0;
    #pragma unroll
    for (int k=0;k<6;k++){
        if (pval[k] > 0.1f && pick[k] != i){
            int d = pick[k] - jb;
            if (d==0) c0=1; else if (d==1) c1=1; else if (d==2) c2=1; else if (d==3) c3=1;
        }
    }
    int ds = i - jb;
    if (ds>=0 && ds<4){ if(ds==0)c0=1; else if(ds==1)c1=1; else if(ds==2)c2=1; else c3=1; }
    *(uchar4*)&g_Adj[(size_t)row*EE + jb] = make_uchar4(c0,c1,c2,c3);
}

// ============================================================================
// sd1_kernel (unchanged)
// ============================================================================
__global__ __launch_bounds__(128) void sd1_kernel(const float* __restrict__ a_src,
                                                  const float* __restrict__ a_dst)
{
    int row = blockIdx.x;
    int hd = threadIdx.x >> 5, lane = threadIdx.x & 31;
    const float* hrow = &g_h1[(size_t)row*512 + hd*128];
    float ps = 0.f, pd = 0.f;
    #pragma unroll
    for (int q=0;q<4;q++){
        float hv = hrow[lane + 32*q];
        ps = fmaf(hv, a_src[hd*128 + lane + 32*q], ps);
        pd = fmaf(hv, a_dst[hd*128 + lane + 32*q], pd);
    }
    #pragma unroll
    for (int off=16;off>0;off>>=1){
        ps += __shfl_xor_sync(0xffffffffu,ps,off);
        pd += __shfl_xor_sync(0xffffffffu,pd,off);
    }
    if (lane==0){ g_s1[row*4+hd]=ps; g_d1[row*4+hd]=pd; }
}

// ============================================================================
// att1_kernel (unchanged)
// ============================================================================
__global__ __launch_bounds__(128) void att1_kernel(
    const float* __restrict__ b_g1, const float* __restrict__ gamma,
    const float* __restrict__ beta)
{
    __shared__ int act[EE];
    __shared__ int wcnt[4], woff[4];
    __shared__ int nact_s;
    __shared__ float wts[4][EE];
    __shared__ float red[4], red2[4];

    int be = blockIdx.x;
    int b = be / EE, t = be % EE;
    int tid = threadIdx.x, w = tid>>5, lane = tid&31;

    bool flag = g_Adj[(size_t)(b*EE + tid)*EE + t] != 0;
    unsigned mball = __ballot_sync(0xffffffffu, flag);
    if (lane==0) wcnt[w] = __popc(mball);
    __syncthreads();
    if (tid==0){ int o=0; for (int i2=0;i2<4;i2++){ woff[i2]=o; o+=wcnt[i2]; } nact_s=o; }
    __syncthreads();
    if (flag) act[woff[w] + __popc(mball & ((1u<<lane)-1u))] = tid;
    __syncthreads();
    int nact = nact_s;

    {
        int hd = w;
        float dv = g_d1[be*4 + hd];
        float mx = -1e30f;
        for (int k=lane;k<nact;k+=32){
            float e = g_s1[(b*EE+act[k])*4 + hd] + dv;
            e = e > 0.f ? e : 0.2f*e;
            wts[hd][k] = e;
            mx = fmaxf(mx, e);
        }
        #pragma unroll
        for (int off=16;off>0;off>>=1) mx = fmaxf(mx, __shfl_xor_sync(0xffffffffu,mx,off));
        float sum = 0.f;
        for (int k=lane;k<nact;k+=32){
            float e = expf(wts[hd][k]-mx);
            wts[hd][k] = e; sum += e;
        }
        #pragma unroll
        for (int off=16;off>0;off>>=1) sum += __shfl_xor_sync(0xffffffffu,sum,off);
        float inv = 1.f/sum;
        for (int k=lane;k<nact;k+=32) wts[hd][k] *= inv;
    }
    __syncthreads();

    float ov[4];
    #pragma unroll
    for (int q=0;q<4;q++){
        int f = tid + q*128;
        float o = 0.f;
        for (int k=0;k<nact;k++)
            o = fmaf(wts[q][k], g_h1[(size_t)(b*EE+act[k])*512 + f], o);
        ov[q] = o + b_g1[f];
    }
    float ls = ov[0]+ov[1]+ov[2]+ov[3];
    #pragma unroll
    for (int off=16;off>0;off>>=1) ls += __shfl_xor_sync(0xffffffffu,ls,off);
    if (lane==0) red[w] = ls;
    __syncthreads();
    float mean = (red[0]+red[1]+red[2]+red[3]) * (1.f/512.f);
    float lv = 0.f;
    #pragma unroll
    for (int q=0;q<4;q++){ float d = ov[q]-mean; lv = fmaf(d,d,lv); }
    #pragma unroll
    for (int off=16;off>0;off>>=1) lv += __shfl_xor_sync(0xffffffffu,lv,off);
    if (lane==0) red2[w] = lv;
    __syncthreads();
    float var = (red2[0]+red2[1]+red2[2]+red2[3]) * (1.f/512.f);
    float rstd = rsqrtf(var + 1e-5f);
    #pragma unroll
    for (int q=0;q<4;q++){
        int f = tid + q*128;
        float y = (ov[q]-mean)*rstd*gamma[f] + beta[f];
        y = y > 0.f ? y : expm1f(y);
        g_g1v[(size_t)be*512 + f] = y;
    }
}

// ============================================================================
// gat2h_kernel (unchanged)
// ============================================================================
__global__ __launch_bounds__(64) void gat2h_kernel(
    const float* __restrict__ Wg2, const float* __restrict__ a_src2,
    const float* __restrict__ a_dst2)
{
    __shared__ float grow[512];
    __shared__ float rs[2], rd[2];
    int row = blockIdx.x, tid = threadIdx.x;
    for (int i=tid;i<512;i+=64) grow[i] = g_g1v[(size_t)row*512 + i];
    __syncthreads();
    float acc = 0.f;
    for (int k=0;k<512;k++) acc = fmaf(grow[k], Wg2[k*64 + tid], acc);
    g_h2[(size_t)row*64 + tid] = acc;
    float ps = acc * a_src2[tid];
    float pd = acc * a_dst2[tid];
    #pragma unroll
    for (int off=16;off>0;off>>=1){
        ps += __shfl_xor_sync(0xffffffffu,ps,off);
        pd += __shfl_xor_sync(0xffffffffu,pd,off);
    }
    int w = tid>>5, lane = tid&31;
    if (lane==0){ rs[w]=ps; rd[w]=pd; }
    __syncthreads();
    if (tid==0){ g_s2[row]=rs[0]+rs[1]; g_d2[row]=rd[0]+rd[1]; }
}

// ============================================================================
// att2_kernel (unchanged)
// ============================================================================
__global__ __launch_bounds__(128) void att2_kernel(
    const float* __restrict__ b_g2, const float* __restrict__ gamma,
    const float* __restrict__ beta)
{
    __shared__ int act[EE];
    __shared__ int wcnt[4], woff[4];
    __shared__ int nact_s;
    __shared__ float wts[EE];
    __shared__ float red[2], red2[2];

    int be = blockIdx.x;
    int b = be / EE, t = be % EE;
    int tid = threadIdx.x, w = tid>>5, lane = tid&31;

    bool flag = g_Adj[(size_t)(b*EE + tid)*EE + t] != 0;
    unsigned mball = __ballot_sync(0xffffffffu, flag);
    if (lane==0) wcnt[w] = __popc(mball);
    __syncthreads();
    if (tid==0){ int o=0; for (int i2=0;i2<4;i2++){ woff[i2]=o; o+=wcnt[i2]; } nact_s=o; }
    __syncthreads();
    if (flag) act[woff[w] + __popc(mball & ((1u<<lane)-1u))] = tid;
    __syncthreads();
    int nact = nact_s;

    if (w == 0){
        float dv = g_d2[be];
        float mx = -1e30f;
        for (int k=lane;k<nact;k+=32){
            float e = g_s2[b*EE + act[k]] + dv;
            e = e > 0.f ? e : 0.2f*e;
            wts[k] = e;
            mx = fmaxf(mx, e);
        }
        #pragma unroll
        for (int off=16;off>0;off>>=1) mx = fmaxf(mx, __shfl_xor_sync(0xffffffffu,mx,off));
        float sum = 0.f;
        for (int k=lane;k<nact;k+=32){
            float e = expf(wts[k]-mx);
            wts[k] = e; sum += e;
        }
        #pragma unroll
        for (int off=16;off>0;off>>=1) sum += __shfl_xor_sync(0xffffffffu,sum,off);
        float inv = 1.f/sum;
        for (int k=lane;k<nact;k+=32) wts[k] *= inv;
    }
    __syncthreads();

    float o = 0.f;
    if (tid < 64){
        for (int k=0;k<nact;k++)
            o = fmaf(wts[k], g_h2[(size_t)(b*EE+act[k])*64 + tid], o);
        o += b_g2[tid];
    }
    float ls = (tid<64) ? o : 0.f;
    #pragma unroll
    for (int off=16;off>0;off>>=1) ls += __shfl_xor_sync(0xffffffffu,ls,off);
    if (w < 2 && lane==0) red[w] = ls;
    __syncthreads();
    float mean = (red[0]+red[1]) * (1.f/64.f);
    float dv2 = (tid<64) ? (o-mean) : 0.f;
    float lv = dv2*dv2;
    #pragma unroll
    for (int off=16;off>0;off>>=1) lv += __shfl_xor_sync(0xffffffffu,lv,off);
    if (w < 2 && lane==0) red2[w] = lv;
    __syncthreads();
    float var = (red2[0]+red2[1]) * (1.f/64.f);
    if (tid < 64){
        float y = (o-mean)*rsqrtf(var+1e-5f)*gamma[tid] + beta[tid];
        y = y > 0.f ? y : expm1f(y);
        g_ent[(size_t)be*64 + tid] = y;
    }
}

// ============================================================================
// cls / rp / pair (unchanged)
// ============================================================================
__global__ __launch_bounds__(256) void cls_kernel(const float* __restrict__ seq,
                                                  const float* __restrict__ W_r1,
                                                  const float* __restrict__ b_r1)
{
    __shared__ float c[HH];
    int b = blockIdx.x, tid = threadIdx.x;
    for (int d=tid; d<HH; d+=256) c[d] = seq[(size_t)b*SS*HH + d];
    __syncthreads();
    float acc = b_r1[tid];
    for (int d=0; d<HH; d++) acc = fmaf(c[d], W_r1[(160+d)*256 + tid], acc);
    g_clsp[b*256 + tid] = acc;
}

__global__ __launch_bounds__(256) void rp_kernel(const float* __restrict__ rel_emb,
                                                 const float* __restrict__ W_r1)
{
    __shared__ float re[32];
    int r = blockIdx.x, tid = threadIdx.x;
    if (tid < 32) re[tid] = rel_emb[r*32 + tid];
    __syncthreads();
    float s = 0.f;
    #pragma unroll 8
    for (int k=0;k<32;k++) s = fmaf(re[k], W_r1[(128+k)*256 + tid], s);
    g_Rp[r*256 + tid] = s;
}

__global__ __launch_bounds__(256) void pair_kernel(
    const int* __restrict__ pair_head, const int* __restrict__ pair_tail,
    const int* __restrict__ pair_rel,  const float* __restrict__ W_r2,
    const float* __restrict__ b_r2,    float* __restrict__ out)
{
    int w = threadIdx.x >> 5, lane = threadIdx.x & 31;
    int bp = blockIdx.x*8 + w;
    int b = bp >> 8;
    int h = pair_head[bp], t = pair_tail[bp], r = pair_rel[bp];
    const float* He = &g_He[(size_t)(b*EE+h)*256 + lane*8];
    const float* Te = &g_Te[(size_t)(b*EE+t)*256 + lane*8];
    const float* Rp = &g_Rp[r*256 + lane*8];
    const float* Cp = &g_clsp[b*256 + lane*8];
    float s = 0.f;
    #pragma unroll
    for (int q=0;q<2;q++){
        float4 a  = *(const float4*)(He + 4*q);
        float4 bb = *(const float4*)(Te + 4*q);
        float4 c  = *(const float4*)(Rp + 4*q);
        float4 d  = *(const float4*)(Cp + 4*q);
        float4 w4 = *(const float4*)&W_r2[lane*8 + 4*q];
        float h0 = fmaxf(a.x+bb.x+c.x+d.x, 0.f); s = fmaf(h0, w4.x, s);
        float h1 = fmaxf(a.y+bb.y+c.y+d.y, 0.f); s = fmaf(h1, w4.y, s);
        float h2 = fmaxf(a.z+bb.z+c.z+d.z, 0.f); s = fmaf(h2, w4.z, s);
        float h3 = fmaxf(a.w+bb.w+c.w+d.w, 0.f); s = fmaf(h3, w4.w, s);
    }
    #pragma unroll
    for (int off=16;off>0;off>>=1) s += __shfl_xor_sync(0xffffffffu,s,off);
    if (lane == 0) out[NER_TOTAL + bp] = s + b_r2[0];
}

// ============================================================================
extern "C" void kernel_launch(void* const* d_in, const int* in_sizes, int n_in,
                              void* d_out, int out_size)
{
    (void)in_sizes; (void)n_in; (void)out_size;
    const float* seq       = (const float*)d_in[0];
    const int*   span_start= (const int*)d_in[1];
    const int*   span_len  = (const int*)d_in[2];
    const int*   ent_type  = (const int*)d_in[3];
    const int*   pair_head = (const int*)d_in[4];
    const int*   pair_tail = (const int*)d_in[5];
    const int*   pair_rel  = (const int*)d_in[6];
    const float* W_ner1    = (const float*)d_in[7];
    const float* b_ner1    = (const float*)d_in[8];
    const float* W_ner2    = (const float*)d_in[9];
    const float* b_ner2    = (const float*)d_in[10];
    const float* type_emb  = (const float*)d_in[11];
    const float* W_g1      = (const float*)d_in[12];
    const float* a_src1    = (const float*)d_in[13];
    const float* a_dst1    = (const float*)d_in[14];
    const float* b_g1      = (const float*)d_in[15];
    const float* g1_gamma  = (const float*)d_in[16];
    const float* g1_beta   = (const float*)d_in[17];
    const float* W_g2      = (const float*)d_in[18];
    const float* a_src2    = (const float*)d_in[19];
    const float* a_dst2    = (const float*)d_in[20];
    const float* b_g2      = (const float*)d_in[21];
    const float* g2_gamma  = (const float*)d_in[22];
    const float* g2_beta   = (const float*)d_in[23];
    const float* rel_emb   = (const float*)d_in[24];
    const float* W_r1      = (const float*)d_in[25];
    const float* b_r1      = (const float*)d_in[26];
    const float* W_r2      = (const float*)d_in[27];
    const float* b_r2      = (const float*)d_in[28];
    float* out = (float*)d_out;

    static cudaStream_t sA = nullptr;
    static cudaEvent_t evRoot = nullptr, evT = nullptr, evA = nullptr;
    if (!sA){
        cudaStreamCreateWithFlags(&sA, cudaStreamNonBlocking);
        cudaEventCreateWithFlags(&evRoot, cudaEventDisableTiming);
        cudaEventCreateWithFlags(&evT, cudaEventDisableTiming);
        cudaEventCreateWithFlags(&evA, cudaEventDisableTiming);
    }

    uint4 *pSh, *pSl, *pXh, *pXl, *pW1h, *pW1l, *pG1h, *pG1l;
    cudaGetSymbolAddress((void**)&pSh,  g_pSh);
    cudaGetSymbolAddress((void**)&pSl,  g_pSl);
    cudaGetSymbolAddress((void**)&pXh,  g_pXh);
    cudaGetSymbolAddress((void**)&pXl,  g_pXl);
    cudaGetSymbolAddress((void**)&pW1h, g_pW1h);
    cudaGetSymbolAddress((void**)&pW1l, g_pW1l);
    cudaGetSymbolAddress((void**)&pG1h, g_pG1h);
    cudaGetSymbolAddress((void**)&pG1l, g_pG1l);
    float *hid, *h1, *xsrc;
    cudaGetSymbolAddress((void**)&hid,  g_hid);
    cudaGetSymbolAddress((void**)&h1,   g_h1);
    cudaGetSymbolAddress((void**)&xsrc, g_x);

    cudaFuncSetAttribute((const void*)pool_kernel,
                         cudaFuncAttributeMaxDynamicSharedMemorySize, 65536);

    // ---- fork: weight packs + NER branch + cls/rp on side stream ----
    cudaEventRecord(evRoot, 0);
    cudaStreamWaitEvent(sA, evRoot, 0);
    pack_b<<<96, 256, 0, sA>>>(W_ner1, 256, pW1h, pW1l);
    pack_b<<<192, 256, 0, sA>>>(W_g1, 512, pG1h, pG1l);
    cudaEventRecord(evT, sA);
    pack_a<<<(1536*48)/8, 256, 0, sA>>>(seq, pSh, pSl);
    mma_packed<<<dim3((BB*SS)/128, 2), 256, 0, sA>>>(pSh, pSl, pW1h, pW1l,
                                                     hid, 256, b_ner1, 1);
    ner_head<<<(BB*SS)/8, 256, 0, sA>>>(W_ner2, b_ner2, out);
    cls_kernel<<<BB, 256, 0, sA>>>(seq, W_r1, b_r1);
    rp_kernel<<<9, 256, 0, sA>>>(rel_emb, W_r1);
    cudaEventRecord(evA, sA);

    // ---- main chain ----
    pool_kernel<<<BB*EE, 256, LL*HH*sizeof(float)>>>(seq, span_start, span_len,
                                                     ent_type, type_emb);
    pack_a<<<(384*48)/8, 256>>>(xsrc, pXh, pXl);
    sim_kernel<<<BB*2, 128>>>();
    topk_kernel<<<(BB*EE)/8, 256>>>();

    cudaStreamWaitEvent(0, evT, 0);
    mma_packed<<<dim3((BB*EE)/128, 4), 256>>>(pXh, pXl, pG1h, pG1l,
                                              h1, 512, nullptr, 0);
    sd1_kernel<<<BB*EE, 128>>>(a_src1, a_dst1);
    att1_kernel<<<BB*EE, 128>>>(b_g1, g1_gamma, g1_beta);

    gat2h_kernel<<<BB*EE, 64>>>(W_g2, a_src2, a_dst2);
    att2_kernel<<<BB*EE, 128>>>(b_g2, g2_gamma, g2_beta);

    gemm_kernel<<<dim3((BB*EE)/64, 2), 128>>>(2, W_r1,          256, 64);
    gemm_kernel<<<dim3((BB*EE)/64, 2), 128>>>(3, W_r1 + 64*256, 256, 64);

    cudaStreamWaitEvent(0, evA, 0);
    pair_kernel<<<(BB*PP)/8, 256>>>(pair_head, pair_tail, pair_rel,
                                    W_r2, b_r2, out);
}